// round 2
// baseline (speedup 1.0000x reference)
#include <cuda_runtime.h>
#include <math.h>

// Problem constants
#define MTOT 2048   // BATCH*SEQ = 32*64
#define NE   4096   // EMBED_DIM
#define KE   4096

// ---------------- scratch (allocation-free: __device__ globals) ----------------
__device__ float g_Q[MTOT * NE];
__device__ float g_K[MTOT * NE];
__device__ float g_V[MTOT * NE];
__device__ float g_G[MTOT * NE];
__device__ float g_A[MTOT * NE];

// =====================================================================
// GEMM:  C[m,n] = sum_k A[m,k] * B[n,k] + bias[n]       (A: 2048x4096,
//        B: 4096x4096, both row-major; "NT" layout — both read along k)
// mode 0: none, mode 1: sigmoid epilogue (gamma projection)
// 128x128 block tile, BK=16, 256 threads, 8x8 per-thread microtile,
// register prefetch of the next global tile (single smem buffer).
// =====================================================================
__global__ __launch_bounds__(256, 2) void gemm_nt_kernel(
    const float* __restrict__ A, const float* __restrict__ B,
    const float* __restrict__ bias, float* __restrict__ C, int mode)
{
    constexpr int BK = 16;
    __shared__ float As[BK][128];
    __shared__ float Bs[BK][128];

    const int tid = threadIdx.x;
    const int bm  = blockIdx.y * 128;
    const int bn  = blockIdx.x * 128;

    // loader mapping: 512 float4 per (128x16) tile; thread handles f=tid, tid+256
    const int r0 = tid >> 2,         c0 = (tid & 3) * 4;
    const int r1 = (tid + 256) >> 2, c1 = (tid & 3) * 4;  // (tid+256)&3 == tid&3

    const float* Abase = A + (size_t)bm * KE;
    const float* Bbase = B + (size_t)bn * KE;

    // preload tile 0 straight to smem
    {
        float4 a0 = *(const float4*)(Abase + (size_t)r0 * KE + c0);
        float4 a1 = *(const float4*)(Abase + (size_t)r1 * KE + c1);
        float4 b0 = *(const float4*)(Bbase + (size_t)r0 * KE + c0);
        float4 b1 = *(const float4*)(Bbase + (size_t)r1 * KE + c1);
        As[c0+0][r0]=a0.x; As[c0+1][r0]=a0.y; As[c0+2][r0]=a0.z; As[c0+3][r0]=a0.w;
        As[c1+0][r1]=a1.x; As[c1+1][r1]=a1.y; As[c1+2][r1]=a1.z; As[c1+3][r1]=a1.w;
        Bs[c0+0][r0]=b0.x; Bs[c0+1][r0]=b0.y; Bs[c0+2][r0]=b0.z; Bs[c0+3][r0]=b0.w;
        Bs[c1+0][r1]=b1.x; Bs[c1+1][r1]=b1.y; Bs[c1+2][r1]=b1.z; Bs[c1+3][r1]=b1.w;
    }

    float acc[8][8];
#pragma unroll
    for (int i = 0; i < 8; i++)
#pragma unroll
        for (int j = 0; j < 8; j++) acc[i][j] = 0.f;

    const int ty = tid >> 4, tx = tid & 15;
    const int rowb = ty * 8, colb = tx * 8;

    __syncthreads();

    float4 pa0, pa1, pb0, pb1;
    for (int kt = 0; kt < KE; kt += BK) {
        const bool has_next = (kt + BK) < KE;
        if (has_next) {
            const int knx = kt + BK;
            pa0 = *(const float4*)(Abase + (size_t)r0 * KE + knx + c0);
            pa1 = *(const float4*)(Abase + (size_t)r1 * KE + knx + c1);
            pb0 = *(const float4*)(Bbase + (size_t)r0 * KE + knx + c0);
            pb1 = *(const float4*)(Bbase + (size_t)r1 * KE + knx + c1);
        }
#pragma unroll
        for (int kk = 0; kk < BK; kk++) {
            float4 av0 = *(const float4*)&As[kk][rowb];
            float4 av1 = *(const float4*)&As[kk][rowb + 4];
            float4 bv0 = *(const float4*)&Bs[kk][colb];
            float4 bv1 = *(const float4*)&Bs[kk][colb + 4];
            float a[8] = {av0.x, av0.y, av0.z, av0.w, av1.x, av1.y, av1.z, av1.w};
            float b[8] = {bv0.x, bv0.y, bv0.z, bv0.w, bv1.x, bv1.y, bv1.z, bv1.w};
#pragma unroll
            for (int i = 0; i < 8; i++)
#pragma unroll
                for (int j = 0; j < 8; j++)
                    acc[i][j] = fmaf(a[i], b[j], acc[i][j]);
        }
        __syncthreads();
        if (has_next) {
            As[c0+0][r0]=pa0.x; As[c0+1][r0]=pa0.y; As[c0+2][r0]=pa0.z; As[c0+3][r0]=pa0.w;
            As[c1+0][r1]=pa1.x; As[c1+1][r1]=pa1.y; As[c1+2][r1]=pa1.z; As[c1+3][r1]=pa1.w;
            Bs[c0+0][r0]=pb0.x; Bs[c0+1][r0]=pb0.y; Bs[c0+2][r0]=pb0.z; Bs[c0+3][r0]=pb0.w;
            Bs[c1+0][r1]=pb1.x; Bs[c1+1][r1]=pb1.y; Bs[c1+2][r1]=pb1.z; Bs[c1+3][r1]=pb1.w;
        }
        __syncthreads();
    }

    // epilogue
    float bv[8];
#pragma unroll
    for (int j = 0; j < 8; j++) bv[j] = bias[bn + colb + j];

#pragma unroll
    for (int i = 0; i < 8; i++) {
        const int m = bm + rowb + i;
        float out[8];
#pragma unroll
        for (int j = 0; j < 8; j++) {
            float v = acc[i][j] + bv[j];
            if (mode == 1) v = 1.f / (1.f + expf(-v));
            out[j] = v;
        }
        float* cp = C + (size_t)m * NE + bn + colb;
        *(float4*)(cp)     = make_float4(out[0], out[1], out[2], out[3]);
        *(float4*)(cp + 4) = make_float4(out[4], out[5], out[6], out[7]);
    }
}

// =====================================================================
// Fused attention: one CTA per (b,h). s=64, d=128.
//  - loads Q,K,gamma tiles to smem
//  - RoPE (module's layout: ang(s,q) = t[q&63] * 10000^(-s/64))
//  - cumprod over s of sigmoid(gamma) -> gc, gc^-1
//  - S[q,k] = (Q.K) * mean_d(gc_q/gc_k) masked causal
//  - O = S @ V
// =====================================================================
#define SD 129  // padded row stride to break bank conflicts

__global__ __launch_bounds__(256, 1) void attn_kernel(
    const float* __restrict__ Q, const float* __restrict__ K,
    const float* __restrict__ V, const float* __restrict__ G,
    const float* __restrict__ t, float* __restrict__ O)
{
    extern __shared__ float sm[];
    float* sQ  = sm;                 // 64*SD
    float* sK  = sm + 64 * SD;       // K, later reused for V
    float* sGc = sm + 2 * 64 * SD;   // cumprod
    float* sGi = sm + 3 * 64 * SD;   // 1/cumprod
    float* sS  = sm + 4 * 64 * SD;   // 64*64 decayed scores

    const int bh = blockIdx.x;           // b*32 + h
    const int b  = bh >> 5, h = bh & 31;
    const int tid = threadIdx.x;
    const size_t base = ((size_t)b * 64) * 4096 + (size_t)h * 128;

    // ---- load Q, K, gamma(sigmoided) ----
    for (int i = tid; i < 64 * 128; i += 256) {
        const int s = i >> 7, d = i & 127;
        const size_t g = base + (size_t)s * 4096 + d;
        sQ [s * SD + d] = Q[g];
        sK [s * SD + d] = K[g];
        sGc[s * SD + d] = G[g];
    }
    __syncthreads();

    // ---- RoPE in place on Q and K (pairs (q, q+64) share the angle) ----
    const float LN1E4_64 = 0.14391156531879916f;  // ln(10000)/64
    for (int i = tid; i < 64 * 64; i += 256) {
        const int s = i >> 6, q = i & 63;
        const float invf = expf(-(float)s * LN1E4_64);
        const float ang  = t[q] * invf;
        const float cs = cosf(ang), sn = sinf(ang);
        float a, b2;
        a = sQ[s * SD + q]; b2 = sQ[s * SD + q + 64];
        sQ[s * SD + q]      = a * cs - b2 * sn;
        sQ[s * SD + q + 64] = b2 * cs + a * sn;
        a = sK[s * SD + q]; b2 = sK[s * SD + q + 64];
        sK[s * SD + q]      = a * cs - b2 * sn;
        sK[s * SD + q + 64] = b2 * cs + a * sn;
    }
    // ---- cumprod over sequence (per d column, 128 columns) ----
    if (tid < 128) {
        float run = 1.f;
        for (int s = 0; s < 64; s++) {
            run *= sGc[s * SD + tid];
            sGc[s * SD + tid] = run;
            sGi[s * SD + tid] = 1.f / run;
        }
    }
    __syncthreads();

    // ---- decayed masked scores: 16x16 thread grid, 4x4 microtile ----
    {
        const int ty = tid >> 4, tx = tid & 15;
        const int q0 = ty * 4, k0 = tx * 4;
        float acc[4][4], dac[4][4];
#pragma unroll
        for (int i = 0; i < 4; i++)
#pragma unroll
            for (int j = 0; j < 4; j++) { acc[i][j] = 0.f; dac[i][j] = 0.f; }

        if (k0 <= q0 + 3) {  // block touches the causal triangle
            for (int kk = 0; kk < 128; kk++) {
                float qv[4], kv[4], gq[4], gi[4];
#pragma unroll
                for (int i = 0; i < 4; i++) {
                    qv[i] = sQ [(q0 + i) * SD + kk];
                    gq[i] = sGc[(q0 + i) * SD + kk];
                }
#pragma unroll
                for (int j = 0; j < 4; j++) {
                    kv[j] = sK [(k0 + j) * SD + kk];
                    gi[j] = sGi[(k0 + j) * SD + kk];
                }
#pragma unroll
                for (int i = 0; i < 4; i++)
#pragma unroll
                    for (int j = 0; j < 4; j++) {
                        acc[i][j] = fmaf(qv[i], kv[j], acc[i][j]);
                        dac[i][j] = fmaf(gq[i], gi[j], dac[i][j]);
                    }
            }
        }
#pragma unroll
        for (int i = 0; i < 4; i++)
#pragma unroll
            for (int j = 0; j < 4; j++) {
                const int qi = q0 + i, ki = k0 + j;
                sS[qi * 64 + ki] =
                    (ki <= qi) ? acc[i][j] * dac[i][j] * (1.0f / 128.0f) : 0.f;
            }
    }
    __syncthreads();

    // ---- load V over K's smem ----
    for (int i = tid; i < 64 * 128; i += 256) {
        const int s = i >> 7, d = i & 127;
        sK[s * SD + d] = V[base + (size_t)s * 4096 + d];
    }
    __syncthreads();

    // ---- O = S @ V : warp w handles rows, lane covers d with stride 32 ----
    {
        const int lane = tid & 31, w = tid >> 5;  // 8 warps
        for (int it = 0; it < 8; it++) {
            const int q = it * 8 + w;
            float a0 = 0.f, a1 = 0.f, a2 = 0.f, a3 = 0.f;
            for (int k = 0; k < 64; k++) {
                const float s_ = sS[q * 64 + k];
                const float* vr = &sK[k * SD];
                a0 = fmaf(s_, vr[lane],      a0);
                a1 = fmaf(s_, vr[lane + 32], a1);
                a2 = fmaf(s_, vr[lane + 64], a2);
                a3 = fmaf(s_, vr[lane + 96], a3);
            }
            float* op = O + base + (size_t)q * 4096;
            op[lane]      = a0;
            op[lane + 32] = a1;
            op[lane + 64] = a2;
            op[lane + 96] = a3;
        }
    }
}

// =====================================================================
// launch
// =====================================================================
extern "C" void kernel_launch(void* const* d_in, const int* in_sizes, int n_in,
                              void* d_out, int out_size)
{
    const float* x  = (const float*)d_in[0];
    const float* t  = (const float*)d_in[1];
    const float* Wq = (const float*)d_in[2];
    const float* bq = (const float*)d_in[3];
    const float* Wk = (const float*)d_in[4];
    const float* bk = (const float*)d_in[5];
    const float* Wv = (const float*)d_in[6];
    const float* bv = (const float*)d_in[7];
    const float* Wd = (const float*)d_in[8];
    const float* bd = (const float*)d_in[9];
    const float* Wo = (const float*)d_in[10];
    const float* bo = (const float*)d_in[11];
    float* out = (float*)d_out;

    float *Qb, *Kb, *Vb, *Gb, *Ab;
    cudaGetSymbolAddress((void**)&Qb, g_Q);
    cudaGetSymbolAddress((void**)&Kb, g_K);
    cudaGetSymbolAddress((void**)&Vb, g_V);
    cudaGetSymbolAddress((void**)&Gb, g_G);
    cudaGetSymbolAddress((void**)&Ab, g_A);

    dim3 grid(NE / 128, MTOT / 128);
    gemm_nt_kernel<<<grid, 256>>>(x, Wq, bq, Qb, 0);
    gemm_nt_kernel<<<grid, 256>>>(x, Wk, bk, Kb, 0);
    gemm_nt_kernel<<<grid, 256>>>(x, Wv, bv, Vb, 0);
    gemm_nt_kernel<<<grid, 256>>>(x, Wd, bd, Gb, 1);  // sigmoid epilogue

    const size_t smem = (size_t)(4 * 64 * SD + 64 * 64) * sizeof(float);
    cudaFuncSetAttribute(attn_kernel,
                         cudaFuncAttributeMaxDynamicSharedMemorySize, (int)smem);
    attn_kernel<<<1024, 256, smem>>>(Qb, Kb, Vb, Gb, t, Ab);

    gemm_nt_kernel<<<grid, 256>>>(Ab, Wo, bo, out, 0);
}

// round 4
// speedup vs baseline: 2.7702x; 2.7702x over previous
#include <cuda_runtime.h>
#include <cuda_bf16.h>
#include <math.h>
#include <stdint.h>

// Problem constants
#define MTOT 2048   // BATCH*SEQ = 32*64
#define NE   4096   // EMBED_DIM
#define KE   4096
#define WSL  16777216ull   // elements per weight slot (4096*4096)

// ---------------- scratch (allocation-free: __device__ globals) ----------------
__device__ float g_Q[MTOT * NE];
__device__ float g_K[MTOT * NE];
__device__ float g_V[MTOT * NE];
__device__ float g_G[MTOT * NE];
__device__ float g_A[MTOT * NE];

__device__ __nv_bfloat16 g_xh[MTOT * NE];
__device__ __nv_bfloat16 g_xl[MTOT * NE];
__device__ __nv_bfloat16 g_ah[MTOT * NE];
__device__ __nv_bfloat16 g_al[MTOT * NE];
__device__ __nv_bfloat16 g_wh[5 * WSL];   // slots: Wq,Wk,Wv,Wd,Wo (hi plane)
__device__ __nv_bfloat16 g_wl[5 * WSL];   // lo plane

// =====================================================================
// helpers
// =====================================================================
__device__ __forceinline__ uint32_t smem_u32(const void* p) {
    uint32_t a;
    asm("{ .reg .u64 t; cvta.to.shared.u64 t, %1; cvt.u32.u64 %0, t; }" : "=r"(a) : "l"(p));
    return a;
}
__device__ __forceinline__ void cp16(uint32_t s, const void* g) {
    asm volatile("cp.async.cg.shared.global [%0], [%1], 16;" :: "r"(s), "l"(g));
}
__device__ __forceinline__ void cp_commit() {
    asm volatile("cp.async.commit_group;" ::: "memory");
}
template <int N>
__device__ __forceinline__ void cp_wait() {
    asm volatile("cp.async.wait_group %0;" :: "n"(N) : "memory");
}
__device__ __forceinline__ void ldm_x4(uint32_t* r, uint32_t a) {
    asm volatile("ldmatrix.sync.aligned.m8n8.x4.shared.b16 {%0,%1,%2,%3}, [%4];"
                 : "=r"(r[0]), "=r"(r[1]), "=r"(r[2]), "=r"(r[3]) : "r"(a));
}
__device__ __forceinline__ void ldm_x2(uint32_t& r0, uint32_t& r1, uint32_t a) {
    asm volatile("ldmatrix.sync.aligned.m8n8.x2.shared.b16 {%0,%1}, [%2];"
                 : "=r"(r0), "=r"(r1) : "r"(a));
}
__device__ __forceinline__ void mma4(float* c, const uint32_t* a, uint32_t b0, uint32_t b1) {
    asm volatile("mma.sync.aligned.m16n8k16.row.col.f32.bf16.bf16.f32 "
                 "{%0,%1,%2,%3}, {%4,%5,%6,%7}, {%8,%9}, {%0,%1,%2,%3};"
                 : "+f"(c[0]), "+f"(c[1]), "+f"(c[2]), "+f"(c[3])
                 : "r"(a[0]), "r"(a[1]), "r"(a[2]), "r"(a[3]), "r"(b0), "r"(b1));
}

// =====================================================================
// fp32 -> bf16 hi/lo split (elementwise, float4 granularity)
// =====================================================================
__global__ void split_k(const float* __restrict__ in, __nv_bfloat16* __restrict__ hi,
                        __nv_bfloat16* __restrict__ lo, int n4)
{
    int i = blockIdx.x * blockDim.x + threadIdx.x;
    const int str = gridDim.x * blockDim.x;
    for (; i < n4; i += str) {
        float4 v = ((const float4*)in)[i];
        __nv_bfloat16 h0 = __float2bfloat16(v.x), h1 = __float2bfloat16(v.y);
        __nv_bfloat16 h2 = __float2bfloat16(v.z), h3 = __float2bfloat16(v.w);
        __nv_bfloat16 l0 = __float2bfloat16(v.x - __bfloat162float(h0));
        __nv_bfloat16 l1 = __float2bfloat16(v.y - __bfloat162float(h1));
        __nv_bfloat16 l2 = __float2bfloat16(v.z - __bfloat162float(h2));
        __nv_bfloat16 l3 = __float2bfloat16(v.w - __bfloat162float(h3));
        __nv_bfloat162* hp = (__nv_bfloat162*)hi;
        __nv_bfloat162* lp = (__nv_bfloat162*)lo;
        hp[2 * i]     = __nv_bfloat162(h0, h1);
        hp[2 * i + 1] = __nv_bfloat162(h2, h3);
        lp[2 * i]     = __nv_bfloat162(l0, l1);
        lp[2 * i + 1] = __nv_bfloat162(l2, l3);
    }
}

// =====================================================================
// bf16-split tensor-core GEMM: C[m,n] = sum_k A[m,k]*W[n,k] + bias[n]
//   A, W given as bf16 hi/lo planes; product = hh + hl + lh (fp32 acc).
// CTA tile 128x256, BK=32, 8 warps (2m x 4n), warp tile 64x64,
// 3-stage cp.async pipeline, ldmatrix fragments, 80B-padded smem rows.
// grid.z selects weight slot / bias / output; z==sigz -> sigmoid.
// =====================================================================
#define PAH 0
#define PAL 10240
#define PBH 20480
#define PBL 40960
#define STG 61440
#define GSMEM (3 * STG)   // 184320 bytes

__global__ __launch_bounds__(256, 1) void gemm_mma(
    const __nv_bfloat16* __restrict__ Ahp, const __nv_bfloat16* __restrict__ Alp,
    const __nv_bfloat16* __restrict__ Whp, const __nv_bfloat16* __restrict__ Wlp,
    const float* __restrict__ b0p, const float* __restrict__ b1p,
    const float* __restrict__ b2p, const float* __restrict__ b3p,
    float* C0, float* C1, float* C2, float* C3, int sigz)
{
    extern __shared__ char smem[];
    const uint32_t sb = smem_u32(smem);
    const int tid = threadIdx.x, z = blockIdx.z;

    const __nv_bfloat16* Wh = Whp + (size_t)z * WSL;
    const __nv_bfloat16* Wl = Wlp + (size_t)z * WSL;
    const float* bias = (z == 0) ? b0p : (z == 1) ? b1p : (z == 2) ? b2p : b3p;
    float*       C    = (z == 0) ? C0  : (z == 1) ? C1  : (z == 2) ? C2  : C3;

    const int bm = blockIdx.y * 128;
    const int bn = blockIdx.x * 256;
    const size_t aoff = (size_t)bm * KE;
    const size_t boff = (size_t)bn * KE;

    // per-thread cp.async chunk mapping (row, 16B chunk within 32-elem row)
    const int crow = tid >> 2, cch = (tid & 3);
    const uint32_t soc = (uint32_t)cch * 16;
    const size_t   goc = (size_t)cch * 8;

    // ldmatrix address offsets (within a stage buffer)
    const int lane = tid & 31, wid = tid >> 5;
    const int wm = wid >> 2, wn = wid & 3;
    const int mA = lane >> 3, rA = lane & 7;
    uint32_t offA[4];
#pragma unroll
    for (int mi = 0; mi < 4; mi++)
        offA[mi] = (uint32_t)((wm * 64 + mi * 16 + (mA & 1) * 8 + rA) * 80 + (mA >> 1) * 16);
    const int lane2 = lane & 15;
    uint32_t offB[8];
#pragma unroll
    for (int nj = 0; nj < 8; nj++)
        offB[nj] = (uint32_t)((wn * 64 + nj * 8 + (lane2 & 7)) * 80 + (lane2 >> 3) * 16);

    float acc[4][8][4];
#pragma unroll
    for (int mi = 0; mi < 4; mi++)
#pragma unroll
        for (int nj = 0; nj < 8; nj++)
#pragma unroll
            for (int r = 0; r < 4; r++) acc[mi][nj][r] = 0.f;

    // stage loader
    auto load_stage = [&](int p, int kt) {
        const uint32_t s = sb + (uint32_t)p * STG;
#pragma unroll
        for (int u = 0; u < 2; u++) {
            const int row = crow + u * 64;
            const uint32_t so = (uint32_t)row * 80 + soc;
            const size_t   go = (size_t)row * KE + kt + goc;
            cp16(s + PAH + so, Ahp + aoff + go);
            cp16(s + PAL + so, Alp + aoff + go);
        }
#pragma unroll
        for (int u = 0; u < 4; u++) {
            const int row = crow + u * 64;
            const uint32_t so = (uint32_t)row * 80 + soc;
            const size_t   go = (size_t)row * KE + kt + goc;
            cp16(s + PBH + so, Wh + boff + go);
            cp16(s + PBL + so, Wl + boff + go);
        }
        cp_commit();
    };

    load_stage(0, 0);
    load_stage(1, 32);

    const int NST = KE / 32;  // 128
    for (int i = 0; i < NST; i++) {
        cp_wait<1>();
        __syncthreads();
        if (i + 2 < NST) load_stage((i + 2) % 3, (i + 2) * 32);
        else             cp_commit();

        const uint32_t s = sb + (uint32_t)(i % 3) * STG;
#pragma unroll
        for (int ks = 0; ks < 2; ks++) {
            const uint32_t kb = (uint32_t)ks * 32;
            uint32_t ah[4][4], al[4][4];
#pragma unroll
            for (int mi = 0; mi < 4; mi++) {
                ldm_x4(ah[mi], s + PAH + offA[mi] + kb);
                ldm_x4(al[mi], s + PAL + offA[mi] + kb);
            }
#pragma unroll
            for (int nj = 0; nj < 8; nj++) {
                uint32_t bh0, bh1, bl0, bl1;
                ldm_x2(bh0, bh1, s + PBH + offB[nj] + kb);
                ldm_x2(bl0, bl1, s + PBL + offB[nj] + kb);
#pragma unroll
                for (int mi = 0; mi < 4; mi++) {
                    mma4(acc[mi][nj], ah[mi], bh0, bh1);
                    mma4(acc[mi][nj], ah[mi], bl0, bl1);
                    mma4(acc[mi][nj], al[mi], bh0, bh1);
                }
            }
        }
    }

    // epilogue
    const int g = lane >> 2, t = lane & 3;
    const bool dos = (z == sigz);
#pragma unroll
    for (int mi = 0; mi < 4; mi++) {
#pragma unroll
        for (int nj = 0; nj < 8; nj++) {
            const int row = bm + wm * 64 + mi * 16 + g;
            const int col = bn + wn * 64 + nj * 8 + 2 * t;
            const float bb0 = bias[col], bb1 = bias[col + 1];
            float v0 = acc[mi][nj][0] + bb0, v1 = acc[mi][nj][1] + bb1;
            float v2 = acc[mi][nj][2] + bb0, v3 = acc[mi][nj][3] + bb1;
            if (dos) {
                v0 = 1.f / (1.f + expf(-v0)); v1 = 1.f / (1.f + expf(-v1));
                v2 = 1.f / (1.f + expf(-v2)); v3 = 1.f / (1.f + expf(-v3));
            }
            *(float2*)(C + (size_t)row * NE + col)       = make_float2(v0, v1);
            *(float2*)(C + (size_t)(row + 8) * NE + col) = make_float2(v2, v3);
        }
    }
}

// =====================================================================
// Fused attention: one CTA per (b,h). s=64, d=128.  (unchanged, verified)
// =====================================================================
#define SD 129

__global__ __launch_bounds__(256, 1) void attn_kernel(
    const float* __restrict__ Q, const float* __restrict__ K,
    const float* __restrict__ V, const float* __restrict__ G,
    const float* __restrict__ t, float* __restrict__ O)
{
    extern __shared__ float sm[];
    float* sQ  = sm;
    float* sK  = sm + 64 * SD;
    float* sGc = sm + 2 * 64 * SD;
    float* sGi = sm + 3 * 64 * SD;
    float* sS  = sm + 4 * 64 * SD;

    const int bh = blockIdx.x;
    const int b  = bh >> 5, h = bh & 31;
    const int tid = threadIdx.x;
    const size_t base = ((size_t)b * 64) * 4096 + (size_t)h * 128;

    for (int i = tid; i < 64 * 128; i += 256) {
        const int s = i >> 7, d = i & 127;
        const size_t g = base + (size_t)s * 4096 + d;
        sQ [s * SD + d] = Q[g];
        sK [s * SD + d] = K[g];
        sGc[s * SD + d] = G[g];
    }
    __syncthreads();

    const float LN1E4_64 = 0.14391156531879916f;
    for (int i = tid; i < 64 * 64; i += 256) {
        const int s = i >> 6, q = i & 63;
        const float invf = expf(-(float)s * LN1E4_64);
        const float ang  = t[q] * invf;
        const float cs = cosf(ang), sn = sinf(ang);
        float a, b2;
        a = sQ[s * SD + q]; b2 = sQ[s * SD + q + 64];
        sQ[s * SD + q]      = a * cs - b2 * sn;
        sQ[s * SD + q + 64] = b2 * cs + a * sn;
        a = sK[s * SD + q]; b2 = sK[s * SD + q + 64];
        sK[s * SD + q]      = a * cs - b2 * sn;
        sK[s * SD + q + 64] = b2 * cs + a * sn;
    }
    if (tid < 128) {
        float run = 1.f;
        for (int s = 0; s < 64; s++) {
            run *= sGc[s * SD + tid];
            sGc[s * SD + tid] = run;
            sGi[s * SD + tid] = 1.f / run;
        }
    }
    __syncthreads();

    {
        const int ty = tid >> 4, tx = tid & 15;
        const int q0 = ty * 4, k0 = tx * 4;
        float acc[4][4], dac[4][4];
#pragma unroll
        for (int i = 0; i < 4; i++)
#pragma unroll
            for (int j = 0; j < 4; j++) { acc[i][j] = 0.f; dac[i][j] = 0.f; }

        if (k0 <= q0 + 3) {
            for (int kk = 0; kk < 128; kk++) {
                float qv[4], kv[4], gq[4], gi[4];
#pragma unroll
                for (int i = 0; i < 4; i++) {
                    qv[i] = sQ [(q0 + i) * SD + kk];
                    gq[i] = sGc[(q0 + i) * SD + kk];
                }
#pragma unroll
                for (int j = 0; j < 4; j++) {
                    kv[j] = sK [(k0 + j) * SD + kk];
                    gi[j] = sGi[(k0 + j) * SD + kk];
                }
#pragma unroll
                for (int i = 0; i < 4; i++)
#pragma unroll
                    for (int j = 0; j < 4; j++) {
                        acc[i][j] = fmaf(qv[i], kv[j], acc[i][j]);
                        dac[i][j] = fmaf(gq[i], gi[j], dac[i][j]);
                    }
            }
        }
#pragma unroll
        for (int i = 0; i < 4; i++)
#pragma unroll
            for (int j = 0; j < 4; j++) {
                const int qi = q0 + i, ki = k0 + j;
                sS[qi * 64 + ki] =
                    (ki <= qi) ? acc[i][j] * dac[i][j] * (1.0f / 128.0f) : 0.f;
            }
    }
    __syncthreads();

    for (int i = tid; i < 64 * 128; i += 256) {
        const int s = i >> 7, d = i & 127;
        sK[s * SD + d] = V[base + (size_t)s * 4096 + d];
    }
    __syncthreads();

    {
        const int lane = tid & 31, w = tid >> 5;
        for (int it = 0; it < 8; it++) {
            const int q = it * 8 + w;
            float a0 = 0.f, a1 = 0.f, a2 = 0.f, a3 = 0.f;
            for (int k = 0; k < 64; k++) {
                const float s_ = sS[q * 64 + k];
                const float* vr = &sK[k * SD];
                a0 = fmaf(s_, vr[lane],      a0);
                a1 = fmaf(s_, vr[lane + 32], a1);
                a2 = fmaf(s_, vr[lane + 64], a2);
                a3 = fmaf(s_, vr[lane + 96], a3);
            }
            float* op = O + base + (size_t)q * 4096;
            op[lane]      = a0;
            op[lane + 32] = a1;
            op[lane + 64] = a2;
            op[lane + 96] = a3;
        }
    }
}

// =====================================================================
// launch
// =====================================================================
extern "C" void kernel_launch(void* const* d_in, const int* in_sizes, int n_in,
                              void* d_out, int out_size)
{
    const float* x  = (const float*)d_in[0];
    const float* t  = (const float*)d_in[1];
    const float* Wq = (const float*)d_in[2];
    const float* bq = (const float*)d_in[3];
    const float* Wk = (const float*)d_in[4];
    const float* bk = (const float*)d_in[5];
    const float* Wv = (const float*)d_in[6];
    const float* bv = (const float*)d_in[7];
    const float* Wd = (const float*)d_in[8];
    const float* bd = (const float*)d_in[9];
    const float* Wo = (const float*)d_in[10];
    const float* bo = (const float*)d_in[11];
    float* out = (float*)d_out;

    float *Qb, *Kb, *Vb, *Gb, *Ab;
    __nv_bfloat16 *xh, *xl, *ah, *al, *wh, *wl;
    cudaGetSymbolAddress((void**)&Qb, g_Q);
    cudaGetSymbolAddress((void**)&Kb, g_K);
    cudaGetSymbolAddress((void**)&Vb, g_V);
    cudaGetSymbolAddress((void**)&Gb, g_G);
    cudaGetSymbolAddress((void**)&Ab, g_A);
    cudaGetSymbolAddress((void**)&xh, g_xh);
    cudaGetSymbolAddress((void**)&xl, g_xl);
    cudaGetSymbolAddress((void**)&ah, g_ah);
    cudaGetSymbolAddress((void**)&al, g_al);
    cudaGetSymbolAddress((void**)&wh, g_wh);
    cudaGetSymbolAddress((void**)&wl, g_wl);

    const int n4x = MTOT * NE / 4;
    const int n4w = NE * KE / 4;
    split_k<<<2048, 256>>>(x,  xh, xl, n4x);
    split_k<<<4096, 256>>>(Wq, wh + 0 * WSL, wl + 0 * WSL, n4w);
    split_k<<<4096, 256>>>(Wk, wh + 1 * WSL, wl + 1 * WSL, n4w);
    split_k<<<4096, 256>>>(Wv, wh + 2 * WSL, wl + 2 * WSL, n4w);
    split_k<<<4096, 256>>>(Wd, wh + 3 * WSL, wl + 3 * WSL, n4w);
    split_k<<<4096, 256>>>(Wo, wh + 4 * WSL, wl + 4 * WSL, n4w);

    cudaFuncSetAttribute(gemm_mma, cudaFuncAttributeMaxDynamicSharedMemorySize, GSMEM);

    // fused Q/K/V/gamma projections (z selects weight slot)
    gemm_mma<<<dim3(NE / 256, MTOT / 128, 4), 256, GSMEM>>>(
        xh, xl, wh, wl, bq, bk, bv, bd, Qb, Kb, Vb, Gb, /*sigz=*/3);

    const size_t asmem = (size_t)(4 * 64 * SD + 64 * 64) * sizeof(float);
    cudaFuncSetAttribute(attn_kernel,
                         cudaFuncAttributeMaxDynamicSharedMemorySize, (int)asmem);
    attn_kernel<<<1024, 256, asmem>>>(Qb, Kb, Vb, Gb, t, Ab);

    // output projection
    split_k<<<2048, 256>>>(Ab, ah, al, n4x);
    gemm_mma<<<dim3(NE / 256, MTOT / 128, 1), 256, GSMEM>>>(
        ah, al, wh + 4 * WSL, wl + 4 * WSL, bo, bo, bo, bo, out, out, out, out, /*sigz=*/-1);
}

// round 5
// speedup vs baseline: 2.8820x; 1.0404x over previous
#include <cuda_runtime.h>
#include <cuda_fp16.h>
#include <math.h>
#include <stdint.h>

// Problem constants
#define MTOT 2048   // BATCH*SEQ = 32*64
#define NE   4096   // EMBED_DIM
#define KE   4096
#define WSL  16777216ull   // elements per weight slot (4096*4096)

// ---------------- scratch (allocation-free: __device__ globals) ----------------
__device__ float g_Q[MTOT * NE];
__device__ float g_K[MTOT * NE];
__device__ float g_V[MTOT * NE];
__device__ float g_G[MTOT * NE];
__device__ float g_A[MTOT * NE];

__device__ __half g_xh[MTOT * NE];
__device__ __half g_xl[MTOT * NE];
__device__ __half g_ah[MTOT * NE];
__device__ __half g_al[MTOT * NE];
__device__ __half g_wh[5 * WSL];   // slots: Wq,Wk,Wv,Wd,Wo (hi plane)
__device__ __half g_wl[WSL];       // lo plane, only needed for Wd (gamma)

// =====================================================================
// helpers
// =====================================================================
__device__ __forceinline__ uint32_t smem_u32(const void* p) {
    uint32_t a;
    asm("{ .reg .u64 t; cvta.to.shared.u64 t, %1; cvt.u32.u64 %0, t; }" : "=r"(a) : "l"(p));
    return a;
}
__device__ __forceinline__ void cp16(uint32_t s, const void* g) {
    asm volatile("cp.async.cg.shared.global [%0], [%1], 16;" :: "r"(s), "l"(g));
}
__device__ __forceinline__ void cp_commit() {
    asm volatile("cp.async.commit_group;" ::: "memory");
}
template <int N>
__device__ __forceinline__ void cp_wait() {
    asm volatile("cp.async.wait_group %0;" :: "n"(N) : "memory");
}
__device__ __forceinline__ void ldm_x4(uint32_t* r, uint32_t a) {
    asm volatile("ldmatrix.sync.aligned.m8n8.x4.shared.b16 {%0,%1,%2,%3}, [%4];"
                 : "=r"(r[0]), "=r"(r[1]), "=r"(r[2]), "=r"(r[3]) : "r"(a));
}
__device__ __forceinline__ void mma4(float* c, const uint32_t* a, uint32_t b0, uint32_t b1) {
    asm volatile("mma.sync.aligned.m16n8k16.row.col.f32.f16.f16.f32 "
                 "{%0,%1,%2,%3}, {%4,%5,%6,%7}, {%8,%9}, {%0,%1,%2,%3};"
                 : "+f"(c[0]), "+f"(c[1]), "+f"(c[2]), "+f"(c[3])
                 : "r"(a[0]), "r"(a[1]), "r"(a[2]), "r"(a[3]), "r"(b0), "r"(b1));
}

// =====================================================================
// fp32 -> fp16 hi/lo split (elementwise, float4 granularity)
// wlo==0: skip writing the lo plane
// =====================================================================
__global__ void split_k(const float* __restrict__ in, __half* __restrict__ hi,
                        __half* __restrict__ lo, int n4, int wlo)
{
    int i = blockIdx.x * blockDim.x + threadIdx.x;
    const int str = gridDim.x * blockDim.x;
    for (; i < n4; i += str) {
        float4 v = ((const float4*)in)[i];
        __half h0 = __float2half(v.x), h1 = __float2half(v.y);
        __half h2 = __float2half(v.z), h3 = __float2half(v.w);
        __half2* hp = (__half2*)hi;
        hp[2 * i]     = __half2(h0, h1);
        hp[2 * i + 1] = __half2(h2, h3);
        if (wlo) {
            __half l0 = __float2half(v.x - __half2float(h0));
            __half l1 = __float2half(v.y - __half2float(h1));
            __half l2 = __float2half(v.z - __half2float(h2));
            __half l3 = __float2half(v.w - __half2float(h3));
            __half2* lp = (__half2*)lo;
            lp[2 * i]     = __half2(l0, l1);
            lp[2 * i + 1] = __half2(l2, l3);
        }
    }
}

// =====================================================================
// fp16-split tensor-core GEMM: C[m,n] = sum_k A[m,k]*W[n,k] + bias[n]
//   product = ah*bh + al*bh (2 terms); z==sigz (gamma): + ah*bl (3 terms)
// CTA tile 128x256, BK=32, 16 warps (4m x 4n), warp tile 32x64,
// 3-stage cp.async pipeline, ldmatrix.x4 fragments, 80B-padded smem rows.
// =====================================================================
#define PAH 0
#define PAL 10240
#define PBH 20480
#define PBL 40960
#define STG 61440
#define GSMEM (3 * STG)   // 184320 bytes

__global__ __launch_bounds__(512, 1) void gemm_mma(
    const __half* __restrict__ Ahp, const __half* __restrict__ Alp,
    const __half* __restrict__ Whp, const __half* __restrict__ Wlp,
    const float* __restrict__ b0p, const float* __restrict__ b1p,
    const float* __restrict__ b2p, const float* __restrict__ b3p,
    float* C0, float* C1, float* C2, float* C3, int sigz)
{
    extern __shared__ char smem[];
    const uint32_t sb = smem_u32(smem);
    const int tid = threadIdx.x, z = blockIdx.z;
    const bool three = (z == sigz);   // gamma: 3-term split + sigmoid

    const __half* Wh = Whp + (size_t)z * WSL;
    const float* bias = (z == 0) ? b0p : (z == 1) ? b1p : (z == 2) ? b2p : b3p;
    float*       C    = (z == 0) ? C0  : (z == 1) ? C1  : (z == 2) ? C2  : C3;

    const int bm = blockIdx.y * 128;
    const int bn = blockIdx.x * 256;
    const size_t aoff = (size_t)bm * KE;
    const size_t boff = (size_t)bn * KE;

    // cp.async mapping: 512 threads; crow 0..127, cch 0..3 (16B chunks)
    const int crow = tid >> 2, cch = tid & 3;
    const uint32_t soc = (uint32_t)crow * 80 + (uint32_t)cch * 16;
    const size_t   goc = (size_t)crow * KE + (size_t)cch * 8;

    // ldmatrix offsets
    const int lane = tid & 31, wid = tid >> 5;
    const int wm = wid >> 2, wn = wid & 3;       // 4x4 warp grid
    const int mA = lane >> 3, rA = lane & 7;
    uint32_t offA[2];
#pragma unroll
    for (int mi = 0; mi < 2; mi++)
        offA[mi] = (uint32_t)((wm * 32 + mi * 16 + (mA & 1) * 8 + rA) * 80 + (mA >> 1) * 16);
    uint32_t offB[4];   // x4 loads: pair of n8 column groups per load
#pragma unroll
    for (int njp = 0; njp < 4; njp++)
        offB[njp] = (uint32_t)((wn * 64 + njp * 16 + (mA >> 1) * 8 + rA) * 80 + (mA & 1) * 16);

    float acc[2][8][4];
#pragma unroll
    for (int mi = 0; mi < 2; mi++)
#pragma unroll
        for (int nj = 0; nj < 8; nj++)
#pragma unroll
            for (int r = 0; r < 4; r++) acc[mi][nj][r] = 0.f;

    auto load_stage = [&](int p, int kt) {
        const uint32_t s = sb + (uint32_t)p * STG;
        cp16(s + PAH + soc, Ahp + aoff + goc + kt);
        cp16(s + PAL + soc, Alp + aoff + goc + kt);
#pragma unroll
        for (int u = 0; u < 2; u++) {
            const uint32_t so2 = soc + (uint32_t)u * 128 * 80;
            const size_t   go2 = goc + (size_t)u * 128 * KE + kt;
            cp16(s + PBH + so2, Wh + boff + go2);
            if (three) cp16(s + PBL + so2, Wlp + boff + go2);
        }
        cp_commit();
    };

    load_stage(0, 0);
    load_stage(1, 32);

    const int NST = KE / 32;  // 128
    for (int i = 0; i < NST; i++) {
        cp_wait<1>();
        __syncthreads();
        if (i + 2 < NST) load_stage((i + 2) % 3, (i + 2) * 32);
        else             cp_commit();

        const uint32_t s = sb + (uint32_t)(i % 3) * STG;
#pragma unroll
        for (int ks = 0; ks < 2; ks++) {
            const uint32_t kb = (uint32_t)ks * 32;
            uint32_t ah[2][4], al[2][4];
#pragma unroll
            for (int mi = 0; mi < 2; mi++) {
                ldm_x4(ah[mi], s + PAH + offA[mi] + kb);
                ldm_x4(al[mi], s + PAL + offA[mi] + kb);
            }
#pragma unroll
            for (int njp = 0; njp < 4; njp++) {
                uint32_t bh[4];
                ldm_x4(bh, s + PBH + offB[njp] + kb);
#pragma unroll
                for (int mi = 0; mi < 2; mi++) {
                    mma4(acc[mi][2 * njp],     ah[mi], bh[0], bh[1]);
                    mma4(acc[mi][2 * njp + 1], ah[mi], bh[2], bh[3]);
                    mma4(acc[mi][2 * njp],     al[mi], bh[0], bh[1]);
                    mma4(acc[mi][2 * njp + 1], al[mi], bh[2], bh[3]);
                }
                if (three) {
                    uint32_t bl[4];
                    ldm_x4(bl, s + PBL + offB[njp] + kb);
#pragma unroll
                    for (int mi = 0; mi < 2; mi++) {
                        mma4(acc[mi][2 * njp],     ah[mi], bl[0], bl[1]);
                        mma4(acc[mi][2 * njp + 1], ah[mi], bl[2], bl[3]);
                    }
                }
            }
        }
    }

    // epilogue
    const int g = lane >> 2, t4 = lane & 3;
#pragma unroll
    for (int mi = 0; mi < 2; mi++) {
#pragma unroll
        for (int nj = 0; nj < 8; nj++) {
            const int row = bm + wm * 32 + mi * 16 + g;
            const int col = bn + wn * 64 + nj * 8 + 2 * t4;
            const float bb0 = bias[col], bb1 = bias[col + 1];
            float v0 = acc[mi][nj][0] + bb0, v1 = acc[mi][nj][1] + bb1;
            float v2 = acc[mi][nj][2] + bb0, v3 = acc[mi][nj][3] + bb1;
            if (three) {
                v0 = 1.f / (1.f + expf(-v0)); v1 = 1.f / (1.f + expf(-v1));
                v2 = 1.f / (1.f + expf(-v2)); v3 = 1.f / (1.f + expf(-v3));
            }
            *(float2*)(C + (size_t)row * NE + col)       = make_float2(v0, v1);
            *(float2*)(C + (size_t)(row + 8) * NE + col) = make_float2(v2, v3);
        }
    }
}

// =====================================================================
// Fused attention: one CTA per (b,h). s=64, d=128.  (unchanged, verified)
// =====================================================================
#define SD 129

__global__ __launch_bounds__(256, 1) void attn_kernel(
    const float* __restrict__ Q, const float* __restrict__ K,
    const float* __restrict__ V, const float* __restrict__ G,
    const float* __restrict__ t, float* __restrict__ O)
{
    extern __shared__ float sm[];
    float* sQ  = sm;
    float* sK  = sm + 64 * SD;
    float* sGc = sm + 2 * 64 * SD;
    float* sGi = sm + 3 * 64 * SD;
    float* sS  = sm + 4 * 64 * SD;

    const int bh = blockIdx.x;
    const int b  = bh >> 5, h = bh & 31;
    const int tid = threadIdx.x;
    const size_t base = ((size_t)b * 64) * 4096 + (size_t)h * 128;

    for (int i = tid; i < 64 * 128; i += 256) {
        const int s = i >> 7, d = i & 127;
        const size_t g = base + (size_t)s * 4096 + d;
        sQ [s * SD + d] = Q[g];
        sK [s * SD + d] = K[g];
        sGc[s * SD + d] = G[g];
    }
    __syncthreads();

    const float LN1E4_64 = 0.14391156531879916f;
    for (int i = tid; i < 64 * 64; i += 256) {
        const int s = i >> 6, q = i & 63;
        const float invf = expf(-(float)s * LN1E4_64);
        const float ang  = t[q] * invf;
        const float cs = cosf(ang), sn = sinf(ang);
        float a, b2;
        a = sQ[s * SD + q]; b2 = sQ[s * SD + q + 64];
        sQ[s * SD + q]      = a * cs - b2 * sn;
        sQ[s * SD + q + 64] = b2 * cs + a * sn;
        a = sK[s * SD + q]; b2 = sK[s * SD + q + 64];
        sK[s * SD + q]      = a * cs - b2 * sn;
        sK[s * SD + q + 64] = b2 * cs + a * sn;
    }
    if (tid < 128) {
        float run = 1.f;
        for (int s = 0; s < 64; s++) {
            run *= sGc[s * SD + tid];
            sGc[s * SD + tid] = run;
            sGi[s * SD + tid] = 1.f / run;
        }
    }
    __syncthreads();

    {
        const int ty = tid >> 4, tx = tid & 15;
        const int q0 = ty * 4, k0 = tx * 4;
        float acc[4][4], dac[4][4];
#pragma unroll
        for (int i = 0; i < 4; i++)
#pragma unroll
            for (int j = 0; j < 4; j++) { acc[i][j] = 0.f; dac[i][j] = 0.f; }

        if (k0 <= q0 + 3) {
            for (int kk = 0; kk < 128; kk++) {
                float qv[4], kv[4], gq[4], gi[4];
#pragma unroll
                for (int i = 0; i < 4; i++) {
                    qv[i] = sQ [(q0 + i) * SD + kk];
                    gq[i] = sGc[(q0 + i) * SD + kk];
                }
#pragma unroll
                for (int j = 0; j < 4; j++) {
                    kv[j] = sK [(k0 + j) * SD + kk];
                    gi[j] = sGi[(k0 + j) * SD + kk];
                }
#pragma unroll
                for (int i = 0; i < 4; i++)
#pragma unroll
                    for (int j = 0; j < 4; j++) {
                        acc[i][j] = fmaf(qv[i], kv[j], acc[i][j]);
                        dac[i][j] = fmaf(gq[i], gi[j], dac[i][j]);
                    }
            }
        }
#pragma unroll
        for (int i = 0; i < 4; i++)
#pragma unroll
            for (int j = 0; j < 4; j++) {
                const int qi = q0 + i, ki = k0 + j;
                sS[qi * 64 + ki] =
                    (ki <= qi) ? acc[i][j] * dac[i][j] * (1.0f / 128.0f) : 0.f;
            }
    }
    __syncthreads();

    for (int i = tid; i < 64 * 128; i += 256) {
        const int s = i >> 7, d = i & 127;
        sK[s * SD + d] = V[base + (size_t)s * 4096 + d];
    }
    __syncthreads();

    {
        const int lane = tid & 31, w = tid >> 5;
        for (int it = 0; it < 8; it++) {
            const int q = it * 8 + w;
            float a0 = 0.f, a1 = 0.f, a2 = 0.f, a3 = 0.f;
            for (int k = 0; k < 64; k++) {
                const float s_ = sS[q * 64 + k];
                const float* vr = &sK[k * SD];
                a0 = fmaf(s_, vr[lane],      a0);
                a1 = fmaf(s_, vr[lane + 32], a1);
                a2 = fmaf(s_, vr[lane + 64], a2);
                a3 = fmaf(s_, vr[lane + 96], a3);
            }
            float* op = O + base + (size_t)q * 4096;
            op[lane]      = a0;
            op[lane + 32] = a1;
            op[lane + 64] = a2;
            op[lane + 96] = a3;
        }
    }
}

// =====================================================================
// launch
// =====================================================================
extern "C" void kernel_launch(void* const* d_in, const int* in_sizes, int n_in,
                              void* d_out, int out_size)
{
    const float* x  = (const float*)d_in[0];
    const float* t  = (const float*)d_in[1];
    const float* Wq = (const float*)d_in[2];
    const float* bq = (const float*)d_in[3];
    const float* Wk = (const float*)d_in[4];
    const float* bk = (const float*)d_in[5];
    const float* Wv = (const float*)d_in[6];
    const float* bv = (const float*)d_in[7];
    const float* Wd = (const float*)d_in[8];
    const float* bd = (const float*)d_in[9];
    const float* Wo = (const float*)d_in[10];
    const float* bo = (const float*)d_in[11];
    float* out = (float*)d_out;

    float *Qb, *Kb, *Vb, *Gb, *Ab;
    __half *xh, *xl, *ah, *al, *wh, *wl;
    cudaGetSymbolAddress((void**)&Qb, g_Q);
    cudaGetSymbolAddress((void**)&Kb, g_K);
    cudaGetSymbolAddress((void**)&Vb, g_V);
    cudaGetSymbolAddress((void**)&Gb, g_G);
    cudaGetSymbolAddress((void**)&Ab, g_A);
    cudaGetSymbolAddress((void**)&xh, g_xh);
    cudaGetSymbolAddress((void**)&xl, g_xl);
    cudaGetSymbolAddress((void**)&ah, g_ah);
    cudaGetSymbolAddress((void**)&al, g_al);
    cudaGetSymbolAddress((void**)&wh, g_wh);
    cudaGetSymbolAddress((void**)&wl, g_wl);

    const int n4x = MTOT * NE / 4;
    const int n4w = NE * KE / 4;
    split_k<<<2048, 256>>>(x,  xh, xl, n4x, 1);
    split_k<<<4096, 256>>>(Wq, wh + 0 * WSL, nullptr, n4w, 0);
    split_k<<<4096, 256>>>(Wk, wh + 1 * WSL, nullptr, n4w, 0);
    split_k<<<4096, 256>>>(Wv, wh + 2 * WSL, nullptr, n4w, 0);
    split_k<<<4096, 256>>>(Wd, wh + 3 * WSL, wl,      n4w, 1);  // gamma: 3-term
    split_k<<<4096, 256>>>(Wo, wh + 4 * WSL, nullptr, n4w, 0);

    cudaFuncSetAttribute(gemm_mma, cudaFuncAttributeMaxDynamicSharedMemorySize, GSMEM);

    // fused Q/K/V/gamma projections (z selects weight slot; z==3 -> 3-term + sigmoid)
    gemm_mma<<<dim3(NE / 256, MTOT / 128, 4), 512, GSMEM>>>(
        xh, xl, wh, wl, bq, bk, bv, bd, Qb, Kb, Vb, Gb, /*sigz=*/3);

    const size_t asmem = (size_t)(4 * 64 * SD + 64 * 64) * sizeof(float);
    cudaFuncSetAttribute(attn_kernel,
                         cudaFuncAttributeMaxDynamicSharedMemorySize, (int)asmem);
    attn_kernel<<<1024, 256, asmem>>>(Qb, Kb, Vb, Gb, t, Ab);

    // output projection (2-term)
    split_k<<<2048, 256>>>(Ab, ah, al, n4x, 1);
    gemm_mma<<<dim3(NE / 256, MTOT / 128, 1), 512, GSMEM>>>(
        ah, al, wh + 4 * WSL, wl, bo, bo, bo, bo, out, out, out, out, /*sigz=*/-1);
}

// round 6
// speedup vs baseline: 3.4187x; 1.1862x over previous
#include <cuda_runtime.h>
#include <cuda_fp16.h>
#include <math.h>
#include <stdint.h>

// Problem constants
#define MTOT 2048   // BATCH*SEQ = 32*64
#define NE   4096   // EMBED_DIM
#define KE   4096
#define WSL  16777216ull   // elements per weight slot (4096*4096)

// ---------------- scratch (allocation-free: __device__ globals) ----------------
__device__ float g_Q[MTOT * NE];
__device__ float g_K[MTOT * NE];
__device__ float g_V[MTOT * NE];
__device__ float g_G[MTOT * NE];
__device__ float g_A[MTOT * NE];

__device__ __half g_xh[MTOT * NE];
__device__ __half g_xl[MTOT * NE];
__device__ __half g_ah[MTOT * NE];
__device__ __half g_al[MTOT * NE];
__device__ __half g_wh[5 * WSL];   // slots: Wq,Wk,Wv,Wd,Wo (hi plane)
__device__ __half g_wl[WSL];       // lo plane, only needed for Wd (gamma)

// =====================================================================
// helpers
// =====================================================================
__device__ __forceinline__ uint32_t smem_u32(const void* p) {
    uint32_t a;
    asm("{ .reg .u64 t; cvta.to.shared.u64 t, %1; cvt.u32.u64 %0, t; }" : "=r"(a) : "l"(p));
    return a;
}
__device__ __forceinline__ void cp16(uint32_t s, const void* g) {
    asm volatile("cp.async.cg.shared.global [%0], [%1], 16;" :: "r"(s), "l"(g));
}
__device__ __forceinline__ void cp_commit() {
    asm volatile("cp.async.commit_group;" ::: "memory");
}
template <int N>
__device__ __forceinline__ void cp_wait() {
    asm volatile("cp.async.wait_group %0;" :: "n"(N) : "memory");
}
__device__ __forceinline__ void ldm_x4(uint32_t* r, uint32_t a) {
    asm volatile("ldmatrix.sync.aligned.m8n8.x4.shared.b16 {%0,%1,%2,%3}, [%4];"
                 : "=r"(r[0]), "=r"(r[1]), "=r"(r[2]), "=r"(r[3]) : "r"(a));
}
__device__ __forceinline__ void mma4(float* c, const uint32_t* a, uint32_t b0, uint32_t b1) {
    asm volatile("mma.sync.aligned.m16n8k16.row.col.f32.f16.f16.f32 "
                 "{%0,%1,%2,%3}, {%4,%5,%6,%7}, {%8,%9}, {%0,%1,%2,%3};"
                 : "+f"(c[0]), "+f"(c[1]), "+f"(c[2]), "+f"(c[3])
                 : "r"(a[0]), "r"(a[1]), "r"(a[2]), "r"(a[3]), "r"(b0), "r"(b1));
}

// =====================================================================
// fp32 -> fp16 hi/lo split (elementwise, float4 granularity)
// =====================================================================
__global__ void split_k(const float* __restrict__ in, __half* __restrict__ hi,
                        __half* __restrict__ lo, int n4, int wlo)
{
    int i = blockIdx.x * blockDim.x + threadIdx.x;
    const int str = gridDim.x * blockDim.x;
    for (; i < n4; i += str) {
        float4 v = ((const float4*)in)[i];
        __half h0 = __float2half(v.x), h1 = __float2half(v.y);
        __half h2 = __float2half(v.z), h3 = __float2half(v.w);
        __half2* hp = (__half2*)hi;
        hp[2 * i]     = __half2(h0, h1);
        hp[2 * i + 1] = __half2(h2, h3);
        if (wlo) {
            __half l0 = __float2half(v.x - __half2float(h0));
            __half l1 = __float2half(v.y - __half2float(h1));
            __half l2 = __float2half(v.z - __half2float(h2));
            __half l3 = __float2half(v.w - __half2float(h3));
            __half2* lp = (__half2*)lo;
            lp[2 * i]     = __half2(l0, l1);
            lp[2 * i + 1] = __half2(l2, l3);
        }
    }
}

// combined split: inA -> hiA+loA, inB -> hiB (one launch; keeps launch #6 = GEMM)
__global__ void split2_k(const float* __restrict__ inA, __half* __restrict__ hiA,
                         __half* __restrict__ loA,
                         const float* __restrict__ inB, __half* __restrict__ hiB, int n4)
{
    int i = blockIdx.x * blockDim.x + threadIdx.x;
    const int str = gridDim.x * blockDim.x;
    for (; i < 2 * n4; i += str) {
        const int sel = (i >= n4);
        const int j = sel ? i - n4 : i;
        const float* in = sel ? inB : inA;
        __half2* hp = (__half2*)(sel ? hiB : hiA);
        float4 v = ((const float4*)in)[j];
        __half h0 = __float2half(v.x), h1 = __float2half(v.y);
        __half h2 = __float2half(v.z), h3 = __float2half(v.w);
        hp[2 * j]     = __half2(h0, h1);
        hp[2 * j + 1] = __half2(h2, h3);
        if (!sel) {
            __half l0 = __float2half(v.x - __half2float(h0));
            __half l1 = __float2half(v.y - __half2float(h1));
            __half l2 = __float2half(v.z - __half2float(h2));
            __half l3 = __float2half(v.w - __half2float(h3));
            __half2* lp = (__half2*)loA;
            lp[2 * j]     = __half2(l0, l1);
            lp[2 * j + 1] = __half2(l2, l3);
        }
    }
}

// =====================================================================
// fp16-split tensor-core GEMM: C[m,n] = sum_k A[m,k]*W[n,k] + bias[n]
//   product = ah*bh + al*bh (2 terms); z==sigz (gamma): + ah*bl (3 terms)
// CTA tile 128x256, BK=32, 8 warps (2m x 4n), warp tile 64x64,
// 3-stage cp.async pipeline, ldmatrix.x4 fragments, 80B-padded rows.
// =====================================================================
#define PAH 0
#define PAL 10240
#define PBH 20480
#define PBL 40960
#define STG 61440
#define GSMEM (3 * STG)   // 184320 bytes

__global__ __launch_bounds__(256, 1) void gemm_mma(
    const __half* __restrict__ Ahp, const __half* __restrict__ Alp,
    const __half* __restrict__ Whp, const __half* __restrict__ Wlp,
    const float* __restrict__ b0p, const float* __restrict__ b1p,
    const float* __restrict__ b2p, const float* __restrict__ b3p,
    float* C0, float* C1, float* C2, float* C3, int sigz)
{
    extern __shared__ char smem[];
    const uint32_t sb = smem_u32(smem);
    const int tid = threadIdx.x, z = blockIdx.z;
    const bool three = (z == sigz);   // gamma: 3-term split + sigmoid

    const __half* Wh = Whp + (size_t)z * WSL;
    const float* bias = (z == 0) ? b0p : (z == 1) ? b1p : (z == 2) ? b2p : b3p;
    float*       C    = (z == 0) ? C0  : (z == 1) ? C1  : (z == 2) ? C2  : C3;

    const int bm = blockIdx.y * 128;
    const int bn = blockIdx.x * 256;
    const size_t aoff = (size_t)bm * KE;
    const size_t boff = (size_t)bn * KE;

    // cp.async mapping: 256 threads; crow 0..63, cch 0..3 (16B chunks)
    const int crow = tid >> 2, cch = tid & 3;
    const uint32_t soc = (uint32_t)crow * 80 + (uint32_t)cch * 16;
    const size_t   goc = (size_t)crow * KE + (size_t)cch * 8;

    // ldmatrix offsets
    const int lane = tid & 31, wid = tid >> 5;
    const int wm = wid >> 2, wn = wid & 3;       // 2x4 warp grid, 64x64 tiles
    const int mA = lane >> 3, rA = lane & 7;
    uint32_t offA[4];
#pragma unroll
    for (int mi = 0; mi < 4; mi++)
        offA[mi] = (uint32_t)((wm * 64 + mi * 16 + (mA & 1) * 8 + rA) * 80 + (mA >> 1) * 16);
    uint32_t offB[4];   // x4: pair of n8 groups (16 rows) per load
#pragma unroll
    for (int njp = 0; njp < 4; njp++)
        offB[njp] = (uint32_t)((wn * 64 + njp * 16 + (mA >> 1) * 8 + rA) * 80 + (mA & 1) * 16);

    float acc[4][8][4];
#pragma unroll
    for (int mi = 0; mi < 4; mi++)
#pragma unroll
        for (int nj = 0; nj < 8; nj++)
#pragma unroll
            for (int r = 0; r < 4; r++) acc[mi][nj][r] = 0.f;

    auto load_stage = [&](int p, int kt) {
        const uint32_t s = sb + (uint32_t)p * STG;
#pragma unroll
        for (int u = 0; u < 2; u++) {
            const uint32_t so2 = soc + (uint32_t)u * 64 * 80;
            const size_t   go2 = goc + (size_t)u * 64 * KE + kt;
            cp16(s + PAH + so2, Ahp + aoff + go2);
            cp16(s + PAL + so2, Alp + aoff + go2);
        }
#pragma unroll
        for (int u = 0; u < 4; u++) {
            const uint32_t so2 = soc + (uint32_t)u * 64 * 80;
            const size_t   go2 = goc + (size_t)u * 64 * KE + kt;
            cp16(s + PBH + so2, Wh + boff + go2);
            if (three) cp16(s + PBL + so2, Wlp + boff + go2);
        }
        cp_commit();
    };

    load_stage(0, 0);
    load_stage(1, 32);

    const int NST = KE / 32;  // 128
    for (int i = 0; i < NST; i++) {
        cp_wait<1>();
        __syncthreads();
        if (i + 2 < NST) load_stage((i + 2) % 3, (i + 2) * 32);
        else             cp_commit();

        const uint32_t s = sb + (uint32_t)(i % 3) * STG;
#pragma unroll
        for (int ks = 0; ks < 2; ks++) {
            const uint32_t kb = (uint32_t)ks * 32;
            uint32_t ah[4][4], al[4][4];
#pragma unroll
            for (int mi = 0; mi < 4; mi++) {
                ldm_x4(ah[mi], s + PAH + offA[mi] + kb);
                ldm_x4(al[mi], s + PAL + offA[mi] + kb);
            }
#pragma unroll
            for (int njp = 0; njp < 4; njp++) {
                uint32_t bh[4];
                ldm_x4(bh, s + PBH + offB[njp] + kb);
#pragma unroll
                for (int mi = 0; mi < 4; mi++) {
                    mma4(acc[mi][2 * njp],     ah[mi], bh[0], bh[1]);
                    mma4(acc[mi][2 * njp + 1], ah[mi], bh[2], bh[3]);
                    mma4(acc[mi][2 * njp],     al[mi], bh[0], bh[1]);
                    mma4(acc[mi][2 * njp + 1], al[mi], bh[2], bh[3]);
                }
                if (three) {
                    uint32_t bl[4];
                    ldm_x4(bl, s + PBL + offB[njp] + kb);
#pragma unroll
                    for (int mi = 0; mi < 4; mi++) {
                        mma4(acc[mi][2 * njp],     ah[mi], bl[0], bl[1]);
                        mma4(acc[mi][2 * njp + 1], ah[mi], bl[2], bl[3]);
                    }
                }
            }
        }
    }

    // epilogue
    const int g = lane >> 2, t4 = lane & 3;
#pragma unroll
    for (int mi = 0; mi < 4; mi++) {
#pragma unroll
        for (int nj = 0; nj < 8; nj++) {
            const int row = bm + wm * 64 + mi * 16 + g;
            const int col = bn + wn * 64 + nj * 8 + 2 * t4;
            const float bb0 = bias[col], bb1 = bias[col + 1];
            float v0 = acc[mi][nj][0] + bb0, v1 = acc[mi][nj][1] + bb1;
            float v2 = acc[mi][nj][2] + bb0, v3 = acc[mi][nj][3] + bb1;
            if (three) {
                v0 = 1.f / (1.f + expf(-v0)); v1 = 1.f / (1.f + expf(-v1));
                v2 = 1.f / (1.f + expf(-v2)); v3 = 1.f / (1.f + expf(-v3));
            }
            *(float2*)(C + (size_t)row * NE + col)       = make_float2(v0, v1);
            *(float2*)(C + (size_t)(row + 8) * NE + col) = make_float2(v2, v3);
        }
    }
}

// =====================================================================
// Fused attention: one CTA per (b,h). s=64, d=128.  (unchanged, verified)
// =====================================================================
#define SD 129

__global__ __launch_bounds__(256, 1) void attn_kernel(
    const float* __restrict__ Q, const float* __restrict__ K,
    const float* __restrict__ V, const float* __restrict__ G,
    const float* __restrict__ t, float* __restrict__ O)
{
    extern __shared__ float sm[];
    float* sQ  = sm;
    float* sK  = sm + 64 * SD;
    float* sGc = sm + 2 * 64 * SD;
    float* sGi = sm + 3 * 64 * SD;
    float* sS  = sm + 4 * 64 * SD;

    const int bh = blockIdx.x;
    const int b  = bh >> 5, h = bh & 31;
    const int tid = threadIdx.x;
    const size_t base = ((size_t)b * 64) * 4096 + (size_t)h * 128;

    for (int i = tid; i < 64 * 128; i += 256) {
        const int s = i >> 7, d = i & 127;
        const size_t g = base + (size_t)s * 4096 + d;
        sQ [s * SD + d] = Q[g];
        sK [s * SD + d] = K[g];
        sGc[s * SD + d] = G[g];
    }
    __syncthreads();

    const float LN1E4_64 = 0.14391156531879916f;
    for (int i = tid; i < 64 * 64; i += 256) {
        const int s = i >> 6, q = i & 63;
        const float invf = expf(-(float)s * LN1E4_64);
        const float ang  = t[q] * invf;
        const float cs = cosf(ang), sn = sinf(ang);
        float a, b2;
        a = sQ[s * SD + q]; b2 = sQ[s * SD + q + 64];
        sQ[s * SD + q]      = a * cs - b2 * sn;
        sQ[s * SD + q + 64] = b2 * cs + a * sn;
        a = sK[s * SD + q]; b2 = sK[s * SD + q + 64];
        sK[s * SD + q]      = a * cs - b2 * sn;
        sK[s * SD + q + 64] = b2 * cs + a * sn;
    }
    if (tid < 128) {
        float run = 1.f;
        for (int s = 0; s < 64; s++) {
            run *= sGc[s * SD + tid];
            sGc[s * SD + tid] = run;
            sGi[s * SD + tid] = 1.f / run;
        }
    }
    __syncthreads();

    {
        const int ty = tid >> 4, tx = tid & 15;
        const int q0 = ty * 4, k0 = tx * 4;
        float acc[4][4], dac[4][4];
#pragma unroll
        for (int i = 0; i < 4; i++)
#pragma unroll
            for (int j = 0; j < 4; j++) { acc[i][j] = 0.f; dac[i][j] = 0.f; }

        if (k0 <= q0 + 3) {
            for (int kk = 0; kk < 128; kk++) {
                float qv[4], kv[4], gq[4], gi[4];
#pragma unroll
                for (int i = 0; i < 4; i++) {
                    qv[i] = sQ [(q0 + i) * SD + kk];
                    gq[i] = sGc[(q0 + i) * SD + kk];
                }
#pragma unroll
                for (int j = 0; j < 4; j++) {
                    kv[j] = sK [(k0 + j) * SD + kk];
                    gi[j] = sGi[(k0 + j) * SD + kk];
                }
#pragma unroll
                for (int i = 0; i < 4; i++)
#pragma unroll
                    for (int j = 0; j < 4; j++) {
                        acc[i][j] = fmaf(qv[i], kv[j], acc[i][j]);
                        dac[i][j] = fmaf(gq[i], gi[j], dac[i][j]);
                    }
            }
        }
#pragma unroll
        for (int i = 0; i < 4; i++)
#pragma unroll
            for (int j = 0; j < 4; j++) {
                const int qi = q0 + i, ki = k0 + j;
                sS[qi * 64 + ki] =
                    (ki <= qi) ? acc[i][j] * dac[i][j] * (1.0f / 128.0f) : 0.f;
            }
    }
    __syncthreads();

    for (int i = tid; i < 64 * 128; i += 256) {
        const int s = i >> 7, d = i & 127;
        sK[s * SD + d] = V[base + (size_t)s * 4096 + d];
    }
    __syncthreads();

    {
        const int lane = tid & 31, w = tid >> 5;
        for (int it = 0; it < 8; it++) {
            const int q = it * 8 + w;
            float a0 = 0.f, a1 = 0.f, a2 = 0.f, a3 = 0.f;
            for (int k = 0; k < 64; k++) {
                const float s_ = sS[q * 64 + k];
                const float* vr = &sK[k * SD];
                a0 = fmaf(s_, vr[lane],      a0);
                a1 = fmaf(s_, vr[lane + 32], a1);
                a2 = fmaf(s_, vr[lane + 64], a2);
                a3 = fmaf(s_, vr[lane + 96], a3);
            }
            float* op = O + base + (size_t)q * 4096;
            op[lane]      = a0;
            op[lane + 32] = a1;
            op[lane + 64] = a2;
            op[lane + 96] = a3;
        }
    }
}

// =====================================================================
// launch (exactly 5 launches before the QKVG GEMM so ncu -s 5 -c 1
// captures gemm_mma)
// =====================================================================
extern "C" void kernel_launch(void* const* d_in, const int* in_sizes, int n_in,
                              void* d_out, int out_size)
{
    const float* x  = (const float*)d_in[0];
    const float* t  = (const float*)d_in[1];
    const float* Wq = (const float*)d_in[2];
    const float* bq = (const float*)d_in[3];
    const float* Wk = (const float*)d_in[4];
    const float* bk = (const float*)d_in[5];
    const float* Wv = (const float*)d_in[6];
    const float* bv = (const float*)d_in[7];
    const float* Wd = (const float*)d_in[8];
    const float* bd = (const float*)d_in[9];
    const float* Wo = (const float*)d_in[10];
    const float* bo = (const float*)d_in[11];
    float* out = (float*)d_out;

    float *Qb, *Kb, *Vb, *Gb, *Ab;
    __half *xh, *xl, *ah, *al, *wh, *wl;
    cudaGetSymbolAddress((void**)&Qb, g_Q);
    cudaGetSymbolAddress((void**)&Kb, g_K);
    cudaGetSymbolAddress((void**)&Vb, g_V);
    cudaGetSymbolAddress((void**)&Gb, g_G);
    cudaGetSymbolAddress((void**)&Ab, g_A);
    cudaGetSymbolAddress((void**)&xh, g_xh);
    cudaGetSymbolAddress((void**)&xl, g_xl);
    cudaGetSymbolAddress((void**)&ah, g_ah);
    cudaGetSymbolAddress((void**)&al, g_al);
    cudaGetSymbolAddress((void**)&wh, g_wh);
    cudaGetSymbolAddress((void**)&wl, g_wl);

    const int n4x = MTOT * NE / 4;
    const int n4w = NE * KE / 4;
    // launches 1-5
    split_k<<<2048, 256>>>(x,  xh, xl, n4x, 1);
    split_k<<<4096, 256>>>(Wq, wh + 0 * WSL, nullptr, n4w, 0);
    split_k<<<4096, 256>>>(Wk, wh + 1 * WSL, nullptr, n4w, 0);
    split_k<<<4096, 256>>>(Wv, wh + 2 * WSL, nullptr, n4w, 0);
    split2_k<<<8192, 256>>>(Wd, wh + 3 * WSL, wl, Wo, wh + 4 * WSL, n4w);

    cudaFuncSetAttribute(gemm_mma, cudaFuncAttributeMaxDynamicSharedMemorySize, GSMEM);

    // launch 6 (ncu-captured): fused Q/K/V/gamma projections
    gemm_mma<<<dim3(NE / 256, MTOT / 128, 4), 256, GSMEM>>>(
        xh, xl, wh, wl, bq, bk, bv, bd, Qb, Kb, Vb, Gb, /*sigz=*/3);

    const size_t asmem = (size_t)(4 * 64 * SD + 64 * 64) * sizeof(float);
    cudaFuncSetAttribute(attn_kernel,
                         cudaFuncAttributeMaxDynamicSharedMemorySize, (int)asmem);
    attn_kernel<<<1024, 256, asmem>>>(Qb, Kb, Vb, Gb, t, Ab);

    // output projection (2-term)
    split_k<<<2048, 256>>>(Ab, ah, al, n4x, 1);
    gemm_mma<<<dim3(NE / 256, MTOT / 128, 1), 256, GSMEM>>>(
        ah, al, wh + 4 * WSL, wl, bo, bo, bo, bo, out, out, out, out, /*sigz=*/-1);
}

// round 7
// speedup vs baseline: 3.4886x; 1.0204x over previous
#include <cuda_runtime.h>
#include <cuda_fp16.h>
#include <math.h>
#include <stdint.h>

// Problem constants
#define MTOT 2048   // BATCH*SEQ = 32*64
#define NE   4096   // EMBED_DIM
#define KE   4096
#define WSL  16777216ull   // elements per weight slot (4096*4096)

// ---------------- scratch (allocation-free: __device__ globals) ----------------
__device__ float g_Q[MTOT * NE];
__device__ float g_K[MTOT * NE];
__device__ float g_V[MTOT * NE];
__device__ float g_G[MTOT * NE];
__device__ float g_A[MTOT * NE];

__device__ __half g_xh[MTOT * NE];
__device__ __half g_xl[MTOT * NE];
__device__ __half g_ah[MTOT * NE];
__device__ __half g_al[MTOT * NE];
__device__ __half g_wh[5 * WSL];   // slots: Wq,Wk,Wv,Wd,Wo (hi plane)
__device__ __half g_wl[WSL];       // lo plane, only needed for Wd (gamma)

// =====================================================================
// helpers
// =====================================================================
__device__ __forceinline__ uint32_t smem_u32(const void* p) {
    uint32_t a;
    asm("{ .reg .u64 t; cvta.to.shared.u64 t, %1; cvt.u32.u64 %0, t; }" : "=r"(a) : "l"(p));
    return a;
}
__device__ __forceinline__ void cp16(uint32_t s, const void* g) {
    asm volatile("cp.async.cg.shared.global [%0], [%1], 16;" :: "r"(s), "l"(g));
}
__device__ __forceinline__ void cp_commit() {
    asm volatile("cp.async.commit_group;" ::: "memory");
}
template <int N>
__device__ __forceinline__ void cp_wait() {
    asm volatile("cp.async.wait_group %0;" :: "n"(N) : "memory");
}
__device__ __forceinline__ void ldm_x4(uint32_t* r, uint32_t a) {
    asm volatile("ldmatrix.sync.aligned.m8n8.x4.shared.b16 {%0,%1,%2,%3}, [%4];"
                 : "=r"(r[0]), "=r"(r[1]), "=r"(r[2]), "=r"(r[3]) : "r"(a));
}
__device__ __forceinline__ void mma4(float* c, const uint32_t* a, uint32_t b0, uint32_t b1) {
    asm volatile("mma.sync.aligned.m16n8k16.row.col.f32.f16.f16.f32 "
                 "{%0,%1,%2,%3}, {%4,%5,%6,%7}, {%8,%9}, {%0,%1,%2,%3};"
                 : "+f"(c[0]), "+f"(c[1]), "+f"(c[2]), "+f"(c[3])
                 : "r"(a[0]), "r"(a[1]), "r"(a[2]), "r"(a[3]), "r"(b0), "r"(b1));
}

// =====================================================================
// fp32 -> fp16 hi/lo split (elementwise, float4 granularity)
// =====================================================================
__global__ void split_k(const float* __restrict__ in, __half* __restrict__ hi,
                        __half* __restrict__ lo, int n4, int wlo)
{
    int i = blockIdx.x * blockDim.x + threadIdx.x;
    const int str = gridDim.x * blockDim.x;
    for (; i < n4; i += str) {
        float4 v = ((const float4*)in)[i];
        __half h0 = __float2half(v.x), h1 = __float2half(v.y);
        __half h2 = __float2half(v.z), h3 = __float2half(v.w);
        __half2* hp = (__half2*)hi;
        hp[2 * i]     = __half2(h0, h1);
        hp[2 * i + 1] = __half2(h2, h3);
        if (wlo) {
            __half l0 = __float2half(v.x - __half2float(h0));
            __half l1 = __float2half(v.y - __half2float(h1));
            __half l2 = __float2half(v.z - __half2float(h2));
            __half l3 = __float2half(v.w - __half2float(h3));
            __half2* lp = (__half2*)lo;
            lp[2 * i]     = __half2(l0, l1);
            lp[2 * i + 1] = __half2(l2, l3);
        }
    }
}

// all 5 weights in one launch: hi planes for slots 0..4; lo plane only for slot 3 (Wd)
__global__ void split_w(const float* __restrict__ w0, const float* __restrict__ w1,
                        const float* __restrict__ w2, const float* __restrict__ w3,
                        const float* __restrict__ w4,
                        __half* __restrict__ wh, __half* __restrict__ wl, int n4w)
{
    int i = blockIdx.x * blockDim.x + threadIdx.x;
    const int str = gridDim.x * blockDim.x;
    const int tot = 5 * n4w;
    for (; i < tot; i += str) {
        const int slot = i / n4w;
        const int j = i - slot * n4w;
        const float* in = (slot == 0) ? w0 : (slot == 1) ? w1 : (slot == 2) ? w2
                        : (slot == 3) ? w3 : w4;
        float4 v = ((const float4*)in)[j];
        __half h0 = __float2half(v.x), h1 = __float2half(v.y);
        __half h2 = __float2half(v.z), h3 = __float2half(v.w);
        __half2* hp = (__half2*)(wh + (size_t)slot * WSL);
        hp[2 * j]     = __half2(h0, h1);
        hp[2 * j + 1] = __half2(h2, h3);
        if (slot == 3) {
            __half l0 = __float2half(v.x - __half2float(h0));
            __half l1 = __float2half(v.y - __half2float(h1));
            __half l2 = __float2half(v.z - __half2float(h2));
            __half l3 = __float2half(v.w - __half2float(h3));
            __half2* lp = (__half2*)wl;
            lp[2 * j]     = __half2(l0, l1);
            lp[2 * j + 1] = __half2(l2, l3);
        }
    }
}

// =====================================================================
// fp16-split tensor-core GEMM: C[m,n] = sum_k A[m,k]*W[n,k] + bias[n]
//   product = ah*bh + al*bh (2 terms); z==sigz (gamma): + ah*bl (3 terms)
// CTA tile 128x256, BK=32, 8 warps (2m x 4n), warp tile 64x64,
// 3-stage cp.async pipeline, ldmatrix.x4 fragments, 80B-padded rows.
// Inner loop batches all fragment loads, then issues all hi-term MMAs
// before lo-term MMAs: accumulator reuse distance 2 -> 32 MMAs.
// =====================================================================
#define PAH 0
#define PAL 10240
#define PBH 20480
#define PBL 40960
#define STG 61440
#define GSMEM (3 * STG)   // 184320 bytes

__global__ __launch_bounds__(256, 1) void gemm_mma(
    const __half* __restrict__ Ahp, const __half* __restrict__ Alp,
    const __half* __restrict__ Whp, const __half* __restrict__ Wlp,
    const float* __restrict__ b0p, const float* __restrict__ b1p,
    const float* __restrict__ b2p, const float* __restrict__ b3p,
    float* C0, float* C1, float* C2, float* C3, int sigz)
{
    extern __shared__ char smem[];
    const uint32_t sb = smem_u32(smem);
    const int tid = threadIdx.x, z = blockIdx.z;
    const bool three = (z == sigz);   // gamma: 3-term split + sigmoid

    const __half* Wh = Whp + (size_t)z * WSL;
    const float* bias = (z == 0) ? b0p : (z == 1) ? b1p : (z == 2) ? b2p : b3p;
    float*       C    = (z == 0) ? C0  : (z == 1) ? C1  : (z == 2) ? C2  : C3;

    const int bm = blockIdx.y * 128;
    const int bn = blockIdx.x * 256;
    const size_t aoff = (size_t)bm * KE;
    const size_t boff = (size_t)bn * KE;

    // cp.async mapping: 256 threads; crow 0..63, cch 0..3 (16B chunks)
    const int crow = tid >> 2, cch = tid & 3;
    const uint32_t soc = (uint32_t)crow * 80 + (uint32_t)cch * 16;
    const size_t   goc = (size_t)crow * KE + (size_t)cch * 8;

    // ldmatrix offsets
    const int lane = tid & 31, wid = tid >> 5;
    const int wm = wid >> 2, wn = wid & 3;       // 2x4 warp grid, 64x64 tiles
    const int mA = lane >> 3, rA = lane & 7;
    uint32_t offA[4];
#pragma unroll
    for (int mi = 0; mi < 4; mi++)
        offA[mi] = (uint32_t)((wm * 64 + mi * 16 + (mA & 1) * 8 + rA) * 80 + (mA >> 1) * 16);
    uint32_t offB[4];   // x4: pair of n8 groups (16 rows) per load
#pragma unroll
    for (int njp = 0; njp < 4; njp++)
        offB[njp] = (uint32_t)((wn * 64 + njp * 16 + (mA >> 1) * 8 + rA) * 80 + (mA & 1) * 16);

    float acc[4][8][4];
#pragma unroll
    for (int mi = 0; mi < 4; mi++)
#pragma unroll
        for (int nj = 0; nj < 8; nj++)
#pragma unroll
            for (int r = 0; r < 4; r++) acc[mi][nj][r] = 0.f;

    auto load_stage = [&](int p, int kt) {
        const uint32_t s = sb + (uint32_t)p * STG;
#pragma unroll
        for (int u = 0; u < 2; u++) {
            const uint32_t so2 = soc + (uint32_t)u * 64 * 80;
            const size_t   go2 = goc + (size_t)u * 64 * KE + kt;
            cp16(s + PAH + so2, Ahp + aoff + go2);
            cp16(s + PAL + so2, Alp + aoff + go2);
        }
#pragma unroll
        for (int u = 0; u < 4; u++) {
            const uint32_t so2 = soc + (uint32_t)u * 64 * 80;
            const size_t   go2 = goc + (size_t)u * 64 * KE + kt;
            cp16(s + PBH + so2, Wh + boff + go2);
            if (three) cp16(s + PBL + so2, Wlp + boff + go2);
        }
        cp_commit();
    };

    load_stage(0, 0);
    load_stage(1, 32);

    const int NST = KE / 32;  // 128
    for (int i = 0; i < NST; i++) {
        cp_wait<1>();
        __syncthreads();
        if (i + 2 < NST) load_stage((i + 2) % 3, (i + 2) * 32);
        else             cp_commit();

        const uint32_t s = sb + (uint32_t)(i % 3) * STG;
#pragma unroll
        for (int ks = 0; ks < 2; ks++) {
            const uint32_t kb = (uint32_t)ks * 32;
            // batch all fragment loads first
            uint32_t ah[4][4], al[4][4], bh[4][4];
#pragma unroll
            for (int mi = 0; mi < 4; mi++) {
                ldm_x4(ah[mi], s + PAH + offA[mi] + kb);
                ldm_x4(al[mi], s + PAL + offA[mi] + kb);
            }
#pragma unroll
            for (int njp = 0; njp < 4; njp++)
                ldm_x4(bh[njp], s + PBH + offB[njp] + kb);

            // all hi-term MMAs (16 independent accumulator chains)
#pragma unroll
            for (int njp = 0; njp < 4; njp++)
#pragma unroll
                for (int mi = 0; mi < 4; mi++) {
                    mma4(acc[mi][2 * njp],     ah[mi], bh[njp][0], bh[njp][1]);
                    mma4(acc[mi][2 * njp + 1], ah[mi], bh[njp][2], bh[njp][3]);
                }
            // all lo-term MMAs (each acc reused 32 MMAs later)
#pragma unroll
            for (int njp = 0; njp < 4; njp++)
#pragma unroll
                for (int mi = 0; mi < 4; mi++) {
                    mma4(acc[mi][2 * njp],     al[mi], bh[njp][0], bh[njp][1]);
                    mma4(acc[mi][2 * njp + 1], al[mi], bh[njp][2], bh[njp][3]);
                }
            if (three) {
#pragma unroll
                for (int njp = 0; njp < 4; njp++) {
                    uint32_t bl[4];
                    ldm_x4(bl, s + PBL + offB[njp] + kb);
#pragma unroll
                    for (int mi = 0; mi < 4; mi++) {
                        mma4(acc[mi][2 * njp],     ah[mi], bl[0], bl[1]);
                        mma4(acc[mi][2 * njp + 1], ah[mi], bl[2], bl[3]);
                    }
                }
            }
        }
    }

    // epilogue
    const int g = lane >> 2, t4 = lane & 3;
#pragma unroll
    for (int mi = 0; mi < 4; mi++) {
#pragma unroll
        for (int nj = 0; nj < 8; nj++) {
            const int row = bm + wm * 64 + mi * 16 + g;
            const int col = bn + wn * 64 + nj * 8 + 2 * t4;
            const float bb0 = bias[col], bb1 = bias[col + 1];
            float v0 = acc[mi][nj][0] + bb0, v1 = acc[mi][nj][1] + bb1;
            float v2 = acc[mi][nj][2] + bb0, v3 = acc[mi][nj][3] + bb1;
            if (three) {
                v0 = 1.f / (1.f + expf(-v0)); v1 = 1.f / (1.f + expf(-v1));
                v2 = 1.f / (1.f + expf(-v2)); v3 = 1.f / (1.f + expf(-v3));
            }
            *(float2*)(C + (size_t)row * NE + col)       = make_float2(v0, v1);
            *(float2*)(C + (size_t)(row + 8) * NE + col) = make_float2(v2, v3);
        }
    }
}

// =====================================================================
// Fused attention: one CTA per (b,h). s=64, d=128.  (unchanged, verified)
// =====================================================================
#define SD 129

__global__ __launch_bounds__(256, 1) void attn_kernel(
    const float* __restrict__ Q, const float* __restrict__ K,
    const float* __restrict__ V, const float* __restrict__ G,
    const float* __restrict__ t, float* __restrict__ O)
{
    extern __shared__ float sm[];
    float* sQ  = sm;
    float* sK  = sm + 64 * SD;
    float* sGc = sm + 2 * 64 * SD;
    float* sGi = sm + 3 * 64 * SD;
    float* sS  = sm + 4 * 64 * SD;

    const int bh = blockIdx.x;
    const int b  = bh >> 5, h = bh & 31;
    const int tid = threadIdx.x;
    const size_t base = ((size_t)b * 64) * 4096 + (size_t)h * 128;

    for (int i = tid; i < 64 * 128; i += 256) {
        const int s = i >> 7, d = i & 127;
        const size_t g = base + (size_t)s * 4096 + d;
        sQ [s * SD + d] = Q[g];
        sK [s * SD + d] = K[g];
        sGc[s * SD + d] = G[g];
    }
    __syncthreads();

    const float LN1E4_64 = 0.14391156531879916f;
    for (int i = tid; i < 64 * 64; i += 256) {
        const int s = i >> 6, q = i & 63;
        const float invf = expf(-(float)s * LN1E4_64);
        const float ang  = t[q] * invf;
        const float cs = cosf(ang), sn = sinf(ang);
        float a, b2;
        a = sQ[s * SD + q]; b2 = sQ[s * SD + q + 64];
        sQ[s * SD + q]      = a * cs - b2 * sn;
        sQ[s * SD + q + 64] = b2 * cs + a * sn;
        a = sK[s * SD + q]; b2 = sK[s * SD + q + 64];
        sK[s * SD + q]      = a * cs - b2 * sn;
        sK[s * SD + q + 64] = b2 * cs + a * sn;
    }
    if (tid < 128) {
        float run = 1.f;
        for (int s = 0; s < 64; s++) {
            run *= sGc[s * SD + tid];
            sGc[s * SD + tid] = run;
            sGi[s * SD + tid] = 1.f / run;
        }
    }
    __syncthreads();

    {
        const int ty = tid >> 4, tx = tid & 15;
        const int q0 = ty * 4, k0 = tx * 4;
        float acc[4][4], dac[4][4];
#pragma unroll
        for (int i = 0; i < 4; i++)
#pragma unroll
            for (int j = 0; j < 4; j++) { acc[i][j] = 0.f; dac[i][j] = 0.f; }

        if (k0 <= q0 + 3) {
            for (int kk = 0; kk < 128; kk++) {
                float qv[4], kv[4], gq[4], gi[4];
#pragma unroll
                for (int i = 0; i < 4; i++) {
                    qv[i] = sQ [(q0 + i) * SD + kk];
                    gq[i] = sGc[(q0 + i) * SD + kk];
                }
#pragma unroll
                for (int j = 0; j < 4; j++) {
                    kv[j] = sK [(k0 + j) * SD + kk];
                    gi[j] = sGi[(k0 + j) * SD + kk];
                }
#pragma unroll
                for (int i = 0; i < 4; i++)
#pragma unroll
                    for (int j = 0; j < 4; j++) {
                        acc[i][j] = fmaf(qv[i], kv[j], acc[i][j]);
                        dac[i][j] = fmaf(gq[i], gi[j], dac[i][j]);
                    }
            }
        }
#pragma unroll
        for (int i = 0; i < 4; i++)
#pragma unroll
            for (int j = 0; j < 4; j++) {
                const int qi = q0 + i, ki = k0 + j;
                sS[qi * 64 + ki] =
                    (ki <= qi) ? acc[i][j] * dac[i][j] * (1.0f / 128.0f) : 0.f;
            }
    }
    __syncthreads();

    for (int i = tid; i < 64 * 128; i += 256) {
        const int s = i >> 7, d = i & 127;
        sK[s * SD + d] = V[base + (size_t)s * 4096 + d];
    }
    __syncthreads();

    {
        const int lane = tid & 31, w = tid >> 5;
        for (int it = 0; it < 8; it++) {
            const int q = it * 8 + w;
            float a0 = 0.f, a1 = 0.f, a2 = 0.f, a3 = 0.f;
            for (int k = 0; k < 64; k++) {
                const float s_ = sS[q * 64 + k];
                const float* vr = &sK[k * SD];
                a0 = fmaf(s_, vr[lane],      a0);
                a1 = fmaf(s_, vr[lane + 32], a1);
                a2 = fmaf(s_, vr[lane + 64], a2);
                a3 = fmaf(s_, vr[lane + 96], a3);
            }
            float* op = O + base + (size_t)q * 4096;
            op[lane]      = a0;
            op[lane + 32] = a1;
            op[lane + 64] = a2;
            op[lane + 96] = a3;
        }
    }
}

// =====================================================================
// launch: split_x, split_w, gemm_qkvg, attn, split_a, gemm_o
// =====================================================================
extern "C" void kernel_launch(void* const* d_in, const int* in_sizes, int n_in,
                              void* d_out, int out_size)
{
    const float* x  = (const float*)d_in[0];
    const float* t  = (const float*)d_in[1];
    const float* Wq = (const float*)d_in[2];
    const float* bq = (const float*)d_in[3];
    const float* Wk = (const float*)d_in[4];
    const float* bk = (const float*)d_in[5];
    const float* Wv = (const float*)d_in[6];
    const float* bv = (const float*)d_in[7];
    const float* Wd = (const float*)d_in[8];
    const float* bd = (const float*)d_in[9];
    const float* Wo = (const float*)d_in[10];
    const float* bo = (const float*)d_in[11];
    float* out = (float*)d_out;

    float *Qb, *Kb, *Vb, *Gb, *Ab;
    __half *xh, *xl, *ah, *al, *wh, *wl;
    cudaGetSymbolAddress((void**)&Qb, g_Q);
    cudaGetSymbolAddress((void**)&Kb, g_K);
    cudaGetSymbolAddress((void**)&Vb, g_V);
    cudaGetSymbolAddress((void**)&Gb, g_G);
    cudaGetSymbolAddress((void**)&Ab, g_A);
    cudaGetSymbolAddress((void**)&xh, g_xh);
    cudaGetSymbolAddress((void**)&xl, g_xl);
    cudaGetSymbolAddress((void**)&ah, g_ah);
    cudaGetSymbolAddress((void**)&al, g_al);
    cudaGetSymbolAddress((void**)&wh, g_wh);
    cudaGetSymbolAddress((void**)&wl, g_wl);

    const int n4x = MTOT * NE / 4;
    const int n4w = NE * KE / 4;
    split_k<<<2048, 256>>>(x, xh, xl, n4x, 1);
    split_w<<<16384, 256>>>(Wq, Wk, Wv, Wd, Wo, wh, wl, n4w);

    cudaFuncSetAttribute(gemm_mma, cudaFuncAttributeMaxDynamicSharedMemorySize, GSMEM);

    // fused Q/K/V/gamma projections
    gemm_mma<<<dim3(NE / 256, MTOT / 128, 4), 256, GSMEM>>>(
        xh, xl, wh, wl, bq, bk, bv, bd, Qb, Kb, Vb, Gb, /*sigz=*/3);

    const size_t asmem = (size_t)(4 * 64 * SD + 64 * 64) * sizeof(float);
    cudaFuncSetAttribute(attn_kernel,
                         cudaFuncAttributeMaxDynamicSharedMemorySize, (int)asmem);
    attn_kernel<<<1024, 256, asmem>>>(Qb, Kb, Vb, Gb, t, Ab);

    // output projection (2-term)
    split_k<<<2048, 256>>>(Ab, ah, al, n4x, 1);
    gemm_mma<<<dim3(NE / 256, MTOT / 128, 1), 256, GSMEM>>>(
        ah, al, wh + 4 * WSL, wl, bo, bo, bo, bo, out, out, out, out, /*sigz=*/-1);
}

// round 8
// speedup vs baseline: 3.5812x; 1.0266x over previous
#include <cuda_runtime.h>
#include <cuda_fp16.h>
#include <math.h>
#include <stdint.h>

// Problem constants
#define MTOT 2048   // BATCH*SEQ = 32*64
#define NE   4096   // EMBED_DIM
#define KE   4096
#define WSL  16777216ull   // elements per weight slot (4096*4096)

// ---------------- scratch (allocation-free: __device__ globals) ----------------
__device__ float g_Q[MTOT * NE];
__device__ float g_K[MTOT * NE];
__device__ float g_V[MTOT * NE];
__device__ float g_G[MTOT * NE];

__device__ __half g_xh[MTOT * NE];
__device__ __half g_xl[MTOT * NE];
__device__ __half g_ah[MTOT * NE];
__device__ __half g_al[MTOT * NE];
__device__ __half g_wh[5 * WSL];   // slots: Wq,Wk,Wv,Wd,Wo (hi plane)
__device__ __half g_wl[WSL];       // lo plane, only needed for Wd (gamma)

// =====================================================================
// helpers
// =====================================================================
__device__ __forceinline__ uint32_t smem_u32(const void* p) {
    uint32_t a;
    asm("{ .reg .u64 t; cvta.to.shared.u64 t, %1; cvt.u32.u64 %0, t; }" : "=r"(a) : "l"(p));
    return a;
}
__device__ __forceinline__ void cp16(uint32_t s, const void* g) {
    asm volatile("cp.async.cg.shared.global [%0], [%1], 16;" :: "r"(s), "l"(g));
}
__device__ __forceinline__ void cp_commit() {
    asm volatile("cp.async.commit_group;" ::: "memory");
}
template <int N>
__device__ __forceinline__ void cp_wait() {
    asm volatile("cp.async.wait_group %0;" :: "n"(N) : "memory");
}
__device__ __forceinline__ void ldm_x4(uint32_t* r, uint32_t a) {
    asm volatile("ldmatrix.sync.aligned.m8n8.x4.shared.b16 {%0,%1,%2,%3}, [%4];"
                 : "=r"(r[0]), "=r"(r[1]), "=r"(r[2]), "=r"(r[3]) : "r"(a));
}
__device__ __forceinline__ void mma4(float* c, const uint32_t* a, uint32_t b0, uint32_t b1) {
    asm volatile("mma.sync.aligned.m16n8k16.row.col.f32.f16.f16.f32 "
                 "{%0,%1,%2,%3}, {%4,%5,%6,%7}, {%8,%9}, {%0,%1,%2,%3};"
                 : "+f"(c[0]), "+f"(c[1]), "+f"(c[2]), "+f"(c[3])
                 : "r"(a[0]), "r"(a[1]), "r"(a[2]), "r"(a[3]), "r"(b0), "r"(b1));
}

// =====================================================================
// fp32 -> fp16 hi/lo split (x and attention activations)
// =====================================================================
__global__ void split_k(const float* __restrict__ in, __half* __restrict__ hi,
                        __half* __restrict__ lo, int n4, int wlo)
{
    int i = blockIdx.x * blockDim.x + threadIdx.x;
    const int str = gridDim.x * blockDim.x;
    for (; i < n4; i += str) {
        float4 v = ((const float4*)in)[i];
        __half h0 = __float2half(v.x), h1 = __float2half(v.y);
        __half h2 = __float2half(v.z), h3 = __float2half(v.w);
        __half2* hp = (__half2*)hi;
        hp[2 * i]     = __half2(h0, h1);
        hp[2 * i + 1] = __half2(h2, h3);
        if (wlo) {
            __half l0 = __float2half(v.x - __half2float(h0));
            __half l1 = __float2half(v.y - __half2float(h1));
            __half l2 = __float2half(v.z - __half2float(h2));
            __half l3 = __float2half(v.w - __half2float(h3));
            __half2* lp = (__half2*)lo;
            lp[2 * i]     = __half2(l0, l1);
            lp[2 * i + 1] = __half2(l2, l3);
        }
    }
}

// up to 3 weight slots per launch; lo plane only for slot == loslot
__global__ void split_w3(const float* __restrict__ w0, const float* __restrict__ w1,
                         const float* __restrict__ w2,
                         __half* __restrict__ whb, __half* __restrict__ wlb,
                         int n4w, int nslots, int loslot)
{
    int i = blockIdx.x * blockDim.x + threadIdx.x;
    const int str = gridDim.x * blockDim.x;
    const int tot = nslots * n4w;
    for (; i < tot; i += str) {
        const int slot = i / n4w;
        const int j = i - slot * n4w;
        const float* in = (slot == 0) ? w0 : (slot == 1) ? w1 : w2;
        float4 v = ((const float4*)in)[j];
        __half h0 = __float2half(v.x), h1 = __float2half(v.y);
        __half h2 = __float2half(v.z), h3 = __float2half(v.w);
        __half2* hp = (__half2*)(whb + (size_t)slot * WSL);
        hp[2 * j]     = __half2(h0, h1);
        hp[2 * j + 1] = __half2(h2, h3);
        if (slot == loslot) {
            __half l0 = __float2half(v.x - __half2float(h0));
            __half l1 = __float2half(v.y - __half2float(h1));
            __half l2 = __float2half(v.z - __half2float(h2));
            __half l3 = __float2half(v.w - __half2float(h3));
            __half2* lp = (__half2*)wlb;
            lp[2 * j]     = __half2(l0, l1);
            lp[2 * j + 1] = __half2(l2, l3);
        }
    }
}

// =====================================================================
// fp16-split tensor-core GEMM (unchanged from R7)
// =====================================================================
#define PAH 0
#define PAL 10240
#define PBH 20480
#define PBL 40960
#define STG 61440
#define GSMEM (3 * STG)   // 184320 bytes

__global__ __launch_bounds__(256, 1) void gemm_mma(
    const __half* __restrict__ Ahp, const __half* __restrict__ Alp,
    const __half* __restrict__ Whp, const __half* __restrict__ Wlp,
    const float* __restrict__ b0p, const float* __restrict__ b1p,
    const float* __restrict__ b2p, const float* __restrict__ b3p,
    float* C0, float* C1, float* C2, float* C3, int sigz)
{
    extern __shared__ char smem[];
    const uint32_t sb = smem_u32(smem);
    const int tid = threadIdx.x, z = blockIdx.z;
    const bool three = (z == sigz);   // gamma: 3-term split + sigmoid

    const __half* Wh = Whp + (size_t)z * WSL;
    const float* bias = (z == 0) ? b0p : (z == 1) ? b1p : (z == 2) ? b2p : b3p;
    float*       C    = (z == 0) ? C0  : (z == 1) ? C1  : (z == 2) ? C2  : C3;

    const int bm = blockIdx.y * 128;
    const int bn = blockIdx.x * 256;
    const size_t aoff = (size_t)bm * KE;
    const size_t boff = (size_t)bn * KE;

    const int crow = tid >> 2, cch = tid & 3;
    const uint32_t soc = (uint32_t)crow * 80 + (uint32_t)cch * 16;
    const size_t   goc = (size_t)crow * KE + (size_t)cch * 8;

    const int lane = tid & 31, wid = tid >> 5;
    const int wm = wid >> 2, wn = wid & 3;
    const int mA = lane >> 3, rA = lane & 7;
    uint32_t offA[4];
#pragma unroll
    for (int mi = 0; mi < 4; mi++)
        offA[mi] = (uint32_t)((wm * 64 + mi * 16 + (mA & 1) * 8 + rA) * 80 + (mA >> 1) * 16);
    uint32_t offB[4];
#pragma unroll
    for (int njp = 0; njp < 4; njp++)
        offB[njp] = (uint32_t)((wn * 64 + njp * 16 + (mA >> 1) * 8 + rA) * 80 + (mA & 1) * 16);

    float acc[4][8][4];
#pragma unroll
    for (int mi = 0; mi < 4; mi++)
#pragma unroll
        for (int nj = 0; nj < 8; nj++)
#pragma unroll
            for (int r = 0; r < 4; r++) acc[mi][nj][r] = 0.f;

    auto load_stage = [&](int p, int kt) {
        const uint32_t s = sb + (uint32_t)p * STG;
#pragma unroll
        for (int u = 0; u < 2; u++) {
            const uint32_t so2 = soc + (uint32_t)u * 64 * 80;
            const size_t   go2 = goc + (size_t)u * 64 * KE + kt;
            cp16(s + PAH + so2, Ahp + aoff + go2);
            cp16(s + PAL + so2, Alp + aoff + go2);
        }
#pragma unroll
        for (int u = 0; u < 4; u++) {
            const uint32_t so2 = soc + (uint32_t)u * 64 * 80;
            const size_t   go2 = goc + (size_t)u * 64 * KE + kt;
            cp16(s + PBH + so2, Wh + boff + go2);
            if (three) cp16(s + PBL + so2, Wlp + boff + go2);
        }
        cp_commit();
    };

    load_stage(0, 0);
    load_stage(1, 32);

    const int NST = KE / 32;  // 128
    for (int i = 0; i < NST; i++) {
        cp_wait<1>();
        __syncthreads();
        if (i + 2 < NST) load_stage((i + 2) % 3, (i + 2) * 32);
        else             cp_commit();

        const uint32_t s = sb + (uint32_t)(i % 3) * STG;
#pragma unroll
        for (int ks = 0; ks < 2; ks++) {
            const uint32_t kb = (uint32_t)ks * 32;
            uint32_t ah[4][4], al[4][4], bh[4][4];
#pragma unroll
            for (int mi = 0; mi < 4; mi++) {
                ldm_x4(ah[mi], s + PAH + offA[mi] + kb);
                ldm_x4(al[mi], s + PAL + offA[mi] + kb);
            }
#pragma unroll
            for (int njp = 0; njp < 4; njp++)
                ldm_x4(bh[njp], s + PBH + offB[njp] + kb);

#pragma unroll
            for (int njp = 0; njp < 4; njp++)
#pragma unroll
                for (int mi = 0; mi < 4; mi++) {
                    mma4(acc[mi][2 * njp],     ah[mi], bh[njp][0], bh[njp][1]);
                    mma4(acc[mi][2 * njp + 1], ah[mi], bh[njp][2], bh[njp][3]);
                }
#pragma unroll
            for (int njp = 0; njp < 4; njp++)
#pragma unroll
                for (int mi = 0; mi < 4; mi++) {
                    mma4(acc[mi][2 * njp],     al[mi], bh[njp][0], bh[njp][1]);
                    mma4(acc[mi][2 * njp + 1], al[mi], bh[njp][2], bh[njp][3]);
                }
            if (three) {
#pragma unroll
                for (int njp = 0; njp < 4; njp++) {
                    uint32_t bl[4];
                    ldm_x4(bl, s + PBL + offB[njp] + kb);
#pragma unroll
                    for (int mi = 0; mi < 4; mi++) {
                        mma4(acc[mi][2 * njp],     ah[mi], bl[0], bl[1]);
                        mma4(acc[mi][2 * njp + 1], ah[mi], bl[2], bl[3]);
                    }
                }
            }
        }
    }

    const int g = lane >> 2, t4 = lane & 3;
#pragma unroll
    for (int mi = 0; mi < 4; mi++) {
#pragma unroll
        for (int nj = 0; nj < 8; nj++) {
            const int row = bm + wm * 64 + mi * 16 + g;
            const int col = bn + wn * 64 + nj * 8 + 2 * t4;
            const float bb0 = bias[col], bb1 = bias[col + 1];
            float v0 = acc[mi][nj][0] + bb0, v1 = acc[mi][nj][1] + bb1;
            float v2 = acc[mi][nj][2] + bb0, v3 = acc[mi][nj][3] + bb1;
            if (three) {
                v0 = 1.f / (1.f + expf(-v0)); v1 = 1.f / (1.f + expf(-v1));
                v2 = 1.f / (1.f + expf(-v2)); v3 = 1.f / (1.f + expf(-v3));
            }
            *(float2*)(C + (size_t)row * NE + col)       = make_float2(v0, v1);
            *(float2*)(C + (size_t)(row + 8) * NE + col) = make_float2(v2, v3);
        }
    }
}

// =====================================================================
// Fused attention v2: 512 threads, float4 LDS, transposed K/Gi,
// warp-aligned causal skip, cp.async V prefetch, fp16 hi/lo epilogue.
// one CTA per (b,h); s=64, d=128.
// =====================================================================
#define ASD  132   // row stride (floats) for row-major tiles (16B aligned)
#define ASDK 68    // row stride (floats) for transposed tiles
// smem float offsets
#define OQ  0                    // sQ   64x132
#define OGC 8448                 // sGc  64x132
#define OKT 16896                // sKT  128x68
#define OGT 25600                // sGiT 128x68
#define OS  34304                // sS   64x64
#define OV  38400                // sV   64x132
#define ASMEM ((38400 + 8448) * 4)   // 187392 bytes

__global__ __launch_bounds__(512, 1) void attn2(
    const float* __restrict__ Q, const float* __restrict__ K,
    const float* __restrict__ V, const float* __restrict__ G,
    const float* __restrict__ t, __half* __restrict__ OH, __half* __restrict__ OL)
{
    extern __shared__ float sm[];
    float* sQ   = sm + OQ;
    float* sGc  = sm + OGC;
    float* sKT  = sm + OKT;
    float* sGiT = sm + OGT;
    float* sS   = sm + OS;
    float* sV   = sm + OV;
    const uint32_t sb = smem_u32(sm);

    const int bh = blockIdx.x;
    const int b  = bh >> 5, h = bh & 31;
    const int tid = threadIdx.x;
    const size_t base = ((size_t)b * 64) * 4096 + (size_t)h * 128;

    // ---- async loads: Q, G (group 1); V (group 2); K via LDG+transposed STS ----
    for (int c = tid; c < 2048; c += 512) {
        const int row = c >> 5, ch = c & 31;
        const uint32_t so = (uint32_t)(row * ASD * 4 + ch * 16);
        const size_t   go = base + (size_t)row * 4096 + ch * 4;
        cp16(sb + OQ * 4 + so,  Q + go);
        cp16(sb + OGC * 4 + so, G + go);
    }
    cp_commit();
    for (int c = tid; c < 2048; c += 512) {
        const int row = c >> 5, ch = c & 31;
        cp16(sb + OV * 4 + (uint32_t)(row * ASD * 4 + ch * 16),
             V + base + (size_t)row * 4096 + ch * 4);
    }
    cp_commit();
    for (int i = tid; i < 8192; i += 512) {
        const int s = i >> 7, d = i & 127;
        sKT[d * ASDK + s] = K[base + (size_t)s * 4096 + d];
    }
    cp_wait<1>();           // Q, G arrived (V may still be in flight)
    __syncthreads();

    // ---- parallel: RoPE (threads 128..511) | cumprod (threads 0..127) ----
    if (tid >= 128) {
        const float LN1E4_64 = 0.14391156531879916f;  // ln(10000)/64
        for (int i = tid - 128; i < 4096; i += 384) {
            const int s = i >> 6, q = i & 63;
            const float invf = expf(-(float)s * LN1E4_64);
            const float ang  = t[q] * invf;
            const float cs = cosf(ang), sn = sinf(ang);
            float a, b2;
            a = sQ[s * ASD + q]; b2 = sQ[s * ASD + q + 64];
            sQ[s * ASD + q]      = a * cs - b2 * sn;
            sQ[s * ASD + q + 64] = b2 * cs + a * sn;
            a = sKT[q * ASDK + s]; b2 = sKT[(q + 64) * ASDK + s];
            sKT[q * ASDK + s]        = a * cs - b2 * sn;
            sKT[(q + 64) * ASDK + s] = b2 * cs + a * sn;
        }
    } else {
        const int d = tid;
        float run = 1.f;
        for (int s = 0; s < 64; s++) {
            run *= sGc[s * ASD + d];
            sGc[s * ASD + d]   = run;
            sGiT[d * ASDK + s] = 1.f / run;
        }
    }
    __syncthreads();

    // ---- score phase: 16 warps = 4x4 macro grid of 16x16 tiles ----
    {
        const int w = tid >> 5, lane = tid & 31;
        const int wq = w >> 2, wk = w & 3;
        const int lq = lane >> 2, lk = lane & 3;
        const int q0 = wq * 16 + lq * 2;
        const int k0 = wk * 16 + lk * 4;
        float acc[2][4] = {{0,0,0,0},{0,0,0,0}};
        float dac[2][4] = {{0,0,0,0},{0,0,0,0}};

        if (wk <= wq) {   // warp-uniform causal skip
#pragma unroll 2
            for (int kk = 0; kk < 128; kk += 4) {
                float qv0[4], qv1[4], gq0[4], gq1[4];
                *(float4*)qv0 = *(const float4*)&sQ[q0 * ASD + kk];
                *(float4*)qv1 = *(const float4*)&sQ[(q0 + 1) * ASD + kk];
                *(float4*)gq0 = *(const float4*)&sGc[q0 * ASD + kk];
                *(float4*)gq1 = *(const float4*)&sGc[(q0 + 1) * ASD + kk];
                float kv[4][4], gi[4][4];
#pragma unroll
                for (int r = 0; r < 4; r++) {
                    *(float4*)kv[r] = *(const float4*)&sKT[(kk + r) * ASDK + k0];
                    *(float4*)gi[r] = *(const float4*)&sGiT[(kk + r) * ASDK + k0];
                }
#pragma unroll
                for (int r = 0; r < 4; r++)
#pragma unroll
                    for (int j = 0; j < 4; j++) {
                        acc[0][j] = fmaf(qv0[r], kv[r][j], acc[0][j]);
                        acc[1][j] = fmaf(qv1[r], kv[r][j], acc[1][j]);
                        dac[0][j] = fmaf(gq0[r], gi[r][j], dac[0][j]);
                        dac[1][j] = fmaf(gq1[r], gi[r][j], dac[1][j]);
                    }
            }
        }
#pragma unroll
        for (int i = 0; i < 2; i++)
#pragma unroll
            for (int j = 0; j < 4; j++) {
                const int qi = q0 + i, kj = k0 + j;
                sS[qi * 64 + kj] =
                    (kj <= qi) ? acc[i][j] * dac[i][j] * (1.0f / 128.0f) : 0.f;
            }
    }
    cp_wait<0>();   // V resident
    __syncthreads();

    // ---- O = S @ V : warp w -> q rows 4w..4w+3; lane -> d = lane*4..+3 ----
    {
        const int w = tid >> 5, lane = tid & 31;
        const int d0 = lane * 4;
#pragma unroll
        for (int qq = 0; qq < 4; qq++) {
            const int q = w * 4 + qq;
            float a0 = 0.f, a1 = 0.f, a2 = 0.f, a3 = 0.f;
            for (int kq = 0; kq <= w; kq++) {   // causal: k <= q (warp-uniform bound)
                float sv[4];
                *(float4*)sv = *(const float4*)&sS[q * 64 + kq * 4];
#pragma unroll
                for (int r = 0; r < 4; r++) {
                    float v[4];
                    *(float4*)v = *(const float4*)&sV[(kq * 4 + r) * ASD + d0];
                    a0 = fmaf(sv[r], v[0], a0);
                    a1 = fmaf(sv[r], v[1], a1);
                    a2 = fmaf(sv[r], v[2], a2);
                    a3 = fmaf(sv[r], v[3], a3);
                }
            }
            // fp16 hi/lo split epilogue (replaces split_a)
            const size_t go = base + (size_t)q * 4096 + d0;
            __half h0 = __float2half(a0), h1 = __float2half(a1);
            __half h2 = __float2half(a2), h3 = __float2half(a3);
            __half l0 = __float2half(a0 - __half2float(h0));
            __half l1 = __float2half(a1 - __half2float(h1));
            __half l2 = __float2half(a2 - __half2float(h2));
            __half l3 = __float2half(a3 - __half2float(h3));
            *(__half2*)(OH + go)     = __half2(h0, h1);
            *(__half2*)(OH + go + 2) = __half2(h2, h3);
            *(__half2*)(OL + go)     = __half2(l0, l1);
            *(__half2*)(OL + go + 2) = __half2(l2, l3);
        }
    }
}

// =====================================================================
// launch: split_x, split_w(2), gemm_qkvg(#4), attn(#5), gemm_o(#6)
// =====================================================================
extern "C" void kernel_launch(void* const* d_in, const int* in_sizes, int n_in,
                              void* d_out, int out_size)
{
    const float* x  = (const float*)d_in[0];
    const float* t  = (const float*)d_in[1];
    const float* Wq = (const float*)d_in[2];
    const float* bq = (const float*)d_in[3];
    const float* Wk = (const float*)d_in[4];
    const float* bk = (const float*)d_in[5];
    const float* Wv = (const float*)d_in[6];
    const float* bv = (const float*)d_in[7];
    const float* Wd = (const float*)d_in[8];
    const float* bd = (const float*)d_in[9];
    const float* Wo = (const float*)d_in[10];
    const float* bo = (const float*)d_in[11];
    float* out = (float*)d_out;

    float *Qb, *Kb, *Vb, *Gb;
    __half *xh, *xl, *ah, *al, *wh, *wl;
    cudaGetSymbolAddress((void**)&Qb, g_Q);
    cudaGetSymbolAddress((void**)&Kb, g_K);
    cudaGetSymbolAddress((void**)&Vb, g_V);
    cudaGetSymbolAddress((void**)&Gb, g_G);
    cudaGetSymbolAddress((void**)&xh, g_xh);
    cudaGetSymbolAddress((void**)&xl, g_xl);
    cudaGetSymbolAddress((void**)&ah, g_ah);
    cudaGetSymbolAddress((void**)&al, g_al);
    cudaGetSymbolAddress((void**)&wh, g_wh);
    cudaGetSymbolAddress((void**)&wl, g_wl);

    const int n4x = MTOT * NE / 4;
    const int n4w = NE * KE / 4;
    // launches 1-3
    split_k<<<2048, 256>>>(x, xh, xl, n4x, 1);
    split_w3<<<8192, 256>>>(Wq, Wk, Wk, wh, (half*)0, n4w, 2, -1);
    split_w3<<<12288, 256>>>(Wv, Wd, Wo, wh + 2 * WSL, wl, n4w, 3, 1);

    cudaFuncSetAttribute(gemm_mma, cudaFuncAttributeMaxDynamicSharedMemorySize, GSMEM);

    // launch 4: fused Q/K/V/gamma projections (z: 0=Q,1=K,2=V,3=gamma)
    gemm_mma<<<dim3(NE / 256, MTOT / 128, 4), 256, GSMEM>>>(
        xh, xl, wh, wl, bq, bk, bv, bd, Qb, Kb, Vb, Gb, /*sigz=*/3);

    // launch 5: fused attention (writes fp16 hi/lo planes directly)
    cudaFuncSetAttribute(attn2, cudaFuncAttributeMaxDynamicSharedMemorySize, ASMEM);
    attn2<<<1024, 512, ASMEM>>>(Qb, Kb, Vb, Gb, t, ah, al);

    // launch 6: output projection (2-term)
    gemm_mma<<<dim3(NE / 256, MTOT / 128, 1), 256, GSMEM>>>(
        ah, al, wh + 4 * WSL, wl, bo, bo, bo, bo, out, out, out, out, /*sigz=*/-1);
}

// round 9
// speedup vs baseline: 3.9385x; 1.0997x over previous
#include <cuda_runtime.h>
#include <cuda_fp16.h>
#include <math.h>
#include <stdint.h>

// Problem constants
#define MTOT 2048   // BATCH*SEQ = 32*64
#define NE   4096   // EMBED_DIM
#define KE   4096
#define WSL  16777216ull   // elements per weight slot (4096*4096)

// ---------------- scratch (allocation-free: __device__ globals) ----------------
__device__ float g_Q[MTOT * NE];
__device__ float g_K[MTOT * NE];
__device__ float g_V[MTOT * NE];
__device__ float g_G[MTOT * NE];

__device__ __half g_xh[MTOT * NE];
__device__ __half g_xl[MTOT * NE];
__device__ __half g_ah[MTOT * NE];
__device__ __half g_al[MTOT * NE];
__device__ __half g_wh[5 * WSL];   // slots: Wq,Wk,Wv,Wd,Wo (hi plane)
__device__ __half g_wl[WSL];       // lo plane, only needed for Wd (gamma)

// =====================================================================
// helpers
// =====================================================================
__device__ __forceinline__ uint32_t smem_u32(const void* p) {
    uint32_t a;
    asm("{ .reg .u64 t; cvta.to.shared.u64 t, %1; cvt.u32.u64 %0, t; }" : "=r"(a) : "l"(p));
    return a;
}
__device__ __forceinline__ void cp16(uint32_t s, const void* g) {
    asm volatile("cp.async.cg.shared.global [%0], [%1], 16;" :: "r"(s), "l"(g));
}
__device__ __forceinline__ void cp_commit() {
    asm volatile("cp.async.commit_group;" ::: "memory");
}
template <int N>
__device__ __forceinline__ void cp_wait() {
    asm volatile("cp.async.wait_group %0;" :: "n"(N) : "memory");
}
__device__ __forceinline__ void ldm_x4(uint32_t* r, uint32_t a) {
    asm volatile("ldmatrix.sync.aligned.m8n8.x4.shared.b16 {%0,%1,%2,%3}, [%4];"
                 : "=r"(r[0]), "=r"(r[1]), "=r"(r[2]), "=r"(r[3]) : "r"(a));
}
__device__ __forceinline__ void mma4(float* c, const uint32_t* a, uint32_t b0, uint32_t b1) {
    asm volatile("mma.sync.aligned.m16n8k16.row.col.f32.f16.f16.f32 "
                 "{%0,%1,%2,%3}, {%4,%5,%6,%7}, {%8,%9}, {%0,%1,%2,%3};"
                 : "+f"(c[0]), "+f"(c[1]), "+f"(c[2]), "+f"(c[3])
                 : "r"(a[0]), "r"(a[1]), "r"(a[2]), "r"(a[3]), "r"(b0), "r"(b1));
}

// =====================================================================
// fp32 -> fp16 hi/lo split
// =====================================================================
__global__ void split_k(const float* __restrict__ in, __half* __restrict__ hi,
                        __half* __restrict__ lo, int n4, int wlo)
{
    int i = blockIdx.x * blockDim.x + threadIdx.x;
    const int str = gridDim.x * blockDim.x;
    for (; i < n4; i += str) {
        float4 v = ((const float4*)in)[i];
        __half h0 = __float2half(v.x), h1 = __float2half(v.y);
        __half h2 = __float2half(v.z), h3 = __float2half(v.w);
        __half2* hp = (__half2*)hi;
        hp[2 * i]     = __half2(h0, h1);
        hp[2 * i + 1] = __half2(h2, h3);
        if (wlo) {
            __half l0 = __float2half(v.x - __half2float(h0));
            __half l1 = __float2half(v.y - __half2float(h1));
            __half l2 = __float2half(v.z - __half2float(h2));
            __half l3 = __float2half(v.w - __half2float(h3));
            __half2* lp = (__half2*)lo;
            lp[2 * i]     = __half2(l0, l1);
            lp[2 * i + 1] = __half2(l2, l3);
        }
    }
}

// up to 3 weight slots per launch; lo plane only for slot == loslot
__global__ void split_w3(const float* __restrict__ w0, const float* __restrict__ w1,
                         const float* __restrict__ w2,
                         __half* __restrict__ whb, __half* __restrict__ wlb,
                         int n4w, int nslots, int loslot)
{
    int i = blockIdx.x * blockDim.x + threadIdx.x;
    const int str = gridDim.x * blockDim.x;
    const int tot = nslots * n4w;
    for (; i < tot; i += str) {
        const int slot = i / n4w;
        const int j = i - slot * n4w;
        const float* in = (slot == 0) ? w0 : (slot == 1) ? w1 : w2;
        float4 v = ((const float4*)in)[j];
        __half h0 = __float2half(v.x), h1 = __float2half(v.y);
        __half h2 = __float2half(v.z), h3 = __float2half(v.w);
        __half2* hp = (__half2*)(whb + (size_t)slot * WSL);
        hp[2 * j]     = __half2(h0, h1);
        hp[2 * j + 1] = __half2(h2, h3);
        if (slot == loslot) {
            __half l0 = __float2half(v.x - __half2float(h0));
            __half l1 = __float2half(v.y - __half2float(h1));
            __half l2 = __float2half(v.z - __half2float(h2));
            __half l3 = __float2half(v.w - __half2float(h3));
            __half2* lp = (__half2*)wlb;
            lp[2 * j]     = __half2(l0, l1);
            lp[2 * j + 1] = __half2(l2, l3);
        }
    }
}

// =====================================================================
// common GEMM geometry
// =====================================================================
#define PAH 0
#define PAL 10240
#define PBH 20480
#define PBL 40960
#define STG 61440
#define GSMEM (3 * STG)   // 184320 bytes

// =====================================================================
// gemm2: 2-term fp16-split GEMM with software-pipelined fragments.
//   C[m,n] = sum_k A[m,k]*W[n,k] + bias[n];  product = ah*bh + al*bh
// CTA tile 128x256, BK=32, 8 warps (2m x 4n), warp tile 64x64, 3 stages.
// =====================================================================
__global__ __launch_bounds__(256, 1) void gemm2(
    const __half* __restrict__ Ahp, const __half* __restrict__ Alp,
    const __half* __restrict__ Whp,
    const float* __restrict__ b0p, const float* __restrict__ b1p,
    const float* __restrict__ b2p,
    float* C0, float* C1, float* C2)
{
    extern __shared__ char smem[];
    const uint32_t sb = smem_u32(smem);
    const int tid = threadIdx.x, z = blockIdx.z;

    const __half* Wh = Whp + (size_t)z * WSL;
    const float* bias = (z == 0) ? b0p : (z == 1) ? b1p : b2p;
    float*       C    = (z == 0) ? C0  : (z == 1) ? C1  : C2;

    const int bm = blockIdx.y * 128;
    const int bn = blockIdx.x * 256;
    const size_t aoff = (size_t)bm * KE;
    const size_t boff = (size_t)bn * KE;

    const int crow = tid >> 2, cch = tid & 3;
    const uint32_t soc = (uint32_t)crow * 80 + (uint32_t)cch * 16;
    const size_t   goc = (size_t)crow * KE + (size_t)cch * 8;

    const int lane = tid & 31, wid = tid >> 5;
    const int wm = wid >> 2, wn = wid & 3;
    const int mA = lane >> 3, rA = lane & 7;
    uint32_t offA[4];
#pragma unroll
    for (int mi = 0; mi < 4; mi++)
        offA[mi] = (uint32_t)((wm * 64 + mi * 16 + (mA & 1) * 8 + rA) * 80 + (mA >> 1) * 16);
    uint32_t offB[4];
#pragma unroll
    for (int njp = 0; njp < 4; njp++)
        offB[njp] = (uint32_t)((wn * 64 + njp * 16 + (mA >> 1) * 8 + rA) * 80 + (mA & 1) * 16);

    float acc[4][8][4];
#pragma unroll
    for (int mi = 0; mi < 4; mi++)
#pragma unroll
        for (int nj = 0; nj < 8; nj++)
#pragma unroll
            for (int r = 0; r < 4; r++) acc[mi][nj][r] = 0.f;

    auto load_stage = [&](int p, int kt) {
        const uint32_t s = sb + (uint32_t)p * STG;
#pragma unroll
        for (int u = 0; u < 2; u++) {
            const uint32_t so2 = soc + (uint32_t)u * 64 * 80;
            const size_t   go2 = goc + (size_t)u * 64 * KE + kt;
            cp16(s + PAH + so2, Ahp + aoff + go2);
            cp16(s + PAL + so2, Alp + aoff + go2);
        }
#pragma unroll
        for (int u = 0; u < 4; u++) {
            const uint32_t so2 = soc + (uint32_t)u * 64 * 80;
            const size_t   go2 = goc + (size_t)u * 64 * KE + kt;
            cp16(s + PBH + so2, Wh + boff + go2);
        }
        cp_commit();
    };

    load_stage(0, 0);
    load_stage(1, 32);

    const int NST = KE / 32;  // 128
    for (int i = 0; i < NST; i++) {
        if (i >= NST - 2) cp_wait<0>();
        else              cp_wait<1>();
        __syncthreads();

        const uint32_t s = sb + (uint32_t)(i % 3) * STG;

        // head fragments (ks=0)
        uint32_t ah0[4][4], bh0[4][4], al[4][4], ah1[4][4], bh1[4][4];
#pragma unroll
        for (int mi = 0; mi < 4; mi++) ldm_x4(ah0[mi], s + PAH + offA[mi]);
#pragma unroll
        for (int njp = 0; njp < 4; njp++) ldm_x4(bh0[njp], s + PBH + offB[njp]);
#pragma unroll
        for (int mi = 0; mi < 4; mi++) ldm_x4(al[mi], s + PAL + offA[mi]);

        // MMA hi(ks=0)
#pragma unroll
        for (int njp = 0; njp < 4; njp++)
#pragma unroll
            for (int mi = 0; mi < 4; mi++) {
                mma4(acc[mi][2 * njp],     ah0[mi], bh0[njp][0], bh0[njp][1]);
                mma4(acc[mi][2 * njp + 1], ah0[mi], bh0[njp][2], bh0[njp][3]);
            }

        // issue next-stage global loads while tensor pipe is busy
        if (i + 2 < NST) load_stage((i + 2) % 3, (i + 2) * 32);

        // prefetch ks=1 hi fragments
#pragma unroll
        for (int mi = 0; mi < 4; mi++) ldm_x4(ah1[mi], s + PAH + offA[mi] + 32);
#pragma unroll
        for (int njp = 0; njp < 4; njp++) ldm_x4(bh1[njp], s + PBH + offB[njp] + 32);

        // MMA lo(ks=0)
#pragma unroll
        for (int njp = 0; njp < 4; njp++)
#pragma unroll
            for (int mi = 0; mi < 4; mi++) {
                mma4(acc[mi][2 * njp],     al[mi], bh0[njp][0], bh0[njp][1]);
                mma4(acc[mi][2 * njp + 1], al[mi], bh0[njp][2], bh0[njp][3]);
            }

        // prefetch ks=1 lo fragments (overwrites al after last use)
#pragma unroll
        for (int mi = 0; mi < 4; mi++) ldm_x4(al[mi], s + PAL + offA[mi] + 32);

        // MMA hi(ks=1)
#pragma unroll
        for (int njp = 0; njp < 4; njp++)
#pragma unroll
            for (int mi = 0; mi < 4; mi++) {
                mma4(acc[mi][2 * njp],     ah1[mi], bh1[njp][0], bh1[njp][1]);
                mma4(acc[mi][2 * njp + 1], ah1[mi], bh1[njp][2], bh1[njp][3]);
            }
        // MMA lo(ks=1)
#pragma unroll
        for (int njp = 0; njp < 4; njp++)
#pragma unroll
            for (int mi = 0; mi < 4; mi++) {
                mma4(acc[mi][2 * njp],     al[mi], bh1[njp][0], bh1[njp][1]);
                mma4(acc[mi][2 * njp + 1], al[mi], bh1[njp][2], bh1[njp][3]);
            }
    }

    // epilogue
    const int g = lane >> 2, t4 = lane & 3;
#pragma unroll
    for (int mi = 0; mi < 4; mi++) {
#pragma unroll
        for (int nj = 0; nj < 8; nj++) {
            const int row = bm + wm * 64 + mi * 16 + g;
            const int col = bn + wn * 64 + nj * 8 + 2 * t4;
            const float bb0 = bias[col], bb1 = bias[col + 1];
            *(float2*)(C + (size_t)row * NE + col) =
                make_float2(acc[mi][nj][0] + bb0, acc[mi][nj][1] + bb1);
            *(float2*)(C + (size_t)(row + 8) * NE + col) =
                make_float2(acc[mi][nj][2] + bb0, acc[mi][nj][3] + bb1);
        }
    }
}

// =====================================================================
// gemm3: gamma projection — 3-term split (ah*bh + al*bh + ah*bl) + sigmoid
// =====================================================================
__global__ __launch_bounds__(256, 1) void gemm3(
    const __half* __restrict__ Ahp, const __half* __restrict__ Alp,
    const __half* __restrict__ Wh, const __half* __restrict__ Wl,
    const float* __restrict__ bias, float* __restrict__ C)
{
    extern __shared__ char smem[];
    const uint32_t sb = smem_u32(smem);
    const int tid = threadIdx.x;

    const int bm = blockIdx.y * 128;
    const int bn = blockIdx.x * 256;
    const size_t aoff = (size_t)bm * KE;
    const size_t boff = (size_t)bn * KE;

    const int crow = tid >> 2, cch = tid & 3;
    const uint32_t soc = (uint32_t)crow * 80 + (uint32_t)cch * 16;
    const size_t   goc = (size_t)crow * KE + (size_t)cch * 8;

    const int lane = tid & 31, wid = tid >> 5;
    const int wm = wid >> 2, wn = wid & 3;
    const int mA = lane >> 3, rA = lane & 7;
    uint32_t offA[4];
#pragma unroll
    for (int mi = 0; mi < 4; mi++)
        offA[mi] = (uint32_t)((wm * 64 + mi * 16 + (mA & 1) * 8 + rA) * 80 + (mA >> 1) * 16);
    uint32_t offB[4];
#pragma unroll
    for (int njp = 0; njp < 4; njp++)
        offB[njp] = (uint32_t)((wn * 64 + njp * 16 + (mA >> 1) * 8 + rA) * 80 + (mA & 1) * 16);

    float acc[4][8][4];
#pragma unroll
    for (int mi = 0; mi < 4; mi++)
#pragma unroll
        for (int nj = 0; nj < 8; nj++)
#pragma unroll
            for (int r = 0; r < 4; r++) acc[mi][nj][r] = 0.f;

    auto load_stage = [&](int p, int kt) {
        const uint32_t s = sb + (uint32_t)p * STG;
#pragma unroll
        for (int u = 0; u < 2; u++) {
            const uint32_t so2 = soc + (uint32_t)u * 64 * 80;
            const size_t   go2 = goc + (size_t)u * 64 * KE + kt;
            cp16(s + PAH + so2, Ahp + aoff + go2);
            cp16(s + PAL + so2, Alp + aoff + go2);
        }
#pragma unroll
        for (int u = 0; u < 4; u++) {
            const uint32_t so2 = soc + (uint32_t)u * 64 * 80;
            const size_t   go2 = goc + (size_t)u * 64 * KE + kt;
            cp16(s + PBH + so2, Wh + boff + go2);
            cp16(s + PBL + so2, Wl + boff + go2);
        }
        cp_commit();
    };

    load_stage(0, 0);
    load_stage(1, 32);

    const int NST = KE / 32;
    for (int i = 0; i < NST; i++) {
        if (i >= NST - 2) cp_wait<0>();
        else              cp_wait<1>();
        __syncthreads();

        const uint32_t s = sb + (uint32_t)(i % 3) * STG;
#pragma unroll
        for (int ks = 0; ks < 2; ks++) {
            const uint32_t kb = (uint32_t)ks * 32;
            uint32_t ah[4][4], al[4][4], bh[4][4];
#pragma unroll
            for (int mi = 0; mi < 4; mi++) {
                ldm_x4(ah[mi], s + PAH + offA[mi] + kb);
                ldm_x4(al[mi], s + PAL + offA[mi] + kb);
            }
#pragma unroll
            for (int njp = 0; njp < 4; njp++)
                ldm_x4(bh[njp], s + PBH + offB[njp] + kb);

#pragma unroll
            for (int njp = 0; njp < 4; njp++)
#pragma unroll
                for (int mi = 0; mi < 4; mi++) {
                    mma4(acc[mi][2 * njp],     ah[mi], bh[njp][0], bh[njp][1]);
                    mma4(acc[mi][2 * njp + 1], ah[mi], bh[njp][2], bh[njp][3]);
                }
            if (ks == 0 && i + 2 < NST) load_stage((i + 2) % 3, (i + 2) * 32);
#pragma unroll
            for (int njp = 0; njp < 4; njp++)
#pragma unroll
                for (int mi = 0; mi < 4; mi++) {
                    mma4(acc[mi][2 * njp],     al[mi], bh[njp][0], bh[njp][1]);
                    mma4(acc[mi][2 * njp + 1], al[mi], bh[njp][2], bh[njp][3]);
                }
#pragma unroll
            for (int njp = 0; njp < 4; njp++) {
                uint32_t bl[4];
                ldm_x4(bl, s + PBL + offB[njp] + kb);
#pragma unroll
                for (int mi = 0; mi < 4; mi++) {
                    mma4(acc[mi][2 * njp],     ah[mi], bl[0], bl[1]);
                    mma4(acc[mi][2 * njp + 1], ah[mi], bl[2], bl[3]);
                }
            }
        }
    }

    const int g = lane >> 2, t4 = lane & 3;
#pragma unroll
    for (int mi = 0; mi < 4; mi++) {
#pragma unroll
        for (int nj = 0; nj < 8; nj++) {
            const int row = bm + wm * 64 + mi * 16 + g;
            const int col = bn + wn * 64 + nj * 8 + 2 * t4;
            const float bb0 = bias[col], bb1 = bias[col + 1];
            float v0 = acc[mi][nj][0] + bb0, v1 = acc[mi][nj][1] + bb1;
            float v2 = acc[mi][nj][2] + bb0, v3 = acc[mi][nj][3] + bb1;
            v0 = 1.f / (1.f + expf(-v0)); v1 = 1.f / (1.f + expf(-v1));
            v2 = 1.f / (1.f + expf(-v2)); v3 = 1.f / (1.f + expf(-v3));
            *(float2*)(C + (size_t)row * NE + col)       = make_float2(v0, v1);
            *(float2*)(C + (size_t)(row + 8) * NE + col) = make_float2(v2, v3);
        }
    }
}

// =====================================================================
// Fused attention v2 (unchanged from R8, verified)
// =====================================================================
#define ASD  132
#define ASDK 68
#define OQ  0
#define OGC 8448
#define OKT 16896
#define OGT 25600
#define OS  34304
#define OV  38400
#define ASMEM ((38400 + 8448) * 4)   // 187392 bytes

__global__ __launch_bounds__(512, 1) void attn2(
    const float* __restrict__ Q, const float* __restrict__ K,
    const float* __restrict__ V, const float* __restrict__ G,
    const float* __restrict__ t, __half* __restrict__ OH, __half* __restrict__ OL)
{
    extern __shared__ float sm[];
    float* sQ   = sm + OQ;
    float* sGc  = sm + OGC;
    float* sKT  = sm + OKT;
    float* sGiT = sm + OGT;
    float* sS   = sm + OS;
    float* sV   = sm + OV;
    const uint32_t sb = smem_u32(sm);

    const int bh = blockIdx.x;
    const int b  = bh >> 5, h = bh & 31;
    const int tid = threadIdx.x;
    const size_t base = ((size_t)b * 64) * 4096 + (size_t)h * 128;

    for (int c = tid; c < 2048; c += 512) {
        const int row = c >> 5, ch = c & 31;
        const uint32_t so = (uint32_t)(row * ASD * 4 + ch * 16);
        const size_t   go = base + (size_t)row * 4096 + ch * 4;
        cp16(sb + OQ * 4 + so,  Q + go);
        cp16(sb + OGC * 4 + so, G + go);
    }
    cp_commit();
    for (int c = tid; c < 2048; c += 512) {
        const int row = c >> 5, ch = c & 31;
        cp16(sb + OV * 4 + (uint32_t)(row * ASD * 4 + ch * 16),
             V + base + (size_t)row * 4096 + ch * 4);
    }
    cp_commit();
    for (int i = tid; i < 8192; i += 512) {
        const int s = i >> 7, d = i & 127;
        sKT[d * ASDK + s] = K[base + (size_t)s * 4096 + d];
    }
    cp_wait<1>();
    __syncthreads();

    if (tid >= 128) {
        const float LN1E4_64 = 0.14391156531879916f;
        for (int i = tid - 128; i < 4096; i += 384) {
            const int s = i >> 6, q = i & 63;
            const float invf = expf(-(float)s * LN1E4_64);
            const float ang  = t[q] * invf;
            const float cs = cosf(ang), sn = sinf(ang);
            float a, b2;
            a = sQ[s * ASD + q]; b2 = sQ[s * ASD + q + 64];
            sQ[s * ASD + q]      = a * cs - b2 * sn;
            sQ[s * ASD + q + 64] = b2 * cs + a * sn;
            a = sKT[q * ASDK + s]; b2 = sKT[(q + 64) * ASDK + s];
            sKT[q * ASDK + s]        = a * cs - b2 * sn;
            sKT[(q + 64) * ASDK + s] = b2 * cs + a * sn;
        }
    } else {
        const int d = tid;
        float run = 1.f;
        for (int s = 0; s < 64; s++) {
            run *= sGc[s * ASD + d];
            sGc[s * ASD + d]   = run;
            sGiT[d * ASDK + s] = 1.f / run;
        }
    }
    __syncthreads();

    {
        const int w = tid >> 5, lane = tid & 31;
        const int wq = w >> 2, wk = w & 3;
        const int lq = lane >> 2, lk = lane & 3;
        const int q0 = wq * 16 + lq * 2;
        const int k0 = wk * 16 + lk * 4;
        float acc[2][4] = {{0,0,0,0},{0,0,0,0}};
        float dac[2][4] = {{0,0,0,0},{0,0,0,0}};

        if (wk <= wq) {
#pragma unroll 2
            for (int kk = 0; kk < 128; kk += 4) {
                float qv0[4], qv1[4], gq0[4], gq1[4];
                *(float4*)qv0 = *(const float4*)&sQ[q0 * ASD + kk];
                *(float4*)qv1 = *(const float4*)&sQ[(q0 + 1) * ASD + kk];
                *(float4*)gq0 = *(const float4*)&sGc[q0 * ASD + kk];
                *(float4*)gq1 = *(const float4*)&sGc[(q0 + 1) * ASD + kk];
                float kv[4][4], gi[4][4];
#pragma unroll
                for (int r = 0; r < 4; r++) {
                    *(float4*)kv[r] = *(const float4*)&sKT[(kk + r) * ASDK + k0];
                    *(float4*)gi[r] = *(const float4*)&sGiT[(kk + r) * ASDK + k0];
                }
#pragma unroll
                for (int r = 0; r < 4; r++)
#pragma unroll
                    for (int j = 0; j < 4; j++) {
                        acc[0][j] = fmaf(qv0[r], kv[r][j], acc[0][j]);
                        acc[1][j] = fmaf(qv1[r], kv[r][j], acc[1][j]);
                        dac[0][j] = fmaf(gq0[r], gi[r][j], dac[0][j]);
                        dac[1][j] = fmaf(gq1[r], gi[r][j], dac[1][j]);
                    }
            }
        }
#pragma unroll
        for (int i = 0; i < 2; i++)
#pragma unroll
            for (int j = 0; j < 4; j++) {
                const int qi = q0 + i, kj = k0 + j;
                sS[qi * 64 + kj] =
                    (kj <= qi) ? acc[i][j] * dac[i][j] * (1.0f / 128.0f) : 0.f;
            }
    }
    cp_wait<0>();
    __syncthreads();

    {
        const int w = tid >> 5, lane = tid & 31;
        const int d0 = lane * 4;
#pragma unroll
        for (int qq = 0; qq < 4; qq++) {
            const int q = w * 4 + qq;
            float a0 = 0.f, a1 = 0.f, a2 = 0.f, a3 = 0.f;
            for (int kq = 0; kq <= w; kq++) {
                float sv[4];
                *(float4*)sv = *(const float4*)&sS[q * 64 + kq * 4];
#pragma unroll
                for (int r = 0; r < 4; r++) {
                    float v[4];
                    *(float4*)v = *(const float4*)&sV[(kq * 4 + r) * ASD + d0];
                    a0 = fmaf(sv[r], v[0], a0);
                    a1 = fmaf(sv[r], v[1], a1);
                    a2 = fmaf(sv[r], v[2], a2);
                    a3 = fmaf(sv[r], v[3], a3);
                }
            }
            const size_t go = base + (size_t)q * 4096 + d0;
            __half h0 = __float2half(a0), h1 = __float2half(a1);
            __half h2 = __float2half(a2), h3 = __float2half(a3);
            __half l0 = __float2half(a0 - __half2float(h0));
            __half l1 = __float2half(a1 - __half2float(h1));
            __half l2 = __float2half(a2 - __half2float(h2));
            __half l3 = __float2half(a3 - __half2float(h3));
            *(__half2*)(OH + go)     = __half2(h0, h1);
            *(__half2*)(OH + go + 2) = __half2(h2, h3);
            *(__half2*)(OL + go)     = __half2(l0, l1);
            *(__half2*)(OL + go + 2) = __half2(l2, l3);
        }
    }
}

// =====================================================================
// launch
// =====================================================================
extern "C" void kernel_launch(void* const* d_in, const int* in_sizes, int n_in,
                              void* d_out, int out_size)
{
    const float* x  = (const float*)d_in[0];
    const float* t  = (const float*)d_in[1];
    const float* Wq = (const float*)d_in[2];
    const float* bq = (const float*)d_in[3];
    const float* Wk = (const float*)d_in[4];
    const float* bk = (const float*)d_in[5];
    const float* Wv = (const float*)d_in[6];
    const float* bv = (const float*)d_in[7];
    const float* Wd = (const float*)d_in[8];
    const float* bd = (const float*)d_in[9];
    const float* Wo = (const float*)d_in[10];
    const float* bo = (const float*)d_in[11];
    float* out = (float*)d_out;

    float *Qb, *Kb, *Vb, *Gb;
    __half *xh, *xl, *ah, *al, *wh, *wl;
    cudaGetSymbolAddress((void**)&Qb, g_Q);
    cudaGetSymbolAddress((void**)&Kb, g_K);
    cudaGetSymbolAddress((void**)&Vb, g_V);
    cudaGetSymbolAddress((void**)&Gb, g_G);
    cudaGetSymbolAddress((void**)&xh, g_xh);
    cudaGetSymbolAddress((void**)&xl, g_xl);
    cudaGetSymbolAddress((void**)&ah, g_ah);
    cudaGetSymbolAddress((void**)&al, g_al);
    cudaGetSymbolAddress((void**)&wh, g_wh);
    cudaGetSymbolAddress((void**)&wl, g_wl);

    const int n4x = MTOT * NE / 4;
    const int n4w = NE * KE / 4;
    split_k<<<2048, 256>>>(x, xh, xl, n4x, 1);
    split_w3<<<12288, 256>>>(Wq, Wk, Wv, wh, (half*)0, n4w, 3, -1);
    split_w3<<<8192, 256>>>(Wd, Wo, Wo, wh + 3 * WSL, wl, n4w, 2, 0);

    cudaFuncSetAttribute(gemm2, cudaFuncAttributeMaxDynamicSharedMemorySize, GSMEM);
    cudaFuncSetAttribute(gemm3, cudaFuncAttributeMaxDynamicSharedMemorySize, GSMEM);

    // Q/K/V projections (2-term, pipelined)
    gemm2<<<dim3(NE / 256, MTOT / 128, 3), 256, GSMEM>>>(
        xh, xl, wh, bq, bk, bv, Qb, Kb, Vb);

    // gamma projection (3-term + sigmoid)
    gemm3<<<dim3(NE / 256, MTOT / 128, 1), 256, GSMEM>>>(
        xh, xl, wh + 3 * WSL, wl, bd, Gb);

    // fused attention (writes fp16 hi/lo planes directly)
    cudaFuncSetAttribute(attn2, cudaFuncAttributeMaxDynamicSharedMemorySize, ASMEM);
    attn2<<<1024, 512, ASMEM>>>(Qb, Kb, Vb, Gb, t, ah, al);

    // output projection (2-term, pipelined)
    gemm2<<<dim3(NE / 256, MTOT / 128, 1), 256, GSMEM>>>(
        ah, al, wh + 4 * WSL, bo, bo, bo, out, out, out);
}

// round 10
// speedup vs baseline: 4.7522x; 1.2066x over previous
#include <cuda_runtime.h>
#include <cuda_fp16.h>
#include <math.h>
#include <stdint.h>

// Problem constants
#define MTOT 2048   // BATCH*SEQ = 32*64
#define NE   4096   // EMBED_DIM
#define KE   4096
#define WSL  16777216ull   // elements per weight slot (4096*4096)

// ---------------- scratch (allocation-free: __device__ globals) ----------------
__device__ float g_Q[MTOT * NE];
__device__ float g_K[MTOT * NE];
__device__ float g_V[MTOT * NE];
__device__ float g_G[MTOT * NE];

__device__ __half g_xh[MTOT * NE];
__device__ __half g_xl[MTOT * NE];
__device__ __half g_ah[MTOT * NE];
__device__ __half g_al[MTOT * NE];
__device__ __half g_wh[5 * WSL];   // slots: Wq,Wk,Wv,Wd,Wo (hi plane)
__device__ __half g_wl[WSL];       // lo plane, only needed for Wd (gamma)

// =====================================================================
// helpers
// =====================================================================
__device__ __forceinline__ uint32_t smem_u32(const void* p) {
    uint32_t a;
    asm("{ .reg .u64 t; cvta.to.shared.u64 t, %1; cvt.u32.u64 %0, t; }" : "=r"(a) : "l"(p));
    return a;
}
__device__ __forceinline__ void cp16(uint32_t s, const void* g) {
    asm volatile("cp.async.cg.shared.global [%0], [%1], 16;" :: "r"(s), "l"(g));
}
__device__ __forceinline__ void cp_commit() {
    asm volatile("cp.async.commit_group;" ::: "memory");
}
template <int N>
__device__ __forceinline__ void cp_wait() {
    asm volatile("cp.async.wait_group %0;" :: "n"(N) : "memory");
}
__device__ __forceinline__ void ldm_x4(uint32_t* r, uint32_t a) {
    asm volatile("ldmatrix.sync.aligned.m8n8.x4.shared.b16 {%0,%1,%2,%3}, [%4];"
                 : "=r"(r[0]), "=r"(r[1]), "=r"(r[2]), "=r"(r[3]) : "r"(a));
}
__device__ __forceinline__ void mma4(float* c, const uint32_t* a, uint32_t b0, uint32_t b1) {
    asm volatile("mma.sync.aligned.m16n8k16.row.col.f32.f16.f16.f32 "
                 "{%0,%1,%2,%3}, {%4,%5,%6,%7}, {%8,%9}, {%0,%1,%2,%3};"
                 : "+f"(c[0]), "+f"(c[1]), "+f"(c[2]), "+f"(c[3])
                 : "r"(a[0]), "r"(a[1]), "r"(a[2]), "r"(a[3]), "r"(b0), "r"(b1));
}

// =====================================================================
// fp32 -> fp16 hi/lo split
// =====================================================================
__global__ void split_k(const float* __restrict__ in, __half* __restrict__ hi,
                        __half* __restrict__ lo, int n4, int wlo)
{
    int i = blockIdx.x * blockDim.x + threadIdx.x;
    const int str = gridDim.x * blockDim.x;
    for (; i < n4; i += str) {
        float4 v = ((const float4*)in)[i];
        __half h0 = __float2half(v.x), h1 = __float2half(v.y);
        __half h2 = __float2half(v.z), h3 = __float2half(v.w);
        __half2* hp = (__half2*)hi;
        hp[2 * i]     = __half2(h0, h1);
        hp[2 * i + 1] = __half2(h2, h3);
        if (wlo) {
            __half l0 = __float2half(v.x - __half2float(h0));
            __half l1 = __float2half(v.y - __half2float(h1));
            __half l2 = __float2half(v.z - __half2float(h2));
            __half l3 = __float2half(v.w - __half2float(h3));
            __half2* lp = (__half2*)lo;
            lp[2 * i]     = __half2(l0, l1);
            lp[2 * i + 1] = __half2(l2, l3);
        }
    }
}

// up to 3 weight slots per launch; lo plane only for slot == loslot
__global__ void split_w3(const float* __restrict__ w0, const float* __restrict__ w1,
                         const float* __restrict__ w2,
                         __half* __restrict__ whb, __half* __restrict__ wlb,
                         int n4w, int nslots, int loslot)
{
    int i = blockIdx.x * blockDim.x + threadIdx.x;
    const int str = gridDim.x * blockDim.x;
    const int tot = nslots * n4w;
    for (; i < tot; i += str) {
        const int slot = i / n4w;
        const int j = i - slot * n4w;
        const float* in = (slot == 0) ? w0 : (slot == 1) ? w1 : w2;
        float4 v = ((const float4*)in)[j];
        __half h0 = __float2half(v.x), h1 = __float2half(v.y);
        __half h2 = __float2half(v.z), h3 = __float2half(v.w);
        __half2* hp = (__half2*)(whb + (size_t)slot * WSL);
        hp[2 * j]     = __half2(h0, h1);
        hp[2 * j + 1] = __half2(h2, h3);
        if (slot == loslot) {
            __half l0 = __float2half(v.x - __half2float(h0));
            __half l1 = __float2half(v.y - __half2float(h1));
            __half l2 = __float2half(v.z - __half2float(h2));
            __half l3 = __float2half(v.w - __half2float(h3));
            __half2* lp = (__half2*)wlb;
            lp[2 * j]     = __half2(l0, l1);
            lp[2 * j + 1] = __half2(l2, l3);
        }
    }
}

// =====================================================================
// common GEMM geometry
// =====================================================================
#define PAH 0
#define PAL 10240
#define PBH 20480
#define PBL 40960
#define STG 61440
#define GSMEM (3 * STG)   // 184320 bytes

// =====================================================================
// gemm_f: fused projection GEMM.
//   z != sigz: 1.5-term split (ah*bh always; al*bh on even k-stages only)
//   z == sigz: gamma — 3-term (ah*bh + al*bh + ah*bl) + sigmoid epilogue
// CTA tile 128x256, BK=32, 8 warps (2m x 4n), warp tile 64x64, 3 stages.
// =====================================================================
__global__ __launch_bounds__(256, 1) void gemm_f(
    const __half* __restrict__ Ahp, const __half* __restrict__ Alp,
    const __half* __restrict__ Whp, const __half* __restrict__ Wlp,
    const float* __restrict__ b0p, const float* __restrict__ b1p,
    const float* __restrict__ b2p, const float* __restrict__ b3p,
    float* C0, float* C1, float* C2, float* C3, int sigz)
{
    extern __shared__ char smem[];
    const uint32_t sb = smem_u32(smem);
    const int tid = threadIdx.x, z = blockIdx.z;
    const bool three = (z == sigz);

    const __half* Wh = Whp + (size_t)z * WSL;
    const float* bias = (z == 0) ? b0p : (z == 1) ? b1p : (z == 2) ? b2p : b3p;
    float*       C    = (z == 0) ? C0  : (z == 1) ? C1  : (z == 2) ? C2  : C3;

    const int bm = blockIdx.y * 128;
    const int bn = blockIdx.x * 256;
    const size_t aoff = (size_t)bm * KE;
    const size_t boff = (size_t)bn * KE;

    const int crow = tid >> 2, cch = tid & 3;
    const uint32_t soc = (uint32_t)crow * 80 + (uint32_t)cch * 16;
    const size_t   goc = (size_t)crow * KE + (size_t)cch * 8;

    const int lane = tid & 31, wid = tid >> 5;
    const int wm = wid >> 2, wn = wid & 3;
    const int mA = lane >> 3, rA = lane & 7;
    uint32_t offA[4];
#pragma unroll
    for (int mi = 0; mi < 4; mi++)
        offA[mi] = (uint32_t)((wm * 64 + mi * 16 + (mA & 1) * 8 + rA) * 80 + (mA >> 1) * 16);
    uint32_t offB[4];
#pragma unroll
    for (int njp = 0; njp < 4; njp++)
        offB[njp] = (uint32_t)((wn * 64 + njp * 16 + (mA >> 1) * 8 + rA) * 80 + (mA & 1) * 16);

    float acc[4][8][4];
#pragma unroll
    for (int mi = 0; mi < 4; mi++)
#pragma unroll
        for (int nj = 0; nj < 8; nj++)
#pragma unroll
            for (int r = 0; r < 4; r++) acc[mi][nj][r] = 0.f;

    const int NST = KE / 32;  // 128

    if (!three) {
        // ---------- 1.5-term path ----------
        auto load2 = [&](int p, int kt, bool dolo) {
            const uint32_t s = sb + (uint32_t)p * STG;
#pragma unroll
            for (int u = 0; u < 2; u++) {
                const uint32_t so2 = soc + (uint32_t)u * 64 * 80;
                const size_t   go2 = goc + (size_t)u * 64 * KE + kt;
                cp16(s + PAH + so2, Ahp + aoff + go2);
                if (dolo) cp16(s + PAL + so2, Alp + aoff + go2);
            }
#pragma unroll
            for (int u = 0; u < 4; u++) {
                const uint32_t so2 = soc + (uint32_t)u * 64 * 80;
                const size_t   go2 = goc + (size_t)u * 64 * KE + kt;
                cp16(s + PBH + so2, Wh + boff + go2);
            }
            cp_commit();
        };

        load2(0, 0, true);
        load2(1, 32, false);

        for (int i = 0; i < NST; i++) {
            if (i >= NST - 2) cp_wait<0>();
            else              cp_wait<1>();
            __syncthreads();

            const uint32_t s = sb + (uint32_t)(i % 3) * STG;
            const bool dolo = ((i & 1) == 0);

            uint32_t ah0[4][4], bh0[4][4], al[4][4], ah1[4][4], bh1[4][4];
#pragma unroll
            for (int mi = 0; mi < 4; mi++) ldm_x4(ah0[mi], s + PAH + offA[mi]);
#pragma unroll
            for (int njp = 0; njp < 4; njp++) ldm_x4(bh0[njp], s + PBH + offB[njp]);
            if (dolo) {
#pragma unroll
                for (int mi = 0; mi < 4; mi++) ldm_x4(al[mi], s + PAL + offA[mi]);
            }

            // MMA hi(ks=0)
#pragma unroll
            for (int njp = 0; njp < 4; njp++)
#pragma unroll
                for (int mi = 0; mi < 4; mi++) {
                    mma4(acc[mi][2 * njp],     ah0[mi], bh0[njp][0], bh0[njp][1]);
                    mma4(acc[mi][2 * njp + 1], ah0[mi], bh0[njp][2], bh0[njp][3]);
                }

            if (i + 2 < NST) load2((i + 2) % 3, (i + 2) * 32, (((i + 2) & 1) == 0));

#pragma unroll
            for (int mi = 0; mi < 4; mi++) ldm_x4(ah1[mi], s + PAH + offA[mi] + 32);
#pragma unroll
            for (int njp = 0; njp < 4; njp++) ldm_x4(bh1[njp], s + PBH + offB[njp] + 32);

            if (dolo) {
                // MMA lo(ks=0)
#pragma unroll
                for (int njp = 0; njp < 4; njp++)
#pragma unroll
                    for (int mi = 0; mi < 4; mi++) {
                        mma4(acc[mi][2 * njp],     al[mi], bh0[njp][0], bh0[njp][1]);
                        mma4(acc[mi][2 * njp + 1], al[mi], bh0[njp][2], bh0[njp][3]);
                    }
#pragma unroll
                for (int mi = 0; mi < 4; mi++) ldm_x4(al[mi], s + PAL + offA[mi] + 32);
            }

            // MMA hi(ks=1)
#pragma unroll
            for (int njp = 0; njp < 4; njp++)
#pragma unroll
                for (int mi = 0; mi < 4; mi++) {
                    mma4(acc[mi][2 * njp],     ah1[mi], bh1[njp][0], bh1[njp][1]);
                    mma4(acc[mi][2 * njp + 1], ah1[mi], bh1[njp][2], bh1[njp][3]);
                }
            if (dolo) {
                // MMA lo(ks=1)
#pragma unroll
                for (int njp = 0; njp < 4; njp++)
#pragma unroll
                    for (int mi = 0; mi < 4; mi++) {
                        mma4(acc[mi][2 * njp],     al[mi], bh1[njp][0], bh1[njp][1]);
                        mma4(acc[mi][2 * njp + 1], al[mi], bh1[njp][2], bh1[njp][3]);
                    }
            }
        }
    } else {
        // ---------- gamma: 3-term + sigmoid ----------
        auto load3 = [&](int p, int kt) {
            const uint32_t s = sb + (uint32_t)p * STG;
#pragma unroll
            for (int u = 0; u < 2; u++) {
                const uint32_t so2 = soc + (uint32_t)u * 64 * 80;
                const size_t   go2 = goc + (size_t)u * 64 * KE + kt;
                cp16(s + PAH + so2, Ahp + aoff + go2);
                cp16(s + PAL + so2, Alp + aoff + go2);
            }
#pragma unroll
            for (int u = 0; u < 4; u++) {
                const uint32_t so2 = soc + (uint32_t)u * 64 * 80;
                const size_t   go2 = goc + (size_t)u * 64 * KE + kt;
                cp16(s + PBH + so2, Wh + boff + go2);
                cp16(s + PBL + so2, Wlp + boff + go2);
            }
            cp_commit();
        };

        load3(0, 0);
        load3(1, 32);

        for (int i = 0; i < NST; i++) {
            if (i >= NST - 2) cp_wait<0>();
            else              cp_wait<1>();
            __syncthreads();

            const uint32_t s = sb + (uint32_t)(i % 3) * STG;
#pragma unroll
            for (int ks = 0; ks < 2; ks++) {
                const uint32_t kb = (uint32_t)ks * 32;
                uint32_t ah[4][4], al[4][4], bh[4][4];
#pragma unroll
                for (int mi = 0; mi < 4; mi++) {
                    ldm_x4(ah[mi], s + PAH + offA[mi] + kb);
                    ldm_x4(al[mi], s + PAL + offA[mi] + kb);
                }
#pragma unroll
                for (int njp = 0; njp < 4; njp++)
                    ldm_x4(bh[njp], s + PBH + offB[njp] + kb);

#pragma unroll
                for (int njp = 0; njp < 4; njp++)
#pragma unroll
                    for (int mi = 0; mi < 4; mi++) {
                        mma4(acc[mi][2 * njp],     ah[mi], bh[njp][0], bh[njp][1]);
                        mma4(acc[mi][2 * njp + 1], ah[mi], bh[njp][2], bh[njp][3]);
                    }
                if (ks == 0 && i + 2 < NST) load3((i + 2) % 3, (i + 2) * 32);
#pragma unroll
                for (int njp = 0; njp < 4; njp++)
#pragma unroll
                    for (int mi = 0; mi < 4; mi++) {
                        mma4(acc[mi][2 * njp],     al[mi], bh[njp][0], bh[njp][1]);
                        mma4(acc[mi][2 * njp + 1], al[mi], bh[njp][2], bh[njp][3]);
                    }
#pragma unroll
                for (int njp = 0; njp < 4; njp++) {
                    uint32_t bl[4];
                    ldm_x4(bl, s + PBL + offB[njp] + kb);
#pragma unroll
                    for (int mi = 0; mi < 4; mi++) {
                        mma4(acc[mi][2 * njp],     ah[mi], bl[0], bl[1]);
                        mma4(acc[mi][2 * njp + 1], ah[mi], bl[2], bl[3]);
                    }
                }
            }
        }
    }

    // epilogue (sigmoid if gamma)
    const int g = lane >> 2, t4 = lane & 3;
#pragma unroll
    for (int mi = 0; mi < 4; mi++) {
#pragma unroll
        for (int nj = 0; nj < 8; nj++) {
            const int row = bm + wm * 64 + mi * 16 + g;
            const int col = bn + wn * 64 + nj * 8 + 2 * t4;
            const float bb0 = bias[col], bb1 = bias[col + 1];
            float v0 = acc[mi][nj][0] + bb0, v1 = acc[mi][nj][1] + bb1;
            float v2 = acc[mi][nj][2] + bb0, v3 = acc[mi][nj][3] + bb1;
            if (three) {
                v0 = 1.f / (1.f + expf(-v0)); v1 = 1.f / (1.f + expf(-v1));
                v2 = 1.f / (1.f + expf(-v2)); v3 = 1.f / (1.f + expf(-v3));
            }
            *(float2*)(C + (size_t)row * NE + col)       = make_float2(v0, v1);
            *(float2*)(C + (size_t)(row + 8) * NE + col) = make_float2(v2, v3);
        }
    }
}

// =====================================================================
// Fused attention v2 (unchanged, verified)
// =====================================================================
#define ASD  132
#define ASDK 68
#define OQ  0
#define OGC 8448
#define OKT 16896
#define OGT 25600
#define OS  34304
#define OV  38400
#define ASMEM ((38400 + 8448) * 4)   // 187392 bytes

__global__ __launch_bounds__(512, 1) void attn2(
    const float* __restrict__ Q, const float* __restrict__ K,
    const float* __restrict__ V, const float* __restrict__ G,
    const float* __restrict__ t, __half* __restrict__ OH, __half* __restrict__ OL)
{
    extern __shared__ float sm[];
    float* sQ   = sm + OQ;
    float* sGc  = sm + OGC;
    float* sKT  = sm + OKT;
    float* sGiT = sm + OGT;
    float* sS   = sm + OS;
    float* sV   = sm + OV;
    const uint32_t sb = smem_u32(sm);

    const int bh = blockIdx.x;
    const int b  = bh >> 5, h = bh & 31;
    const int tid = threadIdx.x;
    const size_t base = ((size_t)b * 64) * 4096 + (size_t)h * 128;

    for (int c = tid; c < 2048; c += 512) {
        const int row = c >> 5, ch = c & 31;
        const uint32_t so = (uint32_t)(row * ASD * 4 + ch * 16);
        const size_t   go = base + (size_t)row * 4096 + ch * 4;
        cp16(sb + OQ * 4 + so,  Q + go);
        cp16(sb + OGC * 4 + so, G + go);
    }
    cp_commit();
    for (int c = tid; c < 2048; c += 512) {
        const int row = c >> 5, ch = c & 31;
        cp16(sb + OV * 4 + (uint32_t)(row * ASD * 4 + ch * 16),
             V + base + (size_t)row * 4096 + ch * 4);
    }
    cp_commit();
    for (int i = tid; i < 8192; i += 512) {
        const int s = i >> 7, d = i & 127;
        sKT[d * ASDK + s] = K[base + (size_t)s * 4096 + d];
    }
    cp_wait<1>();
    __syncthreads();

    if (tid >= 128) {
        const float LN1E4_64 = 0.14391156531879916f;
        for (int i = tid - 128; i < 4096; i += 384) {
            const int s = i >> 6, q = i & 63;
            const float invf = expf(-(float)s * LN1E4_64);
            const float ang  = t[q] * invf;
            const float cs = cosf(ang), sn = sinf(ang);
            float a, b2;
            a = sQ[s * ASD + q]; b2 = sQ[s * ASD + q + 64];
            sQ[s * ASD + q]      = a * cs - b2 * sn;
            sQ[s * ASD + q + 64] = b2 * cs + a * sn;
            a = sKT[q * ASDK + s]; b2 = sKT[(q + 64) * ASDK + s];
            sKT[q * ASDK + s]        = a * cs - b2 * sn;
            sKT[(q + 64) * ASDK + s] = b2 * cs + a * sn;
        }
    } else {
        const int d = tid;
        float run = 1.f;
        for (int s = 0; s < 64; s++) {
            run *= sGc[s * ASD + d];
            sGc[s * ASD + d]   = run;
            sGiT[d * ASDK + s] = 1.f / run;
        }
    }
    __syncthreads();

    {
        const int w = tid >> 5, lane = tid & 31;
        const int wq = w >> 2, wk = w & 3;
        const int lq = lane >> 2, lk = lane & 3;
        const int q0 = wq * 16 + lq * 2;
        const int k0 = wk * 16 + lk * 4;
        float acc[2][4] = {{0,0,0,0},{0,0,0,0}};
        float dac[2][4] = {{0,0,0,0},{0,0,0,0}};

        if (wk <= wq) {
#pragma unroll 2
            for (int kk = 0; kk < 128; kk += 4) {
                float qv0[4], qv1[4], gq0[4], gq1[4];
                *(float4*)qv0 = *(const float4*)&sQ[q0 * ASD + kk];
                *(float4*)qv1 = *(const float4*)&sQ[(q0 + 1) * ASD + kk];
                *(float4*)gq0 = *(const float4*)&sGc[q0 * ASD + kk];
                *(float4*)gq1 = *(const float4*)&sGc[(q0 + 1) * ASD + kk];
                float kv[4][4], gi[4][4];
#pragma unroll
                for (int r = 0; r < 4; r++) {
                    *(float4*)kv[r] = *(const float4*)&sKT[(kk + r) * ASDK + k0];
                    *(float4*)gi[r] = *(const float4*)&sGiT[(kk + r) * ASDK + k0];
                }
#pragma unroll
                for (int r = 0; r < 4; r++)
#pragma unroll
                    for (int j = 0; j < 4; j++) {
                        acc[0][j] = fmaf(qv0[r], kv[r][j], acc[0][j]);
                        acc[1][j] = fmaf(qv1[r], kv[r][j], acc[1][j]);
                        dac[0][j] = fmaf(gq0[r], gi[r][j], dac[0][j]);
                        dac[1][j] = fmaf(gq1[r], gi[r][j], dac[1][j]);
                    }
            }
        }
#pragma unroll
        for (int i = 0; i < 2; i++)
#pragma unroll
            for (int j = 0; j < 4; j++) {
                const int qi = q0 + i, kj = k0 + j;
                sS[qi * 64 + kj] =
                    (kj <= qi) ? acc[i][j] * dac[i][j] * (1.0f / 128.0f) : 0.f;
            }
    }
    cp_wait<0>();
    __syncthreads();

    {
        const int w = tid >> 5, lane = tid & 31;
        const int d0 = lane * 4;
#pragma unroll
        for (int qq = 0; qq < 4; qq++) {
            const int q = w * 4 + qq;
            float a0 = 0.f, a1 = 0.f, a2 = 0.f, a3 = 0.f;
            for (int kq = 0; kq <= w; kq++) {
                float sv[4];
                *(float4*)sv = *(const float4*)&sS[q * 64 + kq * 4];
#pragma unroll
                for (int r = 0; r < 4; r++) {
                    float v[4];
                    *(float4*)v = *(const float4*)&sV[(kq * 4 + r) * ASD + d0];
                    a0 = fmaf(sv[r], v[0], a0);
                    a1 = fmaf(sv[r], v[1], a1);
                    a2 = fmaf(sv[r], v[2], a2);
                    a3 = fmaf(sv[r], v[3], a3);
                }
            }
            const size_t go = base + (size_t)q * 4096 + d0;
            __half h0 = __float2half(a0), h1 = __float2half(a1);
            __half h2 = __float2half(a2), h3 = __float2half(a3);
            __half l0 = __float2half(a0 - __half2float(h0));
            __half l1 = __float2half(a1 - __half2float(h1));
            __half l2 = __float2half(a2 - __half2float(h2));
            __half l3 = __float2half(a3 - __half2float(h3));
            *(__half2*)(OH + go)     = __half2(h0, h1);
            *(__half2*)(OH + go + 2) = __half2(h2, h3);
            *(__half2*)(OL + go)     = __half2(l0, l1);
            *(__half2*)(OL + go + 2) = __half2(l2, l3);
        }
    }
}

// =====================================================================
// launch
// =====================================================================
extern "C" void kernel_launch(void* const* d_in, const int* in_sizes, int n_in,
                              void* d_out, int out_size)
{
    const float* x  = (const float*)d_in[0];
    const float* t  = (const float*)d_in[1];
    const float* Wq = (const float*)d_in[2];
    const float* bq = (const float*)d_in[3];
    const float* Wk = (const float*)d_in[4];
    const float* bk = (const float*)d_in[5];
    const float* Wv = (const float*)d_in[6];
    const float* bv = (const float*)d_in[7];
    const float* Wd = (const float*)d_in[8];
    const float* bd = (const float*)d_in[9];
    const float* Wo = (const float*)d_in[10];
    const float* bo = (const float*)d_in[11];
    float* out = (float*)d_out;

    float *Qb, *Kb, *Vb, *Gb;
    __half *xh, *xl, *ah, *al, *wh, *wl;
    cudaGetSymbolAddress((void**)&Qb, g_Q);
    cudaGetSymbolAddress((void**)&Kb, g_K);
    cudaGetSymbolAddress((void**)&Vb, g_V);
    cudaGetSymbolAddress((void**)&Gb, g_G);
    cudaGetSymbolAddress((void**)&xh, g_xh);
    cudaGetSymbolAddress((void**)&xl, g_xl);
    cudaGetSymbolAddress((void**)&ah, g_ah);
    cudaGetSymbolAddress((void**)&al, g_al);
    cudaGetSymbolAddress((void**)&wh, g_wh);
    cudaGetSymbolAddress((void**)&wl, g_wl);

    const int n4x = MTOT * NE / 4;
    const int n4w = NE * KE / 4;
    split_k<<<2048, 256>>>(x, xh, xl, n4x, 1);
    split_w3<<<12288, 256>>>(Wq, Wk, Wv, wh, (half*)0, n4w, 3, -1);
    split_w3<<<8192, 256>>>(Wd, Wo, Wo, wh + 3 * WSL, wl, n4w, 2, 0);

    cudaFuncSetAttribute(gemm_f, cudaFuncAttributeMaxDynamicSharedMemorySize, GSMEM);

    // merged Q/K/V/gamma projections: one launch, z=3 -> gamma path
    gemm_f<<<dim3(NE / 256, MTOT / 128, 4), 256, GSMEM>>>(
        xh, xl, wh, wl, bq, bk, bv, bd, Qb, Kb, Vb, Gb, /*sigz=*/3);

    // fused attention (writes fp16 hi/lo planes directly)
    cudaFuncSetAttribute(attn2, cudaFuncAttributeMaxDynamicSharedMemorySize, ASMEM);
    attn2<<<1024, 512, ASMEM>>>(Qb, Kb, Vb, Gb, t, ah, al);

    // output projection (1.5-term)
    gemm_f<<<dim3(NE / 256, MTOT / 128, 1), 256, GSMEM>>>(
        ah, al, wh + 4 * WSL, wl, bo, bo, bo, bo, out, out, out, out, /*sigz=*/-1);
}

// round 11
// speedup vs baseline: 5.7378x; 1.2074x over previous
#include <cuda_runtime.h>
#include <cuda_fp16.h>
#include <math.h>
#include <stdint.h>

// Problem constants
#define MTOT 2048   // BATCH*SEQ = 32*64
#define NE   4096   // EMBED_DIM
#define KE   4096
#define WSL  16777216ull   // elements per weight slot (4096*4096)

// ---------------- scratch (allocation-free: __device__ globals) ----------------
__device__ float g_Q[MTOT * NE];
__device__ float g_K[MTOT * NE];
__device__ float g_V[MTOT * NE];
__device__ float g_G[MTOT * NE];

__device__ __half g_xh[MTOT * NE];
__device__ __half g_xl[MTOT * NE];
__device__ __half g_ah[MTOT * NE];
__device__ __half g_wh[5 * WSL];   // slots: Wq,Wk,Wv,Wd,Wo (hi plane)
__device__ __half g_wl[WSL];       // lo plane, only needed for Wd (gamma)

// =====================================================================
// helpers
// =====================================================================
__device__ __forceinline__ uint32_t smem_u32(const void* p) {
    uint32_t a;
    asm("{ .reg .u64 t; cvta.to.shared.u64 t, %1; cvt.u32.u64 %0, t; }" : "=r"(a) : "l"(p));
    return a;
}
__device__ __forceinline__ void cp16(uint32_t s, const void* g) {
    asm volatile("cp.async.cg.shared.global [%0], [%1], 16;" :: "r"(s), "l"(g));
}
__device__ __forceinline__ void cp_commit() {
    asm volatile("cp.async.commit_group;" ::: "memory");
}
template <int N>
__device__ __forceinline__ void cp_wait() {
    asm volatile("cp.async.wait_group %0;" :: "n"(N) : "memory");
}
__device__ __forceinline__ void ldm_x4(uint32_t* r, uint32_t a) {
    asm volatile("ldmatrix.sync.aligned.m8n8.x4.shared.b16 {%0,%1,%2,%3}, [%4];"
                 : "=r"(r[0]), "=r"(r[1]), "=r"(r[2]), "=r"(r[3]) : "r"(a));
}
__device__ __forceinline__ void mma4(float* c, const uint32_t* a, uint32_t b0, uint32_t b1) {
    asm volatile("mma.sync.aligned.m16n8k16.row.col.f32.f16.f16.f32 "
                 "{%0,%1,%2,%3}, {%4,%5,%6,%7}, {%8,%9}, {%0,%1,%2,%3};"
                 : "+f"(c[0]), "+f"(c[1]), "+f"(c[2]), "+f"(c[3])
                 : "r"(a[0]), "r"(a[1]), "r"(a[2]), "r"(a[3]), "r"(b0), "r"(b1));
}

// =====================================================================
// fp32 -> fp16 hi/lo split
// =====================================================================
__global__ void split_k(const float* __restrict__ in, __half* __restrict__ hi,
                        __half* __restrict__ lo, int n4, int wlo)
{
    int i = blockIdx.x * blockDim.x + threadIdx.x;
    const int str = gridDim.x * blockDim.x;
    for (; i < n4; i += str) {
        float4 v = ((const float4*)in)[i];
        __half h0 = __float2half(v.x), h1 = __float2half(v.y);
        __half h2 = __float2half(v.z), h3 = __float2half(v.w);
        __half2* hp = (__half2*)hi;
        hp[2 * i]     = __half2(h0, h1);
        hp[2 * i + 1] = __half2(h2, h3);
        if (wlo) {
            __half l0 = __float2half(v.x - __half2float(h0));
            __half l1 = __float2half(v.y - __half2float(h1));
            __half l2 = __float2half(v.z - __half2float(h2));
            __half l3 = __float2half(v.w - __half2float(h3));
            __half2* lp = (__half2*)lo;
            lp[2 * i]     = __half2(l0, l1);
            lp[2 * i + 1] = __half2(l2, l3);
        }
    }
}

// up to 3 weight slots per launch; lo plane only for slot == loslot
__global__ void split_w3(const float* __restrict__ w0, const float* __restrict__ w1,
                         const float* __restrict__ w2,
                         __half* __restrict__ whb, __half* __restrict__ wlb,
                         int n4w, int nslots, int loslot)
{
    int i = blockIdx.x * blockDim.x + threadIdx.x;
    const int str = gridDim.x * blockDim.x;
    const int tot = nslots * n4w;
    for (; i < tot; i += str) {
        const int slot = i / n4w;
        const int j = i - slot * n4w;
        const float* in = (slot == 0) ? w0 : (slot == 1) ? w1 : w2;
        float4 v = ((const float4*)in)[j];
        __half h0 = __float2half(v.x), h1 = __float2half(v.y);
        __half h2 = __float2half(v.z), h3 = __float2half(v.w);
        __half2* hp = (__half2*)(whb + (size_t)slot * WSL);
        hp[2 * j]     = __half2(h0, h1);
        hp[2 * j + 1] = __half2(h2, h3);
        if (slot == loslot) {
            __half l0 = __float2half(v.x - __half2float(h0));
            __half l1 = __float2half(v.y - __half2float(h1));
            __half l2 = __float2half(v.z - __half2float(h2));
            __half l3 = __float2half(v.w - __half2float(h3));
            __half2* lp = (__half2*)wlb;
            lp[2 * j]     = __half2(l0, l1);
            lp[2 * j + 1] = __half2(l2, l3);
        }
    }
}

// =====================================================================
// common GEMM geometry
// =====================================================================
#define PAH 0
#define PAL 10240
#define PBH 20480
#define PBL 40960
#define STG 61440
#define GSMEM (3 * STG)   // 184320 bytes

// =====================================================================
// gemm_f: fused projection GEMM.
//   z != sigz: 1-term plain fp16 (ah*bh)
//   z == sigz: gamma — 3-term (ah*bh + al*bh + ah*bl) + sigmoid epilogue
// CTA tile 128x256, BK=32, 8 warps (2m x 4n), warp tile 64x64, 3 stages.
// =====================================================================
__global__ __launch_bounds__(256, 1) void gemm_f(
    const __half* __restrict__ Ahp, const __half* __restrict__ Alp,
    const __half* __restrict__ Whp, const __half* __restrict__ Wlp,
    const float* __restrict__ b0p, const float* __restrict__ b1p,
    const float* __restrict__ b2p, const float* __restrict__ b3p,
    float* C0, float* C1, float* C2, float* C3, int sigz)
{
    extern __shared__ char smem[];
    const uint32_t sb = smem_u32(smem);
    const int tid = threadIdx.x, z = blockIdx.z;
    const bool three = (z == sigz);

    const __half* Wh = Whp + (size_t)z * WSL;
    const float* bias = (z == 0) ? b0p : (z == 1) ? b1p : (z == 2) ? b2p : b3p;
    float*       C    = (z == 0) ? C0  : (z == 1) ? C1  : (z == 2) ? C2  : C3;

    const int bm = blockIdx.y * 128;
    const int bn = blockIdx.x * 256;
    const size_t aoff = (size_t)bm * KE;
    const size_t boff = (size_t)bn * KE;

    const int crow = tid >> 2, cch = tid & 3;
    const uint32_t soc = (uint32_t)crow * 80 + (uint32_t)cch * 16;
    const size_t   goc = (size_t)crow * KE + (size_t)cch * 8;

    const int lane = tid & 31, wid = tid >> 5;
    const int wm = wid >> 2, wn = wid & 3;
    const int mA = lane >> 3, rA = lane & 7;
    uint32_t offA[4];
#pragma unroll
    for (int mi = 0; mi < 4; mi++)
        offA[mi] = (uint32_t)((wm * 64 + mi * 16 + (mA & 1) * 8 + rA) * 80 + (mA >> 1) * 16);
    uint32_t offB[4];
#pragma unroll
    for (int njp = 0; njp < 4; njp++)
        offB[njp] = (uint32_t)((wn * 64 + njp * 16 + (mA >> 1) * 8 + rA) * 80 + (mA & 1) * 16);

    float acc[4][8][4];
#pragma unroll
    for (int mi = 0; mi < 4; mi++)
#pragma unroll
        for (int nj = 0; nj < 8; nj++)
#pragma unroll
            for (int r = 0; r < 4; r++) acc[mi][nj][r] = 0.f;

    const int NST = KE / 32;  // 128

    if (!three) {
        // ---------- 1-term path (plain fp16) ----------
        auto load1 = [&](int p, int kt) {
            const uint32_t s = sb + (uint32_t)p * STG;
#pragma unroll
            for (int u = 0; u < 2; u++) {
                const uint32_t so2 = soc + (uint32_t)u * 64 * 80;
                const size_t   go2 = goc + (size_t)u * 64 * KE + kt;
                cp16(s + PAH + so2, Ahp + aoff + go2);
            }
#pragma unroll
            for (int u = 0; u < 4; u++) {
                const uint32_t so2 = soc + (uint32_t)u * 64 * 80;
                const size_t   go2 = goc + (size_t)u * 64 * KE + kt;
                cp16(s + PBH + so2, Wh + boff + go2);
            }
            cp_commit();
        };

        load1(0, 0);
        load1(1, 32);

        for (int i = 0; i < NST; i++) {
            if (i >= NST - 2) cp_wait<0>();
            else              cp_wait<1>();
            __syncthreads();

            const uint32_t s = sb + (uint32_t)(i % 3) * STG;

            uint32_t ah0[4][4], bh0[4][4], ah1[4][4], bh1[4][4];
#pragma unroll
            for (int mi = 0; mi < 4; mi++) ldm_x4(ah0[mi], s + PAH + offA[mi]);
#pragma unroll
            for (int njp = 0; njp < 4; njp++) ldm_x4(bh0[njp], s + PBH + offB[njp]);

            // MMA (ks=0)
#pragma unroll
            for (int njp = 0; njp < 4; njp++)
#pragma unroll
                for (int mi = 0; mi < 4; mi++) {
                    mma4(acc[mi][2 * njp],     ah0[mi], bh0[njp][0], bh0[njp][1]);
                    mma4(acc[mi][2 * njp + 1], ah0[mi], bh0[njp][2], bh0[njp][3]);
                }

            if (i + 2 < NST) load1((i + 2) % 3, (i + 2) * 32);

#pragma unroll
            for (int mi = 0; mi < 4; mi++) ldm_x4(ah1[mi], s + PAH + offA[mi] + 32);
#pragma unroll
            for (int njp = 0; njp < 4; njp++) ldm_x4(bh1[njp], s + PBH + offB[njp] + 32);

            // MMA (ks=1)
#pragma unroll
            for (int njp = 0; njp < 4; njp++)
#pragma unroll
                for (int mi = 0; mi < 4; mi++) {
                    mma4(acc[mi][2 * njp],     ah1[mi], bh1[njp][0], bh1[njp][1]);
                    mma4(acc[mi][2 * njp + 1], ah1[mi], bh1[njp][2], bh1[njp][3]);
                }
        }
    } else {
        // ---------- gamma: 3-term + sigmoid ----------
        auto load3 = [&](int p, int kt) {
            const uint32_t s = sb + (uint32_t)p * STG;
#pragma unroll
            for (int u = 0; u < 2; u++) {
                const uint32_t so2 = soc + (uint32_t)u * 64 * 80;
                const size_t   go2 = goc + (size_t)u * 64 * KE + kt;
                cp16(s + PAH + so2, Ahp + aoff + go2);
                cp16(s + PAL + so2, Alp + aoff + go2);
            }
#pragma unroll
            for (int u = 0; u < 4; u++) {
                const uint32_t so2 = soc + (uint32_t)u * 64 * 80;
                const size_t   go2 = goc + (size_t)u * 64 * KE + kt;
                cp16(s + PBH + so2, Wh + boff + go2);
                cp16(s + PBL + so2, Wlp + boff + go2);
            }
            cp_commit();
        };

        load3(0, 0);
        load3(1, 32);

        for (int i = 0; i < NST; i++) {
            if (i >= NST - 2) cp_wait<0>();
            else              cp_wait<1>();
            __syncthreads();

            const uint32_t s = sb + (uint32_t)(i % 3) * STG;
#pragma unroll
            for (int ks = 0; ks < 2; ks++) {
                const uint32_t kb = (uint32_t)ks * 32;
                uint32_t ah[4][4], al[4][4], bh[4][4];
#pragma unroll
                for (int mi = 0; mi < 4; mi++) {
                    ldm_x4(ah[mi], s + PAH + offA[mi] + kb);
                    ldm_x4(al[mi], s + PAL + offA[mi] + kb);
                }
#pragma unroll
                for (int njp = 0; njp < 4; njp++)
                    ldm_x4(bh[njp], s + PBH + offB[njp] + kb);

#pragma unroll
                for (int njp = 0; njp < 4; njp++)
#pragma unroll
                    for (int mi = 0; mi < 4; mi++) {
                        mma4(acc[mi][2 * njp],     ah[mi], bh[njp][0], bh[njp][1]);
                        mma4(acc[mi][2 * njp + 1], ah[mi], bh[njp][2], bh[njp][3]);
                    }
                if (ks == 0 && i + 2 < NST) load3((i + 2) % 3, (i + 2) * 32);
#pragma unroll
                for (int njp = 0; njp < 4; njp++)
#pragma unroll
                    for (int mi = 0; mi < 4; mi++) {
                        mma4(acc[mi][2 * njp],     al[mi], bh[njp][0], bh[njp][1]);
                        mma4(acc[mi][2 * njp + 1], al[mi], bh[njp][2], bh[njp][3]);
                    }
#pragma unroll
                for (int njp = 0; njp < 4; njp++) {
                    uint32_t bl[4];
                    ldm_x4(bl, s + PBL + offB[njp] + kb);
#pragma unroll
                    for (int mi = 0; mi < 4; mi++) {
                        mma4(acc[mi][2 * njp],     ah[mi], bl[0], bl[1]);
                        mma4(acc[mi][2 * njp + 1], ah[mi], bl[2], bl[3]);
                    }
                }
            }
        }
    }

    // epilogue (sigmoid if gamma)
    const int g = lane >> 2, t4 = lane & 3;
#pragma unroll
    for (int mi = 0; mi < 4; mi++) {
#pragma unroll
        for (int nj = 0; nj < 8; nj++) {
            const int row = bm + wm * 64 + mi * 16 + g;
            const int col = bn + wn * 64 + nj * 8 + 2 * t4;
            const float bb0 = bias[col], bb1 = bias[col + 1];
            float v0 = acc[mi][nj][0] + bb0, v1 = acc[mi][nj][1] + bb1;
            float v2 = acc[mi][nj][2] + bb0, v3 = acc[mi][nj][3] + bb1;
            if (three) {
                v0 = 1.f / (1.f + expf(-v0)); v1 = 1.f / (1.f + expf(-v1));
                v2 = 1.f / (1.f + expf(-v2)); v3 = 1.f / (1.f + expf(-v3));
            }
            *(float2*)(C + (size_t)row * NE + col)       = make_float2(v0, v1);
            *(float2*)(C + (size_t)(row + 8) * NE + col) = make_float2(v2, v3);
        }
    }
}

// =====================================================================
// Fused attention v2 (fp16 hi-only epilogue; out-proj is 1-term)
// =====================================================================
#define ASD  132
#define ASDK 68
#define OQ  0
#define OGC 8448
#define OKT 16896
#define OGT 25600
#define OS  34304
#define OV  38400
#define ASMEM ((38400 + 8448) * 4)   // 187392 bytes

__global__ __launch_bounds__(512, 1) void attn2(
    const float* __restrict__ Q, const float* __restrict__ K,
    const float* __restrict__ V, const float* __restrict__ G,
    const float* __restrict__ t, __half* __restrict__ OH)
{
    extern __shared__ float sm[];
    float* sQ   = sm + OQ;
    float* sGc  = sm + OGC;
    float* sKT  = sm + OKT;
    float* sGiT = sm + OGT;
    float* sS   = sm + OS;
    float* sV   = sm + OV;
    const uint32_t sb = smem_u32(sm);

    const int bh = blockIdx.x;
    const int b  = bh >> 5, h = bh & 31;
    const int tid = threadIdx.x;
    const size_t base = ((size_t)b * 64) * 4096 + (size_t)h * 128;

    for (int c = tid; c < 2048; c += 512) {
        const int row = c >> 5, ch = c & 31;
        const uint32_t so = (uint32_t)(row * ASD * 4 + ch * 16);
        const size_t   go = base + (size_t)row * 4096 + ch * 4;
        cp16(sb + OQ * 4 + so,  Q + go);
        cp16(sb + OGC * 4 + so, G + go);
    }
    cp_commit();
    for (int c = tid; c < 2048; c += 512) {
        const int row = c >> 5, ch = c & 31;
        cp16(sb + OV * 4 + (uint32_t)(row * ASD * 4 + ch * 16),
             V + base + (size_t)row * 4096 + ch * 4);
    }
    cp_commit();
    for (int i = tid; i < 8192; i += 512) {
        const int s = i >> 7, d = i & 127;
        sKT[d * ASDK + s] = K[base + (size_t)s * 4096 + d];
    }
    cp_wait<1>();
    __syncthreads();

    if (tid >= 128) {
        const float LN1E4_64 = 0.14391156531879916f;
        for (int i = tid - 128; i < 4096; i += 384) {
            const int s = i >> 6, q = i & 63;
            const float invf = expf(-(float)s * LN1E4_64);
            const float ang  = t[q] * invf;
            const float cs = cosf(ang), sn = sinf(ang);
            float a, b2;
            a = sQ[s * ASD + q]; b2 = sQ[s * ASD + q + 64];
            sQ[s * ASD + q]      = a * cs - b2 * sn;
            sQ[s * ASD + q + 64] = b2 * cs + a * sn;
            a = sKT[q * ASDK + s]; b2 = sKT[(q + 64) * ASDK + s];
            sKT[q * ASDK + s]        = a * cs - b2 * sn;
            sKT[(q + 64) * ASDK + s] = b2 * cs + a * sn;
        }
    } else {
        const int d = tid;
        float run = 1.f;
        for (int s = 0; s < 64; s++) {
            run *= sGc[s * ASD + d];
            sGc[s * ASD + d]   = run;
            sGiT[d * ASDK + s] = 1.f / run;
        }
    }
    __syncthreads();

    {
        const int w = tid >> 5, lane = tid & 31;
        const int wq = w >> 2, wk = w & 3;
        const int lq = lane >> 2, lk = lane & 3;
        const int q0 = wq * 16 + lq * 2;
        const int k0 = wk * 16 + lk * 4;
        float acc[2][4] = {{0,0,0,0},{0,0,0,0}};
        float dac[2][4] = {{0,0,0,0},{0,0,0,0}};

        if (wk <= wq) {
#pragma unroll 2
            for (int kk = 0; kk < 128; kk += 4) {
                float qv0[4], qv1[4], gq0[4], gq1[4];
                *(float4*)qv0 = *(const float4*)&sQ[q0 * ASD + kk];
                *(float4*)qv1 = *(const float4*)&sQ[(q0 + 1) * ASD + kk];
                *(float4*)gq0 = *(const float4*)&sGc[q0 * ASD + kk];
                *(float4*)gq1 = *(const float4*)&sGc[(q0 + 1) * ASD + kk];
                float kv[4][4], gi[4][4];
#pragma unroll
                for (int r = 0; r < 4; r++) {
                    *(float4*)kv[r] = *(const float4*)&sKT[(kk + r) * ASDK + k0];
                    *(float4*)gi[r] = *(const float4*)&sGiT[(kk + r) * ASDK + k0];
                }
#pragma unroll
                for (int r = 0; r < 4; r++)
#pragma unroll
                    for (int j = 0; j < 4; j++) {
                        acc[0][j] = fmaf(qv0[r], kv[r][j], acc[0][j]);
                        acc[1][j] = fmaf(qv1[r], kv[r][j], acc[1][j]);
                        dac[0][j] = fmaf(gq0[r], gi[r][j], dac[0][j]);
                        dac[1][j] = fmaf(gq1[r], gi[r][j], dac[1][j]);
                    }
            }
        }
#pragma unroll
        for (int i = 0; i < 2; i++)
#pragma unroll
            for (int j = 0; j < 4; j++) {
                const int qi = q0 + i, kj = k0 + j;
                sS[qi * 64 + kj] =
                    (kj <= qi) ? acc[i][j] * dac[i][j] * (1.0f / 128.0f) : 0.f;
            }
    }
    cp_wait<0>();
    __syncthreads();

    {
        const int w = tid >> 5, lane = tid & 31;
        const int d0 = lane * 4;
#pragma unroll
        for (int qq = 0; qq < 4; qq++) {
            const int q = w * 4 + qq;
            float a0 = 0.f, a1 = 0.f, a2 = 0.f, a3 = 0.f;
            for (int kq = 0; kq <= w; kq++) {
                float sv[4];
                *(float4*)sv = *(const float4*)&sS[q * 64 + kq * 4];
#pragma unroll
                for (int r = 0; r < 4; r++) {
                    float v[4];
                    *(float4*)v = *(const float4*)&sV[(kq * 4 + r) * ASD + d0];
                    a0 = fmaf(sv[r], v[0], a0);
                    a1 = fmaf(sv[r], v[1], a1);
                    a2 = fmaf(sv[r], v[2], a2);
                    a3 = fmaf(sv[r], v[3], a3);
                }
            }
            const size_t go = base + (size_t)q * 4096 + d0;
            __half h0 = __float2half(a0), h1 = __float2half(a1);
            __half h2 = __float2half(a2), h3 = __float2half(a3);
            *(__half2*)(OH + go)     = __half2(h0, h1);
            *(__half2*)(OH + go + 2) = __half2(h2, h3);
        }
    }
}

// =====================================================================
// launch
// =====================================================================
extern "C" void kernel_launch(void* const* d_in, const int* in_sizes, int n_in,
                              void* d_out, int out_size)
{
    const float* x  = (const float*)d_in[0];
    const float* t  = (const float*)d_in[1];
    const float* Wq = (const float*)d_in[2];
    const float* bq = (const float*)d_in[3];
    const float* Wk = (const float*)d_in[4];
    const float* bk = (const float*)d_in[5];
    const float* Wv = (const float*)d_in[6];
    const float* bv = (const float*)d_in[7];
    const float* Wd = (const float*)d_in[8];
    const float* bd = (const float*)d_in[9];
    const float* Wo = (const float*)d_in[10];
    const float* bo = (const float*)d_in[11];
    float* out = (float*)d_out;

    float *Qb, *Kb, *Vb, *Gb;
    __half *xh, *xl, *ah, *wh, *wl;
    cudaGetSymbolAddress((void**)&Qb, g_Q);
    cudaGetSymbolAddress((void**)&Kb, g_K);
    cudaGetSymbolAddress((void**)&Vb, g_V);
    cudaGetSymbolAddress((void**)&Gb, g_G);
    cudaGetSymbolAddress((void**)&xh, g_xh);
    cudaGetSymbolAddress((void**)&xl, g_xl);
    cudaGetSymbolAddress((void**)&ah, g_ah);
    cudaGetSymbolAddress((void**)&wh, g_wh);
    cudaGetSymbolAddress((void**)&wl, g_wl);

    const int n4x = MTOT * NE / 4;
    const int n4w = NE * KE / 4;
    split_k<<<2048, 256>>>(x, xh, xl, n4x, 1);          // gamma needs xl
    split_w3<<<12288, 256>>>(Wq, Wk, Wv, wh, (half*)0, n4w, 3, -1);
    split_w3<<<8192, 256>>>(Wd, Wo, Wo, wh + 3 * WSL, wl, n4w, 2, 0);

    cudaFuncSetAttribute(gemm_f, cudaFuncAttributeMaxDynamicSharedMemorySize, GSMEM);

    // merged Q/K/V/gamma projections: z=3 -> gamma (3-term+sigmoid), else 1-term
    gemm_f<<<dim3(NE / 256, MTOT / 128, 4), 256, GSMEM>>>(
        xh, xl, wh, wl, bq, bk, bv, bd, Qb, Kb, Vb, Gb, /*sigz=*/3);

    // fused attention (writes fp16 hi plane only)
    cudaFuncSetAttribute(attn2, cudaFuncAttributeMaxDynamicSharedMemorySize, ASMEM);
    attn2<<<1024, 512, ASMEM>>>(Qb, Kb, Vb, Gb, t, ah);

    // output projection (1-term)
    gemm_f<<<dim3(NE / 256, MTOT / 128, 1), 256, GSMEM>>>(
        ah, (half*)0, wh + 4 * WSL, wl, bo, bo, bo, bo, out, out, out, out, /*sigz=*/-1);
}

// round 12
// speedup vs baseline: 5.8368x; 1.0172x over previous
#include <cuda_runtime.h>
#include <cuda_fp16.h>
#include <math.h>
#include <stdint.h>

// Problem constants
#define MTOT 2048   // BATCH*SEQ = 32*64
#define NE   4096   // EMBED_DIM
#define KE   4096
#define WSL  16777216ull   // elements per weight slot (4096*4096)

// ---------------- scratch (allocation-free: __device__ globals) ----------------
__device__ float g_Q[MTOT * NE];
__device__ float g_K[MTOT * NE];
__device__ float g_V[MTOT * NE];
__device__ float g_G[MTOT * NE];

__device__ __half g_xh[MTOT * NE];
__device__ __half g_xl[MTOT * NE];
__device__ __half g_ah[MTOT * NE];
__device__ __half g_wh[5 * WSL];   // slots: Wq,Wk,Wv,Wd,Wo (hi plane)
__device__ __half g_wl[WSL];       // lo plane, only needed for Wd (gamma)

// =====================================================================
// helpers
// =====================================================================
__device__ __forceinline__ uint32_t smem_u32(const void* p) {
    uint32_t a;
    asm("{ .reg .u64 t; cvta.to.shared.u64 t, %1; cvt.u32.u64 %0, t; }" : "=r"(a) : "l"(p));
    return a;
}
__device__ __forceinline__ void cp16(uint32_t s, const void* g) {
    asm volatile("cp.async.cg.shared.global [%0], [%1], 16;" :: "r"(s), "l"(g));
}
__device__ __forceinline__ void cp_commit() {
    asm volatile("cp.async.commit_group;" ::: "memory");
}
template <int N>
__device__ __forceinline__ void cp_wait() {
    asm volatile("cp.async.wait_group %0;" :: "n"(N) : "memory");
}
__device__ __forceinline__ void ldm_x4(uint32_t* r, uint32_t a) {
    asm volatile("ldmatrix.sync.aligned.m8n8.x4.shared.b16 {%0,%1,%2,%3}, [%4];"
                 : "=r"(r[0]), "=r"(r[1]), "=r"(r[2]), "=r"(r[3]) : "r"(a));
}
__device__ __forceinline__ void mma4(float* c, const uint32_t* a, uint32_t b0, uint32_t b1) {
    asm volatile("mma.sync.aligned.m16n8k16.row.col.f32.f16.f16.f32 "
                 "{%0,%1,%2,%3}, {%4,%5,%6,%7}, {%8,%9}, {%0,%1,%2,%3};"
                 : "+f"(c[0]), "+f"(c[1]), "+f"(c[2]), "+f"(c[3])
                 : "r"(a[0]), "r"(a[1]), "r"(a[2]), "r"(a[3]), "r"(b0), "r"(b1));
}

// =====================================================================
// fp32 -> fp16 hi/lo split
// =====================================================================
__global__ void split_k(const float* __restrict__ in, __half* __restrict__ hi,
                        __half* __restrict__ lo, int n4, int wlo)
{
    int i = blockIdx.x * blockDim.x + threadIdx.x;
    const int str = gridDim.x * blockDim.x;
    for (; i < n4; i += str) {
        float4 v = ((const float4*)in)[i];
        __half h0 = __float2half(v.x), h1 = __float2half(v.y);
        __half h2 = __float2half(v.z), h3 = __float2half(v.w);
        __half2* hp = (__half2*)hi;
        hp[2 * i]     = __half2(h0, h1);
        hp[2 * i + 1] = __half2(h2, h3);
        if (wlo) {
            __half l0 = __float2half(v.x - __half2float(h0));
            __half l1 = __float2half(v.y - __half2float(h1));
            __half l2 = __float2half(v.z - __half2float(h2));
            __half l3 = __float2half(v.w - __half2float(h3));
            __half2* lp = (__half2*)lo;
            lp[2 * i]     = __half2(l0, l1);
            lp[2 * i + 1] = __half2(l2, l3);
        }
    }
}

// up to 3 weight slots per launch; lo plane only for slot == loslot
__global__ void split_w3(const float* __restrict__ w0, const float* __restrict__ w1,
                         const float* __restrict__ w2,
                         __half* __restrict__ whb, __half* __restrict__ wlb,
                         int n4w, int nslots, int loslot)
{
    int i = blockIdx.x * blockDim.x + threadIdx.x;
    const int str = gridDim.x * blockDim.x;
    const int tot = nslots * n4w;
    for (; i < tot; i += str) {
        const int slot = i / n4w;
        const int j = i - slot * n4w;
        const float* in = (slot == 0) ? w0 : (slot == 1) ? w1 : w2;
        float4 v = ((const float4*)in)[j];
        __half h0 = __float2half(v.x), h1 = __float2half(v.y);
        __half h2 = __float2half(v.z), h3 = __float2half(v.w);
        __half2* hp = (__half2*)(whb + (size_t)slot * WSL);
        hp[2 * j]     = __half2(h0, h1);
        hp[2 * j + 1] = __half2(h2, h3);
        if (slot == loslot) {
            __half l0 = __float2half(v.x - __half2float(h0));
            __half l1 = __float2half(v.y - __half2float(h1));
            __half l2 = __float2half(v.z - __half2float(h2));
            __half l3 = __float2half(v.w - __half2float(h3));
            __half2* lp = (__half2*)wlb;
            lp[2 * j]     = __half2(l0, l1);
            lp[2 * j + 1] = __half2(l2, l3);
        }
    }
}

// =====================================================================
// GEMM geometry
// =====================================================================
// gamma path (BK=32, hi+lo planes)
#define PAH 0
#define PAL 10240
#define PBH 20480
#define PBL 40960
#define STG 61440
#define GSMEM (3 * STG)   // 184320 bytes
// 1-term path (BK=64, 144B rows)
#define RS64 144
#define PB64 18432        // A tile = 128*144
#define STG64 55296       // + B tile 256*144

// =====================================================================
// gemm_f: fused projection GEMM.
//   z != sigz: 1-term plain fp16 (ah*bh), BK=64, warp-parity k-stagger
//   z == sigz: gamma — 3-term (ah*bh + al*bh + ah*bl) + sigmoid, BK=32
// CTA tile 128x256, 8 warps (2m x 4n), warp tile 64x64, 3 stages.
// =====================================================================
__global__ __launch_bounds__(256, 1) void gemm_f(
    const __half* __restrict__ Ahp, const __half* __restrict__ Alp,
    const __half* __restrict__ Whp, const __half* __restrict__ Wlp,
    const float* __restrict__ b0p, const float* __restrict__ b1p,
    const float* __restrict__ b2p, const float* __restrict__ b3p,
    float* C0, float* C1, float* C2, float* C3, int sigz)
{
    extern __shared__ char smem[];
    const uint32_t sb = smem_u32(smem);
    const int tid = threadIdx.x, z = blockIdx.z;
    const bool three = (z == sigz);

    const __half* Wh = Whp + (size_t)z * WSL;
    const float* bias = (z == 0) ? b0p : (z == 1) ? b1p : (z == 2) ? b2p : b3p;
    float*       C    = (z == 0) ? C0  : (z == 1) ? C1  : (z == 2) ? C2  : C3;

    const int bm = blockIdx.y * 128;
    const int bn = blockIdx.x * 256;
    const size_t aoff = (size_t)bm * KE;
    const size_t boff = (size_t)bn * KE;

    const int lane = tid & 31, wid = tid >> 5;
    const int wm = wid >> 2, wn = wid & 3;
    const int mA = lane >> 3, rA = lane & 7;

    float acc[4][8][4];
#pragma unroll
    for (int mi = 0; mi < 4; mi++)
#pragma unroll
        for (int nj = 0; nj < 8; nj++)
#pragma unroll
            for (int r = 0; r < 4; r++) acc[mi][nj][r] = 0.f;

    if (!three) {
        // ================= 1-term path: BK=64, staggered =================
        uint32_t offA[4], offB[4];
#pragma unroll
        for (int mi = 0; mi < 4; mi++)
            offA[mi] = (uint32_t)((wm * 64 + mi * 16 + (mA & 1) * 8 + rA) * RS64 + (mA >> 1) * 16);
#pragma unroll
        for (int njp = 0; njp < 4; njp++)
            offB[njp] = (uint32_t)(PB64 + (wn * 64 + njp * 16 + (mA >> 1) * 8 + rA) * RS64 + (mA & 1) * 16);

        auto load64 = [&](int p, int kt) {
            const uint32_t s = sb + (uint32_t)p * STG64;
#pragma unroll
            for (int u = 0; u < 4; u++) {   // A: 1024 chunks
                const int c = tid + u * 256;
                const int row = c >> 3, ch = c & 7;
                cp16(s + (uint32_t)(row * RS64 + ch * 16),
                     Ahp + aoff + (size_t)row * KE + kt + ch * 8);
            }
#pragma unroll
            for (int u = 0; u < 8; u++) {   // B: 2048 chunks
                const int c = tid + u * 256;
                const int row = c >> 3, ch = c & 7;
                cp16(s + PB64 + (uint32_t)(row * RS64 + ch * 16),
                     Wh + boff + (size_t)row * KE + kt + ch * 8);
            }
            cp_commit();
        };

        auto mmab = [&](uint32_t fa[4][4], uint32_t fb[4][4]) {
#pragma unroll
            for (int njp = 0; njp < 4; njp++)
#pragma unroll
                for (int mi = 0; mi < 4; mi++) {
                    mma4(acc[mi][2 * njp],     fa[mi], fb[njp][0], fb[njp][1]);
                    mma4(acc[mi][2 * njp + 1], fa[mi], fb[njp][2], fb[njp][3]);
                }
        };

        const int p2 = (wid & 1) * 2;   // parity stagger: odd warps start at ks=2
        const uint32_t kb0 = (uint32_t)(((0 + p2) & 3) * 32);
        const uint32_t kb1 = (uint32_t)(((1 + p2) & 3) * 32);
        const uint32_t kb2 = (uint32_t)(((2 + p2) & 3) * 32);
        const uint32_t kb3 = (uint32_t)(((3 + p2) & 3) * 32);

        load64(0, 0);
        load64(1, 64);

        const int NST = KE / 64;  // 64
        for (int i = 0; i < NST; i++) {
            if (i >= NST - 2) cp_wait<0>();
            else              cp_wait<1>();
            __syncthreads();

            const uint32_t s = sb + (uint32_t)(i % 3) * STG64;
            uint32_t fA[2][4][4], fB[2][4][4];

#pragma unroll
            for (int mi = 0; mi < 4; mi++)  ldm_x4(fA[0][mi], s + offA[mi] + kb0);
#pragma unroll
            for (int njp = 0; njp < 4; njp++) ldm_x4(fB[0][njp], s + offB[njp] + kb0);
#pragma unroll
            for (int mi = 0; mi < 4; mi++)  ldm_x4(fA[1][mi], s + offA[mi] + kb1);
#pragma unroll
            for (int njp = 0; njp < 4; njp++) ldm_x4(fB[1][njp], s + offB[njp] + kb1);

            mmab(fA[0], fB[0]);

            if (i + 2 < NST) load64((i + 2) % 3, (i + 2) * 64);

#pragma unroll
            for (int mi = 0; mi < 4; mi++)  ldm_x4(fA[0][mi], s + offA[mi] + kb2);
#pragma unroll
            for (int njp = 0; njp < 4; njp++) ldm_x4(fB[0][njp], s + offB[njp] + kb2);

            mmab(fA[1], fB[1]);

#pragma unroll
            for (int mi = 0; mi < 4; mi++)  ldm_x4(fA[1][mi], s + offA[mi] + kb3);
#pragma unroll
            for (int njp = 0; njp < 4; njp++) ldm_x4(fB[1][njp], s + offB[njp] + kb3);

            mmab(fA[0], fB[0]);
            mmab(fA[1], fB[1]);
        }
    } else {
        // ================= gamma: BK=32, 3-term + sigmoid =================
        const int crow = tid >> 2, cch = tid & 3;
        const uint32_t soc = (uint32_t)crow * 80 + (uint32_t)cch * 16;
        const size_t   goc = (size_t)crow * KE + (size_t)cch * 8;

        uint32_t offA[4], offB[4];
#pragma unroll
        for (int mi = 0; mi < 4; mi++)
            offA[mi] = (uint32_t)((wm * 64 + mi * 16 + (mA & 1) * 8 + rA) * 80 + (mA >> 1) * 16);
#pragma unroll
        for (int njp = 0; njp < 4; njp++)
            offB[njp] = (uint32_t)((wn * 64 + njp * 16 + (mA >> 1) * 8 + rA) * 80 + (mA & 1) * 16);

        auto load3 = [&](int p, int kt) {
            const uint32_t s = sb + (uint32_t)p * STG;
#pragma unroll
            for (int u = 0; u < 2; u++) {
                const uint32_t so2 = soc + (uint32_t)u * 64 * 80;
                const size_t   go2 = goc + (size_t)u * 64 * KE + kt;
                cp16(s + PAH + so2, Ahp + aoff + go2);
                cp16(s + PAL + so2, Alp + aoff + go2);
            }
#pragma unroll
            for (int u = 0; u < 4; u++) {
                const uint32_t so2 = soc + (uint32_t)u * 64 * 80;
                const size_t   go2 = goc + (size_t)u * 64 * KE + kt;
                cp16(s + PBH + so2, Wh + boff + go2);
                cp16(s + PBL + so2, Wlp + boff + go2);
            }
            cp_commit();
        };

        load3(0, 0);
        load3(1, 32);

        const int NST = KE / 32;
        for (int i = 0; i < NST; i++) {
            if (i >= NST - 2) cp_wait<0>();
            else              cp_wait<1>();
            __syncthreads();

            const uint32_t s = sb + (uint32_t)(i % 3) * STG;
#pragma unroll
            for (int ks = 0; ks < 2; ks++) {
                const uint32_t kb = (uint32_t)((ks ^ (wid & 1)) * 32);  // parity stagger
                uint32_t ah[4][4], al[4][4], bh[4][4];
#pragma unroll
                for (int mi = 0; mi < 4; mi++) {
                    ldm_x4(ah[mi], s + PAH + offA[mi] + kb);
                    ldm_x4(al[mi], s + PAL + offA[mi] + kb);
                }
#pragma unroll
                for (int njp = 0; njp < 4; njp++)
                    ldm_x4(bh[njp], s + PBH + offB[njp] + kb);

#pragma unroll
                for (int njp = 0; njp < 4; njp++)
#pragma unroll
                    for (int mi = 0; mi < 4; mi++) {
                        mma4(acc[mi][2 * njp],     ah[mi], bh[njp][0], bh[njp][1]);
                        mma4(acc[mi][2 * njp + 1], ah[mi], bh[njp][2], bh[njp][3]);
                    }
                if (ks == 0 && i + 2 < NST) load3((i + 2) % 3, (i + 2) * 32);
#pragma unroll
                for (int njp = 0; njp < 4; njp++)
#pragma unroll
                    for (int mi = 0; mi < 4; mi++) {
                        mma4(acc[mi][2 * njp],     al[mi], bh[njp][0], bh[njp][1]);
                        mma4(acc[mi][2 * njp + 1], al[mi], bh[njp][2], bh[njp][3]);
                    }
#pragma unroll
                for (int njp = 0; njp < 4; njp++) {
                    uint32_t bl[4];
                    ldm_x4(bl, s + PBL + offB[njp] + kb);
#pragma unroll
                    for (int mi = 0; mi < 4; mi++) {
                        mma4(acc[mi][2 * njp],     ah[mi], bl[0], bl[1]);
                        mma4(acc[mi][2 * njp + 1], ah[mi], bl[2], bl[3]);
                    }
                }
            }
        }
    }

    // epilogue (sigmoid if gamma)
    const int g = lane >> 2, t4 = lane & 3;
#pragma unroll
    for (int mi = 0; mi < 4; mi++) {
#pragma unroll
        for (int nj = 0; nj < 8; nj++) {
            const int row = bm + wm * 64 + mi * 16 + g;
            const int col = bn + wn * 64 + nj * 8 + 2 * t4;
            const float bb0 = bias[col], bb1 = bias[col + 1];
            float v0 = acc[mi][nj][0] + bb0, v1 = acc[mi][nj][1] + bb1;
            float v2 = acc[mi][nj][2] + bb0, v3 = acc[mi][nj][3] + bb1;
            if (three) {
                v0 = 1.f / (1.f + expf(-v0)); v1 = 1.f / (1.f + expf(-v1));
                v2 = 1.f / (1.f + expf(-v2)); v3 = 1.f / (1.f + expf(-v3));
            }
            *(float2*)(C + (size_t)row * NE + col)       = make_float2(v0, v1);
            *(float2*)(C + (size_t)(row + 8) * NE + col) = make_float2(v2, v3);
        }
    }
}

// =====================================================================
// Fused attention v2 (unchanged, verified)
// =====================================================================
#define ASD  132
#define ASDK 68
#define OQ  0
#define OGC 8448
#define OKT 16896
#define OGT 25600
#define OS  34304
#define OV  38400
#define ASMEM ((38400 + 8448) * 4)   // 187392 bytes

__global__ __launch_bounds__(512, 1) void attn2(
    const float* __restrict__ Q, const float* __restrict__ K,
    const float* __restrict__ V, const float* __restrict__ G,
    const float* __restrict__ t, __half* __restrict__ OH)
{
    extern __shared__ float sm[];
    float* sQ   = sm + OQ;
    float* sGc  = sm + OGC;
    float* sKT  = sm + OKT;
    float* sGiT = sm + OGT;
    float* sS   = sm + OS;
    float* sV   = sm + OV;
    const uint32_t sb = smem_u32(sm);

    const int bh = blockIdx.x;
    const int b  = bh >> 5, h = bh & 31;
    const int tid = threadIdx.x;
    const size_t base = ((size_t)b * 64) * 4096 + (size_t)h * 128;

    for (int c = tid; c < 2048; c += 512) {
        const int row = c >> 5, ch = c & 31;
        const uint32_t so = (uint32_t)(row * ASD * 4 + ch * 16);
        const size_t   go = base + (size_t)row * 4096 + ch * 4;
        cp16(sb + OQ * 4 + so,  Q + go);
        cp16(sb + OGC * 4 + so, G + go);
    }
    cp_commit();
    for (int c = tid; c < 2048; c += 512) {
        const int row = c >> 5, ch = c & 31;
        cp16(sb + OV * 4 + (uint32_t)(row * ASD * 4 + ch * 16),
             V + base + (size_t)row * 4096 + ch * 4);
    }
    cp_commit();
    for (int i = tid; i < 8192; i += 512) {
        const int s = i >> 7, d = i & 127;
        sKT[d * ASDK + s] = K[base + (size_t)s * 4096 + d];
    }
    cp_wait<1>();
    __syncthreads();

    if (tid >= 128) {
        const float LN1E4_64 = 0.14391156531879916f;
        for (int i = tid - 128; i < 4096; i += 384) {
            const int s = i >> 6, q = i & 63;
            const float invf = expf(-(float)s * LN1E4_64);
            const float ang  = t[q] * invf;
            const float cs = cosf(ang), sn = sinf(ang);
            float a, b2;
            a = sQ[s * ASD + q]; b2 = sQ[s * ASD + q + 64];
            sQ[s * ASD + q]      = a * cs - b2 * sn;
            sQ[s * ASD + q + 64] = b2 * cs + a * sn;
            a = sKT[q * ASDK + s]; b2 = sKT[(q + 64) * ASDK + s];
            sKT[q * ASDK + s]        = a * cs - b2 * sn;
            sKT[(q + 64) * ASDK + s] = b2 * cs + a * sn;
        }
    } else {
        const int d = tid;
        float run = 1.f;
        for (int s = 0; s < 64; s++) {
            run *= sGc[s * ASD + d];
            sGc[s * ASD + d]   = run;
            sGiT[d * ASDK + s] = 1.f / run;
        }
    }
    __syncthreads();

    {
        const int w = tid >> 5, lane = tid & 31;
        const int wq = w >> 2, wk = w & 3;
        const int lq = lane >> 2, lk = lane & 3;
        const int q0 = wq * 16 + lq * 2;
        const int k0 = wk * 16 + lk * 4;
        float acc[2][4] = {{0,0,0,0},{0,0,0,0}};
        float dac[2][4] = {{0,0,0,0},{0,0,0,0}};

        if (wk <= wq) {
#pragma unroll 2
            for (int kk = 0; kk < 128; kk += 4) {
                float qv0[4], qv1[4], gq0[4], gq1[4];
                *(float4*)qv0 = *(const float4*)&sQ[q0 * ASD + kk];
                *(float4*)qv1 = *(const float4*)&sQ[(q0 + 1) * ASD + kk];
                *(float4*)gq0 = *(const float4*)&sGc[q0 * ASD + kk];
                *(float4*)gq1 = *(const float4*)&sGc[(q0 + 1) * ASD + kk];
                float kv[4][4], gi[4][4];
#pragma unroll
                for (int r = 0; r < 4; r++) {
                    *(float4*)kv[r] = *(const float4*)&sKT[(kk + r) * ASDK + k0];
                    *(float4*)gi[r] = *(const float4*)&sGiT[(kk + r) * ASDK + k0];
                }
#pragma unroll
                for (int r = 0; r < 4; r++)
#pragma unroll
                    for (int j = 0; j < 4; j++) {
                        acc[0][j] = fmaf(qv0[r], kv[r][j], acc[0][j]);
                        acc[1][j] = fmaf(qv1[r], kv[r][j], acc[1][j]);
                        dac[0][j] = fmaf(gq0[r], gi[r][j], dac[0][j]);
                        dac[1][j] = fmaf(gq1[r], gi[r][j], dac[1][j]);
                    }
            }
        }
#pragma unroll
        for (int i = 0; i < 2; i++)
#pragma unroll
            for (int j = 0; j < 4; j++) {
                const int qi = q0 + i, kj = k0 + j;
                sS[qi * 64 + kj] =
                    (kj <= qi) ? acc[i][j] * dac[i][j] * (1.0f / 128.0f) : 0.f;
            }
    }
    cp_wait<0>();
    __syncthreads();

    {
        const int w = tid >> 5, lane = tid & 31;
        const int d0 = lane * 4;
#pragma unroll
        for (int qq = 0; qq < 4; qq++) {
            const int q = w * 4 + qq;
            float a0 = 0.f, a1 = 0.f, a2 = 0.f, a3 = 0.f;
            for (int kq = 0; kq <= w; kq++) {
                float sv[4];
                *(float4*)sv = *(const float4*)&sS[q * 64 + kq * 4];
#pragma unroll
                for (int r = 0; r < 4; r++) {
                    float v[4];
                    *(float4*)v = *(const float4*)&sV[(kq * 4 + r) * ASD + d0];
                    a0 = fmaf(sv[r], v[0], a0);
                    a1 = fmaf(sv[r], v[1], a1);
                    a2 = fmaf(sv[r], v[2], a2);
                    a3 = fmaf(sv[r], v[3], a3);
                }
            }
            const size_t go = base + (size_t)q * 4096 + d0;
            __half h0 = __float2half(a0), h1 = __float2half(a1);
            __half h2 = __float2half(a2), h3 = __float2half(a3);
            *(__half2*)(OH + go)     = __half2(h0, h1);
            *(__half2*)(OH + go + 2) = __half2(h2, h3);
        }
    }
}

// =====================================================================
// launch
// =====================================================================
extern "C" void kernel_launch(void* const* d_in, const int* in_sizes, int n_in,
                              void* d_out, int out_size)
{
    const float* x  = (const float*)d_in[0];
    const float* t  = (const float*)d_in[1];
    const float* Wq = (const float*)d_in[2];
    const float* bq = (const float*)d_in[3];
    const float* Wk = (const float*)d_in[4];
    const float* bk = (const float*)d_in[5];
    const float* Wv = (const float*)d_in[6];
    const float* bv = (const float*)d_in[7];
    const float* Wd = (const float*)d_in[8];
    const float* bd = (const float*)d_in[9];
    const float* Wo = (const float*)d_in[10];
    const float* bo = (const float*)d_in[11];
    float* out = (float*)d_out;

    float *Qb, *Kb, *Vb, *Gb;
    __half *xh, *xl, *ah, *wh, *wl;
    cudaGetSymbolAddress((void**)&Qb, g_Q);
    cudaGetSymbolAddress((void**)&Kb, g_K);
    cudaGetSymbolAddress((void**)&Vb, g_V);
    cudaGetSymbolAddress((void**)&Gb, g_G);
    cudaGetSymbolAddress((void**)&xh, g_xh);
    cudaGetSymbolAddress((void**)&xl, g_xl);
    cudaGetSymbolAddress((void**)&ah, g_ah);
    cudaGetSymbolAddress((void**)&wh, g_wh);
    cudaGetSymbolAddress((void**)&wl, g_wl);

    const int n4x = MTOT * NE / 4;
    const int n4w = NE * KE / 4;
    split_k<<<2048, 256>>>(x, xh, xl, n4x, 1);          // gamma needs xl
    split_w3<<<12288, 256>>>(Wq, Wk, Wv, wh, (half*)0, n4w, 3, -1);
    split_w3<<<8192, 256>>>(Wd, Wo, Wo, wh + 3 * WSL, wl, n4w, 2, 0);

    cudaFuncSetAttribute(gemm_f, cudaFuncAttributeMaxDynamicSharedMemorySize, GSMEM);

    // merged Q/K/V/gamma projections: z=3 -> gamma (3-term+sigmoid), else 1-term BK=64
    gemm_f<<<dim3(NE / 256, MTOT / 128, 4), 256, GSMEM>>>(
        xh, xl, wh, wl, bq, bk, bv, bd, Qb, Kb, Vb, Gb, /*sigz=*/3);

    // fused attention (writes fp16 hi plane only)
    cudaFuncSetAttribute(attn2, cudaFuncAttributeMaxDynamicSharedMemorySize, ASMEM);
    attn2<<<1024, 512, ASMEM>>>(Qb, Kb, Vb, Gb, t, ah);

    // output projection (1-term BK=64)
    gemm_f<<<dim3(NE / 256, MTOT / 128, 1), 256, GSMEM>>>(
        ah, (half*)0, wh + 4 * WSL, wl, bo, bo, bo, bo, out, out, out, out, /*sigz=*/-1);
}

// round 14
// speedup vs baseline: 7.8287x; 1.3413x over previous
#include <cuda_runtime.h>
#include <cuda_fp16.h>
#include <math.h>
#include <stdint.h>

// Problem constants
#define MTOT 2048   // BATCH*SEQ = 32*64
#define NE   4096   // EMBED_DIM
#define KE   4096
#define WSL  16777216ull   // elements per weight slot (4096*4096)

// ---------------- scratch (allocation-free: __device__ globals) ----------------
__device__ float g_Q[MTOT * NE];
__device__ float g_K[MTOT * NE];
__device__ float g_V[MTOT * NE];
__device__ float g_G[MTOT * NE];

__device__ __half g_xh[MTOT * NE];
__device__ __half g_ah[MTOT * NE];
__device__ __half g_wh[5 * WSL];   // slots: Wq,Wk,Wv,Wd,Wo (fp16)

// =====================================================================
// helpers
// =====================================================================
__device__ __forceinline__ uint32_t smem_u32(const void* p) {
    uint32_t a;
    asm("{ .reg .u64 t; cvta.to.shared.u64 t, %1; cvt.u32.u64 %0, t; }" : "=r"(a) : "l"(p));
    return a;
}
__device__ __forceinline__ void cp16(uint32_t s, const void* g) {
    asm volatile("cp.async.cg.shared.global [%0], [%1], 16;" :: "r"(s), "l"(g));
}
__device__ __forceinline__ void cp_commit() {
    asm volatile("cp.async.commit_group;" ::: "memory");
}
template <int N>
__device__ __forceinline__ void cp_wait() {
    asm volatile("cp.async.wait_group %0;" :: "n"(N) : "memory");
}
__device__ __forceinline__ void ldm_x4(uint32_t* r, uint32_t a) {
    asm volatile("ldmatrix.sync.aligned.m8n8.x4.shared.b16 {%0,%1,%2,%3}, [%4];"
                 : "=r"(r[0]), "=r"(r[1]), "=r"(r[2]), "=r"(r[3]) : "r"(a));
}
__device__ __forceinline__ void mma4(float* c, const uint32_t* a, uint32_t b0, uint32_t b1) {
    asm volatile("mma.sync.aligned.m16n8k16.row.col.f32.f16.f16.f32 "
                 "{%0,%1,%2,%3}, {%4,%5,%6,%7}, {%8,%9}, {%0,%1,%2,%3};"
                 : "+f"(c[0]), "+f"(c[1]), "+f"(c[2]), "+f"(c[3])
                 : "r"(a[0]), "r"(a[1]), "r"(a[2]), "r"(a[3]), "r"(b0), "r"(b1));
}

// =====================================================================
// fp32 -> fp16 convert (hi plane only)
// =====================================================================
__global__ void conv_h(const float* __restrict__ in, __half* __restrict__ hi, int n4)
{
    int i = blockIdx.x * blockDim.x + threadIdx.x;
    const int str = gridDim.x * blockDim.x;
    for (; i < n4; i += str) {
        float4 v = ((const float4*)in)[i];
        __half2* hp = (__half2*)hi;
        hp[2 * i]     = __half2(__float2half(v.x), __float2half(v.y));
        hp[2 * i + 1] = __half2(__float2half(v.z), __float2half(v.w));
    }
}

// all 5 weights -> fp16 in one launch
__global__ void conv_w5(const float* __restrict__ w0, const float* __restrict__ w1,
                        const float* __restrict__ w2, const float* __restrict__ w3,
                        const float* __restrict__ w4, __half* __restrict__ whb, int n4w)
{
    int i = blockIdx.x * blockDim.x + threadIdx.x;
    const int str = gridDim.x * blockDim.x;
    const int tot = 5 * n4w;
    for (; i < tot; i += str) {
        const int slot = i / n4w;
        const int j = i - slot * n4w;
        const float* in = (slot == 0) ? w0 : (slot == 1) ? w1 : (slot == 2) ? w2
                        : (slot == 3) ? w3 : w4;
        float4 v = ((const float4*)in)[j];
        __half2* hp = (__half2*)(whb + (size_t)slot * WSL);
        hp[2 * j]     = __half2(__float2half(v.x), __float2half(v.y));
        hp[2 * j + 1] = __half2(__float2half(v.z), __float2half(v.w));
    }
}

// =====================================================================
// gemm_f: 1-term fp16 GEMM, BK=64, warp-parity k-stagger.
//   C[m,n] = sum_k A[m,k]*W[n,k] + bias[n];  z==sigz -> sigmoid epilogue
// CTA tile 128x256, 8 warps (2m x 4n), warp tile 64x64, 3 stages.
// =====================================================================
#define RS64 144
#define PB64 18432        // A tile = 128*144
#define STG64 55296       // + B tile 256*144
#define GSMEM (3 * STG64) // 165888 bytes

__global__ __launch_bounds__(256, 1) void gemm_f(
    const __half* __restrict__ Ahp, const __half* __restrict__ Whp,
    const float* __restrict__ b0p, const float* __restrict__ b1p,
    const float* __restrict__ b2p, const float* __restrict__ b3p,
    float* C0, float* C1, float* C2, float* C3, int sigz)
{
    extern __shared__ char smem[];
    const uint32_t sb = smem_u32(smem);
    const int tid = threadIdx.x, z = blockIdx.z;
    const bool dosig = (z == sigz);

    const __half* Wh = Whp + (size_t)z * WSL;
    const float* bias = (z == 0) ? b0p : (z == 1) ? b1p : (z == 2) ? b2p : b3p;
    float*       C    = (z == 0) ? C0  : (z == 1) ? C1  : (z == 2) ? C2  : C3;

    const int bm = blockIdx.y * 128;
    const int bn = blockIdx.x * 256;
    const size_t aoff = (size_t)bm * KE;
    const size_t boff = (size_t)bn * KE;

    const int lane = tid & 31, wid = tid >> 5;
    const int wm = wid >> 2, wn = wid & 3;
    const int mA = lane >> 3, rA = lane & 7;

    uint32_t offA[4], offB[4];
#pragma unroll
    for (int mi = 0; mi < 4; mi++)
        offA[mi] = (uint32_t)((wm * 64 + mi * 16 + (mA & 1) * 8 + rA) * RS64 + (mA >> 1) * 16);
#pragma unroll
    for (int njp = 0; njp < 4; njp++)
        offB[njp] = (uint32_t)(PB64 + (wn * 64 + njp * 16 + (mA >> 1) * 8 + rA) * RS64 + (mA & 1) * 16);

    float acc[4][8][4];
#pragma unroll
    for (int mi = 0; mi < 4; mi++)
#pragma unroll
        for (int nj = 0; nj < 8; nj++)
#pragma unroll
            for (int r = 0; r < 4; r++) acc[mi][nj][r] = 0.f;

    auto load64 = [&](int p, int kt) {
        const uint32_t s = sb + (uint32_t)p * STG64;
#pragma unroll
        for (int u = 0; u < 4; u++) {   // A: 1024 16B chunks
            const int c = tid + u * 256;
            const int row = c >> 3, ch = c & 7;
            cp16(s + (uint32_t)(row * RS64 + ch * 16),
                 Ahp + aoff + (size_t)row * KE + kt + ch * 8);
        }
#pragma unroll
        for (int u = 0; u < 8; u++) {   // B: 2048 16B chunks
            const int c = tid + u * 256;
            const int row = c >> 3, ch = c & 7;
            cp16(s + PB64 + (uint32_t)(row * RS64 + ch * 16),
                 Wh + boff + (size_t)row * KE + kt + ch * 8);
        }
        cp_commit();
    };

    auto mmab = [&](uint32_t fa[4][4], uint32_t fb[4][4]) {
#pragma unroll
        for (int njp = 0; njp < 4; njp++)
#pragma unroll
            for (int mi = 0; mi < 4; mi++) {
                mma4(acc[mi][2 * njp],     fa[mi], fb[njp][0], fb[njp][1]);
                mma4(acc[mi][2 * njp + 1], fa[mi], fb[njp][2], fb[njp][3]);
            }
    };

    const int p2 = (wid & 1) * 2;   // parity stagger: odd warps start at ks=2
    const uint32_t kb0 = (uint32_t)(((0 + p2) & 3) * 32);
    const uint32_t kb1 = (uint32_t)(((1 + p2) & 3) * 32);
    const uint32_t kb2 = (uint32_t)(((2 + p2) & 3) * 32);
    const uint32_t kb3 = (uint32_t)(((3 + p2) & 3) * 32);

    load64(0, 0);
    load64(1, 64);

    const int NST = KE / 64;  // 64
    for (int i = 0; i < NST; i++) {
        if (i >= NST - 2) cp_wait<0>();
        else              cp_wait<1>();
        __syncthreads();

        const uint32_t s = sb + (uint32_t)(i % 3) * STG64;
        uint32_t fA[2][4][4], fB[2][4][4];

#pragma unroll
        for (int mi = 0; mi < 4; mi++)    ldm_x4(fA[0][mi], s + offA[mi] + kb0);
#pragma unroll
        for (int njp = 0; njp < 4; njp++) ldm_x4(fB[0][njp], s + offB[njp] + kb0);
#pragma unroll
        for (int mi = 0; mi < 4; mi++)    ldm_x4(fA[1][mi], s + offA[mi] + kb1);
#pragma unroll
        for (int njp = 0; njp < 4; njp++) ldm_x4(fB[1][njp], s + offB[njp] + kb1);

        mmab(fA[0], fB[0]);

        if (i + 2 < NST) load64((i + 2) % 3, (i + 2) * 64);

#pragma unroll
        for (int mi = 0; mi < 4; mi++)    ldm_x4(fA[0][mi], s + offA[mi] + kb2);
#pragma unroll
        for (int njp = 0; njp < 4; njp++) ldm_x4(fB[0][njp], s + offB[njp] + kb2);

        mmab(fA[1], fB[1]);

#pragma unroll
        for (int mi = 0; mi < 4; mi++)    ldm_x4(fA[1][mi], s + offA[mi] + kb3);
#pragma unroll
        for (int njp = 0; njp < 4; njp++) ldm_x4(fB[1][njp], s + offB[njp] + kb3);

        mmab(fA[0], fB[0]);
        mmab(fA[1], fB[1]);
    }

    // epilogue (sigmoid if gamma)
    const int g = lane >> 2, t4 = lane & 3;
#pragma unroll
    for (int mi = 0; mi < 4; mi++) {
#pragma unroll
        for (int nj = 0; nj < 8; nj++) {
            const int row = bm + wm * 64 + mi * 16 + g;
            const int col = bn + wn * 64 + nj * 8 + 2 * t4;
            const float bb0 = bias[col], bb1 = bias[col + 1];
            float v0 = acc[mi][nj][0] + bb0, v1 = acc[mi][nj][1] + bb1;
            float v2 = acc[mi][nj][2] + bb0, v3 = acc[mi][nj][3] + bb1;
            if (dosig) {
                v0 = 1.f / (1.f + expf(-v0)); v1 = 1.f / (1.f + expf(-v1));
                v2 = 1.f / (1.f + expf(-v2)); v3 = 1.f / (1.f + expf(-v3));
            }
            *(float2*)(C + (size_t)row * NE + col)       = make_float2(v0, v1);
            *(float2*)(C + (size_t)(row + 8) * NE + col) = make_float2(v2, v3);
        }
    }
}

// =====================================================================
// Fused attention v2 (unchanged, verified; fp16 hi-only epilogue)
// =====================================================================
#define ASD  132
#define ASDK 68
#define OQ  0
#define OGC 8448
#define OKT 16896
#define OGT 25600
#define OS  34304
#define OV  38400
#define ASMEM ((38400 + 8448) * 4)   // 187392 bytes

__global__ __launch_bounds__(512, 1) void attn2(
    const float* __restrict__ Q, const float* __restrict__ K,
    const float* __restrict__ V, const float* __restrict__ G,
    const float* __restrict__ t, __half* __restrict__ OH)
{
    extern __shared__ float sm[];
    float* sQ   = sm + OQ;
    float* sGc  = sm + OGC;
    float* sKT  = sm + OKT;
    float* sGiT = sm + OGT;
    float* sS   = sm + OS;
    float* sV   = sm + OV;
    const uint32_t sb = smem_u32(sm);

    const int bh = blockIdx.x;
    const int b  = bh >> 5, h = bh & 31;
    const int tid = threadIdx.x;
    const size_t base = ((size_t)b * 64) * 4096 + (size_t)h * 128;

    for (int c = tid; c < 2048; c += 512) {
        const int row = c >> 5, ch = c & 31;
        const uint32_t so = (uint32_t)(row * ASD * 4 + ch * 16);
        const size_t   go = base + (size_t)row * 4096 + ch * 4;
        cp16(sb + OQ * 4 + so,  Q + go);
        cp16(sb + OGC * 4 + so, G + go);
    }
    cp_commit();
    for (int c = tid; c < 2048; c += 512) {
        const int row = c >> 5, ch = c & 31;
        cp16(sb + OV * 4 + (uint32_t)(row * ASD * 4 + ch * 16),
             V + base + (size_t)row * 4096 + ch * 4);
    }
    cp_commit();
    for (int i = tid; i < 8192; i += 512) {
        const int s = i >> 7, d = i & 127;
        sKT[d * ASDK + s] = K[base + (size_t)s * 4096 + d];
    }
    cp_wait<1>();
    __syncthreads();

    if (tid >= 128) {
        const float LN1E4_64 = 0.14391156531879916f;
        for (int i = tid - 128; i < 4096; i += 384) {
            const int s = i >> 6, q = i & 63;
            const float invf = expf(-(float)s * LN1E4_64);
            const float ang  = t[q] * invf;
            const float cs = cosf(ang), sn = sinf(ang);
            float a, b2;
            a = sQ[s * ASD + q]; b2 = sQ[s * ASD + q + 64];
            sQ[s * ASD + q]      = a * cs - b2 * sn;
            sQ[s * ASD + q + 64] = b2 * cs + a * sn;
            a = sKT[q * ASDK + s]; b2 = sKT[(q + 64) * ASDK + s];
            sKT[q * ASDK + s]        = a * cs - b2 * sn;
            sKT[(q + 64) * ASDK + s] = b2 * cs + a * sn;
        }
    } else {
        const int d = tid;
        float run = 1.f;
        for (int s = 0; s < 64; s++) {
            run *= sGc[s * ASD + d];
            sGc[s * ASD + d]   = run;
            sGiT[d * ASDK + s] = 1.f / run;
        }
    }
    __syncthreads();

    {
        const int w = tid >> 5, lane = tid & 31;
        const int wq = w >> 2, wk = w & 3;
        const int lq = lane >> 2, lk = lane & 3;
        const int q0 = wq * 16 + lq * 2;
        const int k0 = wk * 16 + lk * 4;
        float acc[2][4] = {{0,0,0,0},{0,0,0,0}};
        float dac[2][4] = {{0,0,0,0},{0,0,0,0}};

        if (wk <= wq) {
#pragma unroll 2
            for (int kk = 0; kk < 128; kk += 4) {
                float qv0[4], qv1[4], gq0[4], gq1[4];
                *(float4*)qv0 = *(const float4*)&sQ[q0 * ASD + kk];
                *(float4*)qv1 = *(const float4*)&sQ[(q0 + 1) * ASD + kk];
                *(float4*)gq0 = *(const float4*)&sGc[q0 * ASD + kk];
                *(float4*)gq1 = *(const float4*)&sGc[(q0 + 1) * ASD + kk];
                float kv[4][4], gi[4][4];
#pragma unroll
                for (int r = 0; r < 4; r++) {
                    *(float4*)kv[r] = *(const float4*)&sKT[(kk + r) * ASDK + k0];
                    *(float4*)gi[r] = *(const float4*)&sGiT[(kk + r) * ASDK + k0];
                }
#pragma unroll
                for (int r = 0; r < 4; r++)
#pragma unroll
                    for (int j = 0; j < 4; j++) {
                        acc[0][j] = fmaf(qv0[r], kv[r][j], acc[0][j]);
                        acc[1][j] = fmaf(qv1[r], kv[r][j], acc[1][j]);
                        dac[0][j] = fmaf(gq0[r], gi[r][j], dac[0][j]);
                        dac[1][j] = fmaf(gq1[r], gi[r][j], dac[1][j]);
                    }
            }
        }
#pragma unroll
        for (int i = 0; i < 2; i++)
#pragma unroll
            for (int j = 0; j < 4; j++) {
                const int qi = q0 + i, kj = k0 + j;
                sS[qi * 64 + kj] =
                    (kj <= qi) ? acc[i][j] * dac[i][j] * (1.0f / 128.0f) : 0.f;
            }
    }
    cp_wait<0>();
    __syncthreads();

    {
        const int w = tid >> 5, lane = tid & 31;
        const int d0 = lane * 4;
#pragma unroll
        for (int qq = 0; qq < 4; qq++) {
            const int q = w * 4 + qq;
            float a0 = 0.f, a1 = 0.f, a2 = 0.f, a3 = 0.f;
            for (int kq = 0; kq <= w; kq++) {
                float sv[4];
                *(float4*)sv = *(const float4*)&sS[q * 64 + kq * 4];
#pragma unroll
                for (int r = 0; r < 4; r++) {
                    float v[4];
                    *(float4*)v = *(const float4*)&sV[(kq * 4 + r) * ASD + d0];
                    a0 = fmaf(sv[r], v[0], a0);
                    a1 = fmaf(sv[r], v[1], a1);
                    a2 = fmaf(sv[r], v[2], a2);
                    a3 = fmaf(sv[r], v[3], a3);
                }
            }
            const size_t go = base + (size_t)q * 4096 + d0;
            *(__half2*)(OH + go)     = __half2(__float2half(a0), __float2half(a1));
            *(__half2*)(OH + go + 2) = __half2(__float2half(a2), __float2half(a3));
        }
    }
}

// =====================================================================
// launch
// =====================================================================
extern "C" void kernel_launch(void* const* d_in, const int* in_sizes, int n_in,
                              void* d_out, int out_size)
{
    const float* x  = (const float*)d_in[0];
    const float* t  = (const float*)d_in[1];
    const float* Wq = (const float*)d_in[2];
    const float* bq = (const float*)d_in[3];
    const float* Wk = (const float*)d_in[4];
    const float* bk = (const float*)d_in[5];
    const float* Wv = (const float*)d_in[6];
    const float* bv = (const float*)d_in[7];
    const float* Wd = (const float*)d_in[8];
    const float* bd = (const float*)d_in[9];
    const float* Wo = (const float*)d_in[10];
    const float* bo = (const float*)d_in[11];
    float* out = (float*)d_out;

    float *Qb, *Kb, *Vb, *Gb;
    __half *xh, *ah, *wh;
    cudaGetSymbolAddress((void**)&Qb, g_Q);
    cudaGetSymbolAddress((void**)&Kb, g_K);
    cudaGetSymbolAddress((void**)&Vb, g_V);
    cudaGetSymbolAddress((void**)&Gb, g_G);
    cudaGetSymbolAddress((void**)&xh, g_xh);
    cudaGetSymbolAddress((void**)&ah, g_ah);
    cudaGetSymbolAddress((void**)&wh, g_wh);

    const int n4x = MTOT * NE / 4;
    const int n4w = NE * KE / 4;
    conv_h<<<2048, 256>>>(x, xh, n4x);
    conv_w5<<<16384, 256>>>(Wq, Wk, Wv, Wd, Wo, wh, n4w);

    cudaFuncSetAttribute(gemm_f, cudaFuncAttributeMaxDynamicSharedMemorySize, GSMEM);

    // merged Q/K/V/gamma projections (all 1-term; z=3 -> sigmoid epilogue)
    gemm_f<<<dim3(NE / 256, MTOT / 128, 4), 256, GSMEM>>>(
        xh, wh, bq, bk, bv, bd, Qb, Kb, Vb, Gb, /*sigz=*/3);

    // fused attention (writes fp16 plane directly)
    cudaFuncSetAttribute(attn2, cudaFuncAttributeMaxDynamicSharedMemorySize, ASMEM);
    attn2<<<1024, 512, ASMEM>>>(Qb, Kb, Vb, Gb, t, ah);

    // output projection (1-term)
    gemm_f<<<dim3(NE / 256, MTOT / 128, 1), 256, GSMEM>>>(
        ah, wh + 4 * WSL, bo, bo, bo, bo, out, out, out, out, /*sigz=*/-1);
}

// round 15
// speedup vs baseline: 8.3304x; 1.0641x over previous
#include <cuda_runtime.h>
#include <cuda_fp16.h>
#include <math.h>
#include <stdint.h>

// Problem constants
#define MTOT 2048   // BATCH*SEQ = 32*64
#define NE   4096   // EMBED_DIM
#define KE   4096
#define WSL  16777216ull   // elements per weight slot (4096*4096)

// ---------------- scratch (allocation-free: __device__ globals) ----------------
__device__ float g_Q[MTOT * NE];
__device__ float g_K[MTOT * NE];
__device__ float g_V[MTOT * NE];
__device__ float g_G[MTOT * NE];

__device__ __half g_xh[MTOT * NE];
__device__ __half g_ah[MTOT * NE];
__device__ __half g_wh[5 * WSL];   // slots: Wq,Wk,Wv,Wd,Wo (fp16)

// =====================================================================
// helpers
// =====================================================================
__device__ __forceinline__ uint32_t smem_u32(const void* p) {
    uint32_t a;
    asm("{ .reg .u64 t; cvta.to.shared.u64 t, %1; cvt.u32.u64 %0, t; }" : "=r"(a) : "l"(p));
    return a;
}
__device__ __forceinline__ void cp16(uint32_t s, const void* g) {
    asm volatile("cp.async.cg.shared.global [%0], [%1], 16;" :: "r"(s), "l"(g));
}
__device__ __forceinline__ void cp_commit() {
    asm volatile("cp.async.commit_group;" ::: "memory");
}
template <int N>
__device__ __forceinline__ void cp_wait() {
    asm volatile("cp.async.wait_group %0;" :: "n"(N) : "memory");
}
__device__ __forceinline__ void ldm_x4(uint32_t* r, uint32_t a) {
    asm volatile("ldmatrix.sync.aligned.m8n8.x4.shared.b16 {%0,%1,%2,%3}, [%4];"
                 : "=r"(r[0]), "=r"(r[1]), "=r"(r[2]), "=r"(r[3]) : "r"(a));
}
__device__ __forceinline__ void mma4(float* c, const uint32_t* a, uint32_t b0, uint32_t b1) {
    asm volatile("mma.sync.aligned.m16n8k16.row.col.f32.f16.f16.f32 "
                 "{%0,%1,%2,%3}, {%4,%5,%6,%7}, {%8,%9}, {%0,%1,%2,%3};"
                 : "+f"(c[0]), "+f"(c[1]), "+f"(c[2]), "+f"(c[3])
                 : "r"(a[0]), "r"(a[1]), "r"(a[2]), "r"(a[3]), "r"(b0), "r"(b1));
}

// =====================================================================
// fp32 -> fp16 converts (unchanged, verified)
// =====================================================================
__global__ void conv_h(const float* __restrict__ in, __half* __restrict__ hi, int n4)
{
    int i = blockIdx.x * blockDim.x + threadIdx.x;
    const int str = gridDim.x * blockDim.x;
    for (; i < n4; i += str) {
        float4 v = ((const float4*)in)[i];
        __half2* hp = (__half2*)hi;
        hp[2 * i]     = __half2(__float2half(v.x), __float2half(v.y));
        hp[2 * i + 1] = __half2(__float2half(v.z), __float2half(v.w));
    }
}

__global__ void conv_w5(const float* __restrict__ w0, const float* __restrict__ w1,
                        const float* __restrict__ w2, const float* __restrict__ w3,
                        const float* __restrict__ w4, __half* __restrict__ whb, int n4w)
{
    int i = blockIdx.x * blockDim.x + threadIdx.x;
    const int str = gridDim.x * blockDim.x;
    const int tot = 5 * n4w;
    for (; i < tot; i += str) {
        const int slot = i / n4w;
        const int j = i - slot * n4w;
        const float* in = (slot == 0) ? w0 : (slot == 1) ? w1 : (slot == 2) ? w2
                        : (slot == 3) ? w3 : w4;
        float4 v = ((const float4*)in)[j];
        __half2* hp = (__half2*)(whb + (size_t)slot * WSL);
        hp[2 * j]     = __half2(__float2half(v.x), __float2half(v.y));
        hp[2 * j + 1] = __half2(__float2half(v.z), __float2half(v.w));
    }
}

// =====================================================================
// gemm_f: 1-term fp16 GEMM, BK=64 (unchanged, verified at 1129us)
// =====================================================================
#define RS64 144
#define PB64 18432
#define STG64 55296
#define GSMEM (3 * STG64) // 165888 bytes

__global__ __launch_bounds__(256, 1) void gemm_f(
    const __half* __restrict__ Ahp, const __half* __restrict__ Whp,
    const float* __restrict__ b0p, const float* __restrict__ b1p,
    const float* __restrict__ b2p, const float* __restrict__ b3p,
    float* C0, float* C1, float* C2, float* C3, int sigz)
{
    extern __shared__ char smem[];
    const uint32_t sb = smem_u32(smem);
    const int tid = threadIdx.x, z = blockIdx.z;
    const bool dosig = (z == sigz);

    const __half* Wh = Whp + (size_t)z * WSL;
    const float* bias = (z == 0) ? b0p : (z == 1) ? b1p : (z == 2) ? b2p : b3p;
    float*       C    = (z == 0) ? C0  : (z == 1) ? C1  : (z == 2) ? C2  : C3;

    const int bm = blockIdx.y * 128;
    const int bn = blockIdx.x * 256;
    const size_t aoff = (size_t)bm * KE;
    const size_t boff = (size_t)bn * KE;

    const int lane = tid & 31, wid = tid >> 5;
    const int wm = wid >> 2, wn = wid & 3;
    const int mA = lane >> 3, rA = lane & 7;

    uint32_t offA[4], offB[4];
#pragma unroll
    for (int mi = 0; mi < 4; mi++)
        offA[mi] = (uint32_t)((wm * 64 + mi * 16 + (mA & 1) * 8 + rA) * RS64 + (mA >> 1) * 16);
#pragma unroll
    for (int njp = 0; njp < 4; njp++)
        offB[njp] = (uint32_t)(PB64 + (wn * 64 + njp * 16 + (mA >> 1) * 8 + rA) * RS64 + (mA & 1) * 16);

    float acc[4][8][4];
#pragma unroll
    for (int mi = 0; mi < 4; mi++)
#pragma unroll
        for (int nj = 0; nj < 8; nj++)
#pragma unroll
            for (int r = 0; r < 4; r++) acc[mi][nj][r] = 0.f;

    auto load64 = [&](int p, int kt) {
        const uint32_t s = sb + (uint32_t)p * STG64;
#pragma unroll
        for (int u = 0; u < 4; u++) {
            const int c = tid + u * 256;
            const int row = c >> 3, ch = c & 7;
            cp16(s + (uint32_t)(row * RS64 + ch * 16),
                 Ahp + aoff + (size_t)row * KE + kt + ch * 8);
        }
#pragma unroll
        for (int u = 0; u < 8; u++) {
            const int c = tid + u * 256;
            const int row = c >> 3, ch = c & 7;
            cp16(s + PB64 + (uint32_t)(row * RS64 + ch * 16),
                 Wh + boff + (size_t)row * KE + kt + ch * 8);
        }
        cp_commit();
    };

    auto mmab = [&](uint32_t fa[4][4], uint32_t fb[4][4]) {
#pragma unroll
        for (int njp = 0; njp < 4; njp++)
#pragma unroll
            for (int mi = 0; mi < 4; mi++) {
                mma4(acc[mi][2 * njp],     fa[mi], fb[njp][0], fb[njp][1]);
                mma4(acc[mi][2 * njp + 1], fa[mi], fb[njp][2], fb[njp][3]);
            }
    };

    const int p2 = (wid & 1) * 2;
    const uint32_t kb0 = (uint32_t)(((0 + p2) & 3) * 32);
    const uint32_t kb1 = (uint32_t)(((1 + p2) & 3) * 32);
    const uint32_t kb2 = (uint32_t)(((2 + p2) & 3) * 32);
    const uint32_t kb3 = (uint32_t)(((3 + p2) & 3) * 32);

    load64(0, 0);
    load64(1, 64);

    const int NST = KE / 64;
    for (int i = 0; i < NST; i++) {
        if (i >= NST - 2) cp_wait<0>();
        else              cp_wait<1>();
        __syncthreads();

        const uint32_t s = sb + (uint32_t)(i % 3) * STG64;
        uint32_t fA[2][4][4], fB[2][4][4];

#pragma unroll
        for (int mi = 0; mi < 4; mi++)    ldm_x4(fA[0][mi], s + offA[mi] + kb0);
#pragma unroll
        for (int njp = 0; njp < 4; njp++) ldm_x4(fB[0][njp], s + offB[njp] + kb0);
#pragma unroll
        for (int mi = 0; mi < 4; mi++)    ldm_x4(fA[1][mi], s + offA[mi] + kb1);
#pragma unroll
        for (int njp = 0; njp < 4; njp++) ldm_x4(fB[1][njp], s + offB[njp] + kb1);

        mmab(fA[0], fB[0]);

        if (i + 2 < NST) load64((i + 2) % 3, (i + 2) * 64);

#pragma unroll
        for (int mi = 0; mi < 4; mi++)    ldm_x4(fA[0][mi], s + offA[mi] + kb2);
#pragma unroll
        for (int njp = 0; njp < 4; njp++) ldm_x4(fB[0][njp], s + offB[njp] + kb2);

        mmab(fA[1], fB[1]);

#pragma unroll
        for (int mi = 0; mi < 4; mi++)    ldm_x4(fA[1][mi], s + offA[mi] + kb3);
#pragma unroll
        for (int njp = 0; njp < 4; njp++) ldm_x4(fB[1][njp], s + offB[njp] + kb3);

        mmab(fA[0], fB[0]);
        mmab(fA[1], fB[1]);
    }

    const int g = lane >> 2, t4 = lane & 3;
#pragma unroll
    for (int mi = 0; mi < 4; mi++) {
#pragma unroll
        for (int nj = 0; nj < 8; nj++) {
            const int row = bm + wm * 64 + mi * 16 + g;
            const int col = bn + wn * 64 + nj * 8 + 2 * t4;
            const float bb0 = bias[col], bb1 = bias[col + 1];
            float v0 = acc[mi][nj][0] + bb0, v1 = acc[mi][nj][1] + bb1;
            float v2 = acc[mi][nj][2] + bb0, v3 = acc[mi][nj][3] + bb1;
            if (dosig) {
                v0 = 1.f / (1.f + expf(-v0)); v1 = 1.f / (1.f + expf(-v1));
                v2 = 1.f / (1.f + expf(-v2)); v3 = 1.f / (1.f + expf(-v3));
            }
            *(float2*)(C + (size_t)row * NE + col)       = make_float2(v0, v1);
            *(float2*)(C + (size_t)(row + 8) * NE + col) = make_float2(v2, v3);
        }
    }
}

// =====================================================================
// attn3: 384 threads, 2 CTAs/SM. fp16 Q/K/V/S smem, fp32 gc/gi.
// RoPE fused into load (shared angle for Q,K). V overlaid on Q post-score.
// smem layout (bytes):
//   [0      ,  17408) sQV  : half [64][136]   (Q, then V)
//   [17408  ,  34816) sKT  : half [128][68]   (K transposed)
//   [34816  ,  68608) sGc  : float [64][132]  (gamma -> cumprod)
//   [68608  , 103424) sGiT : float [128][68]  (1/cumprod, transposed)
//   [103424 , 112128) sS   : half [64][68]    (decayed scores)
// =====================================================================
#define SQH 136
#define SKH 68
#define SGD 132
#define SGI 68
#define SSH 68
#define A3_OKT 17408
#define A3_OGC 34816
#define A3_OGI 68608
#define A3_OS  103424
#define A3SMEM 112128

__global__ __launch_bounds__(384, 2) void attn3(
    const float* __restrict__ Q, const float* __restrict__ K,
    const float* __restrict__ V, const float* __restrict__ G,
    const float* __restrict__ t, __half* __restrict__ OH)
{
    extern __shared__ char smc[];
    __half* sQV  = (__half*)(smc);
    __half* sKT  = (__half*)(smc + A3_OKT);
    float*  sGc  = (float*)(smc + A3_OGC);
    float*  sGiT = (float*)(smc + A3_OGI);
    __half* sS   = (__half*)(smc + A3_OS);
    const uint32_t sb = smem_u32(smc);

    const int bh = blockIdx.x;
    const int b  = bh >> 5, h = bh & 31;
    const int tid = threadIdx.x;
    const size_t base = ((size_t)b * 64) * 4096 + (size_t)h * 128;

    // ---- G via cp.async (fp32) ----
    for (int c = tid; c < 2048; c += 384) {
        const int row = c >> 5, ch = c & 31;
        cp16(sb + A3_OGC + (uint32_t)(row * 528 + ch * 16),
             G + base + (size_t)row * 4096 + ch * 4);
    }
    cp_commit();

    // ---- Q,K load + fused RoPE (shared angle), store fp16 ----
    const float LN1E4_64 = 0.14391156531879916f;
    for (int i = tid; i < 4096; i += 384) {
        const int s = i >> 6, q = i & 63;
        const float invf = expf(-(float)s * LN1E4_64);
        const float ang  = t[q] * invf;
        const float cs = cosf(ang), sn = sinf(ang);
        float a, b2;
        a = Q[base + (size_t)s * 4096 + q]; b2 = Q[base + (size_t)s * 4096 + q + 64];
        sQV[s * SQH + q]      = __float2half(a * cs - b2 * sn);
        sQV[s * SQH + q + 64] = __float2half(b2 * cs + a * sn);
        a = K[base + (size_t)s * 4096 + q]; b2 = K[base + (size_t)s * 4096 + q + 64];
        sKT[q * SKH + s]        = __float2half(a * cs - b2 * sn);
        sKT[(q + 64) * SKH + s] = __float2half(b2 * cs + a * sn);
    }
    cp_wait<0>();
    __syncthreads();

    // ---- cumprod (fp32), gi transposed ----
    if (tid < 128) {
        const int d = tid;
        float run = 1.f;
        for (int s = 0; s < 64; s++) {
            run *= sGc[s * SGD + d];
            sGc[s * SGD + d]  = run;
            sGiT[d * SGI + s] = 1.f / run;
        }
    }
    __syncthreads();

    // ---- score phase: 10 active warps on lower-triangle 16x16 tiles ----
    {
        const int w = tid >> 5, lane = tid & 31;
        int wq = 0;
        if (w >= 1) wq = 1;
        if (w >= 3) wq = 2;
        if (w >= 6) wq = 3;
        const int wk = w - (wq * (wq + 1)) / 2;

        if (w < 10) {
            const int lq = lane >> 2, lk = lane & 3;
            const int q0 = wq * 16 + lq * 2;
            const int k0 = wk * 16 + lk * 4;
            float acc[2][4] = {{0,0,0,0},{0,0,0,0}};
            float dac[2][4] = {{0,0,0,0},{0,0,0,0}};

#pragma unroll 2
            for (int kk = 0; kk < 128; kk += 4) {
                float2 q0a = __half22float2(*(const __half2*)&sQV[q0 * SQH + kk]);
                float2 q0b = __half22float2(*(const __half2*)&sQV[q0 * SQH + kk + 2]);
                float2 q1a = __half22float2(*(const __half2*)&sQV[(q0 + 1) * SQH + kk]);
                float2 q1b = __half22float2(*(const __half2*)&sQV[(q0 + 1) * SQH + kk + 2]);
                const float qv0[4] = {q0a.x, q0a.y, q0b.x, q0b.y};
                const float qv1[4] = {q1a.x, q1a.y, q1b.x, q1b.y};
                float gq0[4], gq1[4];
                *(float4*)gq0 = *(const float4*)&sGc[q0 * SGD + kk];
                *(float4*)gq1 = *(const float4*)&sGc[(q0 + 1) * SGD + kk];
                float kv[4][4], gi[4][4];
#pragma unroll
                for (int r = 0; r < 4; r++) {
                    float2 ka = __half22float2(*(const __half2*)&sKT[(kk + r) * SKH + k0]);
                    float2 kb = __half22float2(*(const __half2*)&sKT[(kk + r) * SKH + k0 + 2]);
                    kv[r][0] = ka.x; kv[r][1] = ka.y; kv[r][2] = kb.x; kv[r][3] = kb.y;
                    *(float4*)gi[r] = *(const float4*)&sGiT[(kk + r) * SGI + k0];
                }
#pragma unroll
                for (int r = 0; r < 4; r++)
#pragma unroll
                    for (int j = 0; j < 4; j++) {
                        acc[0][j] = fmaf(qv0[r], kv[r][j], acc[0][j]);
                        acc[1][j] = fmaf(qv1[r], kv[r][j], acc[1][j]);
                        dac[0][j] = fmaf(gq0[r], gi[r][j], dac[0][j]);
                        dac[1][j] = fmaf(gq1[r], gi[r][j], dac[1][j]);
                    }
            }
#pragma unroll
            for (int i = 0; i < 2; i++) {
                const int qi = q0 + i;
                float v[4];
#pragma unroll
                for (int j = 0; j < 4; j++) {
                    const int kj = k0 + j;
                    v[j] = (kj <= qi) ? acc[i][j] * dac[i][j] * (1.0f / 128.0f) : 0.f;
                }
                *(__half2*)&sS[qi * SSH + k0]     = __floats2half2_rn(v[0], v[1]);
                *(__half2*)&sS[qi * SSH + k0 + 2] = __floats2half2_rn(v[2], v[3]);
            }
        }
    }
    __syncthreads();

    // ---- V load (fp32 -> fp16), overlaid on Q buffer ----
    for (int c = tid; c < 2048; c += 384) {
        const int row = c >> 5, ch = c & 31;
        float4 v = *(const float4*)(V + base + (size_t)row * 4096 + ch * 4);
        __half2* dst = (__half2*)&sQV[row * SQH + ch * 4];
        dst[0] = __floats2half2_rn(v.x, v.y);
        dst[1] = __floats2half2_rn(v.z, v.w);
    }
    __syncthreads();

    // ---- O = S @ V: 16 causal chunks of 4 q-rows over 12 warps ----
    {
        const int w = tid >> 5, lane = tid & 31;
        const int d0 = lane * 4;
        for (int c = w; c < 16; c += 12) {
#pragma unroll
            for (int qq = 0; qq < 4; qq++) {
                const int q = c * 4 + qq;
                float a0 = 0.f, a1 = 0.f, a2 = 0.f, a3 = 0.f;
                for (int kq = 0; kq <= c; kq++) {
                    float2 sa = __half22float2(*(const __half2*)&sS[q * SSH + kq * 4]);
                    float2 sc = __half22float2(*(const __half2*)&sS[q * SSH + kq * 4 + 2]);
                    const float sv[4] = {sa.x, sa.y, sc.x, sc.y};
#pragma unroll
                    for (int r = 0; r < 4; r++) {
                        float2 va = __half22float2(*(const __half2*)&sQV[(kq * 4 + r) * SQH + d0]);
                        float2 vb = __half22float2(*(const __half2*)&sQV[(kq * 4 + r) * SQH + d0 + 2]);
                        a0 = fmaf(sv[r], va.x, a0);
                        a1 = fmaf(sv[r], va.y, a1);
                        a2 = fmaf(sv[r], vb.x, a2);
                        a3 = fmaf(sv[r], vb.y, a3);
                    }
                }
                const size_t go = base + (size_t)q * 4096 + d0;
                *(__half2*)(OH + go)     = __floats2half2_rn(a0, a1);
                *(__half2*)(OH + go + 2) = __floats2half2_rn(a2, a3);
            }
        }
    }
}

// =====================================================================
// launch
// =====================================================================
extern "C" void kernel_launch(void* const* d_in, const int* in_sizes, int n_in,
                              void* d_out, int out_size)
{
    const float* x  = (const float*)d_in[0];
    const float* t  = (const float*)d_in[1];
    const float* Wq = (const float*)d_in[2];
    const float* bq = (const float*)d_in[3];
    const float* Wk = (const float*)d_in[4];
    const float* bk = (const float*)d_in[5];
    const float* Wv = (const float*)d_in[6];
    const float* bv = (const float*)d_in[7];
    const float* Wd = (const float*)d_in[8];
    const float* bd = (const float*)d_in[9];
    const float* Wo = (const float*)d_in[10];
    const float* bo = (const float*)d_in[11];
    float* out = (float*)d_out;

    float *Qb, *Kb, *Vb, *Gb;
    __half *xh, *ah, *wh;
    cudaGetSymbolAddress((void**)&Qb, g_Q);
    cudaGetSymbolAddress((void**)&Kb, g_K);
    cudaGetSymbolAddress((void**)&Vb, g_V);
    cudaGetSymbolAddress((void**)&Gb, g_G);
    cudaGetSymbolAddress((void**)&xh, g_xh);
    cudaGetSymbolAddress((void**)&ah, g_ah);
    cudaGetSymbolAddress((void**)&wh, g_wh);

    const int n4x = MTOT * NE / 4;
    const int n4w = NE * KE / 4;
    conv_h<<<2048, 256>>>(x, xh, n4x);
    conv_w5<<<16384, 256>>>(Wq, Wk, Wv, Wd, Wo, wh, n4w);

    cudaFuncSetAttribute(gemm_f, cudaFuncAttributeMaxDynamicSharedMemorySize, GSMEM);

    // merged Q/K/V/gamma projections (all 1-term; z=3 -> sigmoid epilogue)
    gemm_f<<<dim3(NE / 256, MTOT / 128, 4), 256, GSMEM>>>(
        xh, wh, bq, bk, bv, bd, Qb, Kb, Vb, Gb, /*sigz=*/3);

    // fused attention (2 CTAs/SM, writes fp16 plane directly)
    cudaFuncSetAttribute(attn3, cudaFuncAttributeMaxDynamicSharedMemorySize, A3SMEM);
    attn3<<<1024, 384, A3SMEM>>>(Qb, Kb, Vb, Gb, t, ah);

    // output projection (1-term)
    gemm_f<<<dim3(NE / 256, MTOT / 128, 1), 256, GSMEM>>>(
        ah, wh + 4 * WSL, bo, bo, bo, bo, out, out, out, out, /*sigz=*/-1);
}